// round 2
// baseline (speedup 1.0000x reference)
#include <cuda_runtime.h>
#include <math.h>
#include <stdint.h>

#define B 4
#define L 1024
#define D 768
#define H 12
#define NE 42
#define MM 4
#define P 512
#define BLKSZ 64
#define NL 97
#define GB 12          // D / BLKSZ
#define KD 1536        // 2*D
#define ROWS (B*P)     // 2048

typedef unsigned long long ull;

// ---- packed f32x2 helpers (Blackwell FFMA2 via PTX) -----------------------
__device__ __forceinline__ ull pack2(float lo, float hi) {
    ull r; asm("mov.b64 %0, {%1, %2};" : "=l"(r) : "f"(lo), "f"(hi)); return r;
}
__device__ __forceinline__ void fma2(ull& d, ull a, ull b) {
    asm("fma.rn.f32x2 %0, %1, %2, %0;" : "+l"(d) : "l"(a), "l"(b));
}
__device__ __forceinline__ float2 unpack2(ull v) {
    float2 r; asm("mov.b64 {%0, %1}, %2;" : "=f"(r.x), "=f"(r.y) : "l"(v)); return r;
}

// ---------------- scratch (device globals; no allocation allowed) ----------
__device__ __align__(16) float g_eemb[B*NE*D];
__device__ __align__(16) float g_eatt[B*NE*H*L];
__device__ __align__(16) float g_htw[B*P*L];
__device__ __align__(16) float g_rs[(size_t)ROWS*D];
__device__ __align__(16) float g_zs[(size_t)ROWS*D];
__device__ __align__(16) float g_zo[(size_t)ROWS*D];
__device__ __align__(16) float g_part[(size_t)GB*ROWS*NL];

// ---------------- kernel 1: entity embeddings (logsumexp over mentions) ----
__global__ void k_eemb(const float* __restrict__ seq, const int* __restrict__ mpos) {
    const int be = blockIdx.x;
    const int b = be / NE;
    __shared__ int pos[MM];
    if (threadIdx.x < MM) pos[threadIdx.x] = mpos[be*MM + threadIdx.x] + 1;
    __syncthreads();
    const float* sb = seq + (size_t)b * L * D;
    for (int d = threadIdx.x; d < D; d += blockDim.x) {
        float v0 = sb[(size_t)pos[0]*D + d];
        float v1 = sb[(size_t)pos[1]*D + d];
        float v2 = sb[(size_t)pos[2]*D + d];
        float v3 = sb[(size_t)pos[3]*D + d];
        float mx = fmaxf(fmaxf(v0, v1), fmaxf(v2, v3));
        float s = expf(v0-mx) + expf(v1-mx) + expf(v2-mx) + expf(v3-mx);
        g_eemb[(size_t)be*D + d] = mx + logf(s);
    }
}

// ---------------- kernel 2: entity attentions (mean over mention rows) -----
__global__ void k_eatt(const float* __restrict__ att, const int* __restrict__ mpos) {
    const int idx = blockIdx.x;
    const int h  = idx % H;
    const int be = idx / H;
    const int b  = be / NE;
    __shared__ int pos[MM];
    if (threadIdx.x < MM) pos[threadIdx.x] = mpos[be*MM + threadIdx.x] + 1;
    __syncthreads();
    const float* ab = att + (size_t)(b*H + h) * L * L;
    float* outp = g_eatt + ((size_t)be*H + h) * L;
    for (int l = threadIdx.x; l < L; l += blockDim.x) {
        float s = ab[(size_t)pos[0]*L + l] + ab[(size_t)pos[1]*L + l]
                + ab[(size_t)pos[2]*L + l] + ab[(size_t)pos[3]*L + l];
        outp[l] = 0.25f * s;
    }
}

// ---------------- kernel 3: per-pair channel weights, normalized -----------
__global__ void k_htw(const int* __restrict__ hts) {
    const int bp = blockIdx.x;
    const int b  = bp / P;
    const int hi = hts[bp*2 + 0];
    const int ti = hts[bp*2 + 1];
    const float* eh = g_eatt + (size_t)(b*NE + hi) * H * L;
    const float* et = g_eatt + (size_t)(b*NE + ti) * H * L;
    const int tid = threadIdx.x;
    float w[4];
    float lsum = 0.f;
    #pragma unroll
    for (int r = 0; r < 4; r++) {
        const int l = tid + r*256;
        float acc = 0.f;
        #pragma unroll
        for (int hh = 0; hh < H; hh++)
            acc += eh[hh*L + l] * et[hh*L + l];
        w[r] = acc;
        lsum += acc;
    }
    __shared__ float red[256];
    red[tid] = lsum;
    __syncthreads();
    for (int s = 128; s > 0; s >>= 1) {
        if (tid < s) red[tid] += red[tid + s];
        __syncthreads();
    }
    const float total = red[0];
    const float scale = 1.f / ((float)H * (total / (float)H + 1e-5f));
    float* outp = g_htw + (size_t)bp * L;
    #pragma unroll
    for (int r = 0; r < 4; r++)
        outp[tid + r*256] = w[r] * scale;
}

// ---------------- kernel 4: rs = ht_w @ seq  (128x64 tile, f32x2) ----------
__global__ void k_rs(const float* __restrict__ seq) {
    const int b  = blockIdx.z;
    const int p0 = blockIdx.y * 128;
    const int n0 = blockIdx.x * 64;
    const float* A  = g_htw + (size_t)(b*P + p0) * L;
    const float* Bm = seq   + (size_t)b * L * D;
    __shared__ ull As2[16][128];
    __shared__ __align__(16) float Bs[16][64];
    const int tid = threadIdx.x;
    const int tx = tid & 7, ty = tid >> 3;      // tx: 8 n-octets, ty: 32 row-quads
    ull acc[4][4] = {};
    for (int k0 = 0; k0 < L; k0 += 16) {
        {
            const int m = tid >> 1, kk = (tid & 1) * 8;
            const float* src = A + (size_t)m * L + k0 + kk;
            float4 v0 = *(const float4*)src;
            float4 v1 = *(const float4*)(src + 4);
            As2[kk+0][m] = pack2(v0.x, v0.x); As2[kk+1][m] = pack2(v0.y, v0.y);
            As2[kk+2][m] = pack2(v0.z, v0.z); As2[kk+3][m] = pack2(v0.w, v0.w);
            As2[kk+4][m] = pack2(v1.x, v1.x); As2[kk+5][m] = pack2(v1.y, v1.y);
            As2[kk+6][m] = pack2(v1.z, v1.z); As2[kk+7][m] = pack2(v1.w, v1.w);
            *(float4*)&Bs[tid >> 4][(tid & 15) * 4] =
                *(const float4*)&Bm[(size_t)(k0 + (tid >> 4))*D + n0 + (tid & 15)*4];
        }
        __syncthreads();
        #pragma unroll
        for (int k = 0; k < 16; k++) {
            ull a0 = As2[k][ty*4+0], a1 = As2[k][ty*4+1];
            ull a2 = As2[k][ty*4+2], a3 = As2[k][ty*4+3];
            const ull* bp = (const ull*)&Bs[k][tx*8];
            ull b0 = bp[0], b1 = bp[1], b2 = bp[2], b3 = bp[3];
            fma2(acc[0][0],a0,b0); fma2(acc[0][1],a0,b1); fma2(acc[0][2],a0,b2); fma2(acc[0][3],a0,b3);
            fma2(acc[1][0],a1,b0); fma2(acc[1][1],a1,b1); fma2(acc[1][2],a1,b2); fma2(acc[1][3],a1,b3);
            fma2(acc[2][0],a2,b0); fma2(acc[2][1],a2,b1); fma2(acc[2][2],a2,b2); fma2(acc[2][3],a2,b3);
            fma2(acc[3][0],a3,b0); fma2(acc[3][1],a3,b1); fma2(acc[3][2],a3,b2); fma2(acc[3][3],a3,b3);
        }
        __syncthreads();
    }
    #pragma unroll
    for (int i = 0; i < 4; i++) {
        const size_t row = (size_t)(b*P + p0 + ty*4 + i);
        #pragma unroll
        for (int u = 0; u < 4; u++) {
            float2 v = unpack2(acc[i][u]);
            *(float2*)&g_rs[row*D + n0 + tx*8 + u*2] = v;
        }
    }
}

// ---- kernel 5: merged extractors z = tanh([gathered_emb, rs] @ W + b) -----
__global__ void k_extract(const float* __restrict__ Wh, const float* __restrict__ bh,
                          const float* __restrict__ Wt, const float* __restrict__ bt,
                          const int* __restrict__ hts) {
    const int which = blockIdx.z;
    const float* W    = which ? Wt : Wh;
    const float* bias = which ? bt : bh;
    float* outb = which ? g_zo : g_zs;
    const int n0 = blockIdx.x * 64;
    const int r0 = blockIdx.y * 128;
    __shared__ ull As2[16][128];
    __shared__ __align__(16) float Bs[16][64];
    __shared__ const float* arow[128];
    const int tid = threadIdx.x;
    if (tid < 128) {
        const int row = r0 + tid;
        arow[tid] = g_eemb + (size_t)((row / P) * NE + hts[row*2 + which]) * D;
    }
    __syncthreads();
    const int tx = tid & 7, ty = tid >> 3;
    ull acc[4][4] = {};
    for (int k0 = 0; k0 < KD; k0 += 16) {
        {
            const int m = tid >> 1, kk = (tid & 1) * 8;
            const float* src = (k0 < D) ? (arow[m] + k0 + kk)
                                        : (g_rs + (size_t)(r0 + m)*D + (k0 - D) + kk);
            float4 v0 = *(const float4*)src;
            float4 v1 = *(const float4*)(src + 4);
            As2[kk+0][m] = pack2(v0.x, v0.x); As2[kk+1][m] = pack2(v0.y, v0.y);
            As2[kk+2][m] = pack2(v0.z, v0.z); As2[kk+3][m] = pack2(v0.w, v0.w);
            As2[kk+4][m] = pack2(v1.x, v1.x); As2[kk+5][m] = pack2(v1.y, v1.y);
            As2[kk+6][m] = pack2(v1.z, v1.z); As2[kk+7][m] = pack2(v1.w, v1.w);
            *(float4*)&Bs[tid >> 4][(tid & 15) * 4] =
                *(const float4*)&W[(size_t)(k0 + (tid >> 4))*D + n0 + (tid & 15)*4];
        }
        __syncthreads();
        #pragma unroll
        for (int k = 0; k < 16; k++) {
            ull a0 = As2[k][ty*4+0], a1 = As2[k][ty*4+1];
            ull a2 = As2[k][ty*4+2], a3 = As2[k][ty*4+3];
            const ull* bp = (const ull*)&Bs[k][tx*8];
            ull b0 = bp[0], b1 = bp[1], b2 = bp[2], b3 = bp[3];
            fma2(acc[0][0],a0,b0); fma2(acc[0][1],a0,b1); fma2(acc[0][2],a0,b2); fma2(acc[0][3],a0,b3);
            fma2(acc[1][0],a1,b0); fma2(acc[1][1],a1,b1); fma2(acc[1][2],a1,b2); fma2(acc[1][3],a1,b3);
            fma2(acc[2][0],a2,b0); fma2(acc[2][1],a2,b1); fma2(acc[2][2],a2,b2); fma2(acc[2][3],a2,b3);
            fma2(acc[3][0],a3,b0); fma2(acc[3][1],a3,b1); fma2(acc[3][2],a3,b2); fma2(acc[3][3],a3,b3);
        }
        __syncthreads();
    }
    #pragma unroll
    for (int i = 0; i < 4; i++) {
        const size_t row = (size_t)(r0 + ty*4 + i);
        #pragma unroll
        for (int u = 0; u < 4; u++) {
            const int n = n0 + tx*8 + u*2;
            float2 v = unpack2(acc[i][u]);
            float2 bb = *(const float2*)&bias[n];
            float2 o;
            o.x = tanhf(v.x + bb.x);
            o.y = tanhf(v.y + bb.y);
            *(float2*)&outb[row*D + n] = o;
        }
    }
}

// ---- kernel 6: grouped bilinear logits (labels 0..95), j-packed f32x2 -----
// Dynamic smem: zosP[64*32] ull | zss[4096] float | WsP[4][32*97] ull = 132096 B
#define LNT 256
__global__ __launch_bounds__(LNT, 1) void k_logits(const float* __restrict__ Wbi) {
    const int g  = blockIdx.y;
    const int r0 = blockIdx.x * 64;
    extern __shared__ ull sh[];
    ull*   zosP = sh;                       // 2048 ull
    float* zss  = (float*)(sh + 2048);      // 4096 floats (2048 ull)
    ull*   WsP  = sh + 4096;                // 4 * 3104 ull
    const int tid = threadIdx.x;
    const int tx = tid & 31, ty = tid >> 5; // ty in [0,8)
    const float* Wg = Wbi + (size_t)g * BLKSZ * BLKSZ * NL;

    // stage zo (paired over j) and zs slices for this (g, row-block)
    for (int t = tid; t < 2048; t += LNT) {
        const int row = t >> 5, jp = t & 31;
        zosP[t] = *(const ull*)&g_zo[(size_t)(r0 + row)*D + g*BLKSZ + jp*2];
    }
    for (int t = tid; t < 4096; t += LNT) {
        const int row = t >> 6, i = t & 63;
        zss[t] = g_zs[(size_t)(r0 + row)*D + g*BLKSZ + i];
    }

    ull acc[8][3] = {};
    for (int i0 = 0; i0 < BLKSZ; i0 += 4) {
        __syncthreads();
        {   // stage 4 W i-slices, interleaving j-pairs into ull lanes
            const int n = tid & 127, jb = tid >> 7;     // jb in {0,1}
            if (n < NL) {
                #pragma unroll
                for (int s = 0; s < 4; s++) {
                    const float* src = Wg + (size_t)(i0 + s) * BLKSZ * NL;
                    float* Wf = (float*)(WsP + s * 3104);
                    #pragma unroll
                    for (int j0 = 0; j0 < 32; j0++) {
                        const int j = jb + j0*2;
                        Wf[(((j >> 1) * NL) + n)*2 + (j & 1)] = src[j*NL + n];
                    }
                }
            }
        }
        __syncthreads();
        #pragma unroll
        for (int s = 0; s < 4; s++) {
            const ull* Wp = WsP + s * 3104 + tx;
            ull tmp[8][3] = {};
            #pragma unroll 4
            for (int jp = 0; jp < 32; jp++) {
                const ull w0 = Wp[jp*NL], w1 = Wp[jp*NL + 32], w2 = Wp[jp*NL + 64];
                #pragma unroll
                for (int pp = 0; pp < 8; pp++) {
                    const ull zop = zosP[(ty + 8*pp)*32 + jp];
                    fma2(tmp[pp][0], zop, w0);
                    fma2(tmp[pp][1], zop, w1);
                    fma2(tmp[pp][2], zop, w2);
                }
            }
            const int i = i0 + s;
            #pragma unroll
            for (int pp = 0; pp < 8; pp++) {
                const float zi = zss[(ty + 8*pp)*64 + i];
                const ull zp = pack2(zi, zi);
                fma2(acc[pp][0], zp, tmp[pp][0]);
                fma2(acc[pp][1], zp, tmp[pp][1]);
                fma2(acc[pp][2], zp, tmp[pp][2]);
            }
        }
    }
    float* outp = g_part + ((size_t)g * ROWS + r0) * NL;
    #pragma unroll
    for (int pp = 0; pp < 8; pp++) {
        const int row = ty + 8*pp;
        #pragma unroll
        for (int nn = 0; nn < 3; nn++) {
            float2 u = unpack2(acc[pp][nn]);
            outp[row*NL + tx + 32*nn] = u.x + u.y;
        }
        if (tx == 0) outp[row*NL + 96] = 0.f;   // col 96 filled by k_col96 (g=0 slice)
    }
}

// ---- kernel 6b: label 96 column (full bilinear for n=96, all groups) ------
__global__ void k_col96(const float* __restrict__ Wbi) {
    const int r0 = blockIdx.x * 64;           // 32 blocks
    __shared__ __align__(16) float Wc[64*64];
    __shared__ __align__(16) float zsh[64*64];
    const int tid = threadIdx.x;              // 256
    const int wid = tid >> 5, tx = tid & 31;
    float acc[8] = {};
    for (int g = 0; g < GB; g++) {
        __syncthreads();
        for (int t = tid; t < 4096; t += 256) {
            Wc[t]  = Wbi[(size_t)(g*4096 + t)*NL + 96];
            zsh[t] = g_zs[(size_t)(r0 + (t >> 6))*D + g*BLKSZ + (t & 63)];
        }
        __syncthreads();
        #pragma unroll
        for (int rr = 0; rr < 8; rr++) {
            const int rl = wid*8 + rr;
            ull v = 0;
            #pragma unroll 8
            for (int i = 0; i < 64; i++) {
                const float zi = zsh[rl*64 + i];
                const ull zp = pack2(zi, zi);
                const ull w = *(const ull*)&Wc[i*64 + tx*2];
                fma2(v, zp, w);
            }
            float2 vv = unpack2(v);
            const float2 zop = *(const float2*)&g_zo[(size_t)(r0 + rl)*D + g*BLKSZ + tx*2];
            float d = vv.x * zop.x + vv.y * zop.y;
            #pragma unroll
            for (int off = 16; off > 0; off >>= 1)
                d += __shfl_xor_sync(0xffffffffu, d, off);
            acc[rr] += d;
        }
    }
    if (tx == 0) {
        #pragma unroll
        for (int rr = 0; rr < 8; rr++)
            g_part[(size_t)(r0 + wid*8 + rr)*NL + 96] = acc[rr];  // g=0 slice
    }
}

// ---- kernel 7: reduce partials over g, add bias ---------------------------
__global__ void k_reduce(const float* __restrict__ b_bi, float* __restrict__ out) {
    const int idx = blockIdx.x * 256 + threadIdx.x;
    if (idx >= ROWS * NL) return;
    const int n = idx % NL;
    float s = b_bi[n];
    #pragma unroll
    for (int g = 0; g < GB; g++)
        s += g_part[(size_t)g * (ROWS*NL) + idx];
    out[idx] = s;
}

// ---------------------------------------------------------------------------
extern "C" void kernel_launch(void* const* d_in, const int* in_sizes, int n_in,
                              void* d_out, int out_size) {
    const float* seq    = (const float*)d_in[0];
    const float* att    = (const float*)d_in[1];
    const int*   mpos   = (const int*)d_in[2];
    const int*   hts    = (const int*)d_in[3];
    const float* W_head = (const float*)d_in[4];
    const float* b_head = (const float*)d_in[5];
    const float* W_tail = (const float*)d_in[6];
    const float* b_tail = (const float*)d_in[7];
    const float* W_bi   = (const float*)d_in[8];
    const float* b_bi   = (const float*)d_in[9];
    float* out = (float*)d_out;

    cudaFuncSetAttribute(k_logits, cudaFuncAttributeMaxDynamicSharedMemorySize, 132096);

    k_eemb<<<B*NE, 256>>>(seq, mpos);
    k_eatt<<<B*NE*H, 256>>>(att, mpos);
    k_htw<<<B*P, 256>>>(hts);

    dim3 grs(D/64, P/128, B);
    k_rs<<<grs, 256>>>(seq);

    dim3 gex(D/64, ROWS/128, 2);
    k_extract<<<gex, 256>>>(W_head, b_head, W_tail, b_tail, hts);

    dim3 glg(ROWS/64, GB);
    k_logits<<<glg, LNT, 132096>>>(W_bi);
    k_col96<<<ROWS/64, 256>>>(W_bi);

    k_reduce<<<(ROWS*NL + 255)/256, 256>>>(b_bi, out);
}

// round 3
// speedup vs baseline: 1.8522x; 1.8522x over previous
#include <cuda_runtime.h>
#include <cuda_fp16.h>
#include <math.h>
#include <stdint.h>

#define B 4
#define L 1024
#define D 768
#define H 12
#define NE 42
#define MM 4
#define P 512
#define BLKSZ 64
#define NL 97
#define GB 12          // D / BLKSZ
#define KD 1536        // 2*D
#define ROWS (B*P)     // 2048

// ---------------- scratch (device globals; no allocation allowed) ----------
__device__ __align__(16) float g_eemb[B*NE*D];
__device__ __align__(16) float g_eatt[B*NE*H*L];
__device__ __align__(16) float g_htw[B*P*L];
__device__ __align__(16) float g_rs[(size_t)ROWS*D];
__device__ __align__(16) float g_zs[(size_t)ROWS*D];
__device__ __align__(16) float g_zo[(size_t)ROWS*D];
__device__ __align__(16) float g_part[(size_t)GB*ROWS*NL];
// fragment-ready W_bi (hi/lo fp16 split): [g][kstep s:256][ntile t:13][lane:32] uint2
__device__ __align__(16) uint2 g_Whi[(size_t)GB*256*13*32];
__device__ __align__(16) uint2 g_Wlo[(size_t)GB*256*13*32];

// ---- half2 helpers --------------------------------------------------------
__device__ __forceinline__ unsigned h2pack(float a, float b) {
    __half2 h = __float22half2_rn(make_float2(a, b));
    return reinterpret_cast<unsigned&>(h);
}
__device__ __forceinline__ float2 h2unpack(unsigned u) {
    __half2 h = reinterpret_cast<__half2&>(u);
    return __half22float2(h);
}

// ---- mma.sync m16n8k16 fp16 -> fp32 ---------------------------------------
__device__ __forceinline__ void mma16816(float* d, const unsigned* a, unsigned b0, unsigned b1) {
    asm volatile(
        "mma.sync.aligned.m16n8k16.row.col.f32.f16.f16.f32 "
        "{%0,%1,%2,%3}, {%4,%5,%6,%7}, {%8,%9}, {%0,%1,%2,%3};"
        : "+f"(d[0]), "+f"(d[1]), "+f"(d[2]), "+f"(d[3])
        : "r"(a[0]), "r"(a[1]), "r"(a[2]), "r"(a[3]), "r"(b0), "r"(b1));
}

// ---------------- kernel 1: entity embeddings (logsumexp over mentions) ----
__global__ void k_eemb(const float* __restrict__ seq, const int* __restrict__ mpos) {
    const int be = blockIdx.x;
    const int b = be / NE;
    __shared__ int pos[MM];
    if (threadIdx.x < MM) pos[threadIdx.x] = mpos[be*MM + threadIdx.x] + 1;
    __syncthreads();
    const float* sb = seq + (size_t)b * L * D;
    for (int d = threadIdx.x; d < D; d += blockDim.x) {
        float v0 = sb[(size_t)pos[0]*D + d];
        float v1 = sb[(size_t)pos[1]*D + d];
        float v2 = sb[(size_t)pos[2]*D + d];
        float v3 = sb[(size_t)pos[3]*D + d];
        float mx = fmaxf(fmaxf(v0, v1), fmaxf(v2, v3));
        float s = expf(v0-mx) + expf(v1-mx) + expf(v2-mx) + expf(v3-mx);
        g_eemb[(size_t)be*D + d] = mx + logf(s);
    }
}

// ---------------- kernel 2: entity attentions (mean over mention rows) -----
__global__ void k_eatt(const float* __restrict__ att, const int* __restrict__ mpos) {
    const int idx = blockIdx.x;
    const int h  = idx % H;
    const int be = idx / H;
    const int b  = be / NE;
    __shared__ int pos[MM];
    if (threadIdx.x < MM) pos[threadIdx.x] = mpos[be*MM + threadIdx.x] + 1;
    __syncthreads();
    const float* ab = att + (size_t)(b*H + h) * L * L;
    float* outp = g_eatt + ((size_t)be*H + h) * L;
    for (int l = threadIdx.x; l < L; l += blockDim.x) {
        float s = ab[(size_t)pos[0]*L + l] + ab[(size_t)pos[1]*L + l]
                + ab[(size_t)pos[2]*L + l] + ab[(size_t)pos[3]*L + l];
        outp[l] = 0.25f * s;
    }
}

// ---------------- kernel 3: per-pair channel weights, normalized -----------
__global__ void k_htw(const int* __restrict__ hts) {
    const int bp = blockIdx.x;
    const int b  = bp / P;
    const int hi = hts[bp*2 + 0];
    const int ti = hts[bp*2 + 1];
    const float* eh = g_eatt + (size_t)(b*NE + hi) * H * L;
    const float* et = g_eatt + (size_t)(b*NE + ti) * H * L;
    const int tid = threadIdx.x;
    float w[4];
    float lsum = 0.f;
    #pragma unroll
    for (int r = 0; r < 4; r++) {
        const int l = tid + r*256;
        float acc = 0.f;
        #pragma unroll
        for (int hh = 0; hh < H; hh++)
            acc += eh[hh*L + l] * et[hh*L + l];
        w[r] = acc;
        lsum += acc;
    }
    __shared__ float red[256];
    red[tid] = lsum;
    __syncthreads();
    for (int s = 128; s > 0; s >>= 1) {
        if (tid < s) red[tid] += red[tid + s];
        __syncthreads();
    }
    const float total = red[0];
    const float scale = 1.f / ((float)H * (total / (float)H + 1e-5f));
    float* outp = g_htw + (size_t)bp * L;
    #pragma unroll
    for (int r = 0; r < 4; r++)
        outp[tid + r*256] = w[r] * scale;
}

// ---------------- kernel 4: rs = ht_w @ seq (round-1 proven version) -------
__global__ void k_rs(const float* __restrict__ seq) {
    const int b  = blockIdx.z;
    const int p0 = blockIdx.y * 64;
    const int n0 = blockIdx.x * 64;
    const float* A  = g_htw + (size_t)b * P * L;
    const float* Bm = seq   + (size_t)b * L * D;
    __shared__ float As[16][64];
    __shared__ float Bs[16][64];
    const int tid = threadIdx.x;
    const int tx = tid & 15, ty = tid >> 4;
    float acc[4][4] = {};
    for (int k0 = 0; k0 < L; k0 += 16) {
        {
            const int m  = tid >> 2;
            const int kk = (tid & 3) * 4;
            const float4 v = *(const float4*)&A[(size_t)(p0 + m)*L + k0 + kk];
            As[kk+0][m] = v.x; As[kk+1][m] = v.y; As[kk+2][m] = v.z; As[kk+3][m] = v.w;
        }
        {
            const int kr = tid >> 4;
            const int nn = (tid & 15) * 4;
            *(float4*)&Bs[kr][nn] = *(const float4*)&Bm[(size_t)(k0 + kr)*D + n0 + nn];
        }
        __syncthreads();
        #pragma unroll
        for (int k = 0; k < 16; k++) {
            const float4 a  = *(const float4*)&As[k][ty*4];
            const float4 bb = *(const float4*)&Bs[k][tx*4];
            float av[4] = {a.x, a.y, a.z, a.w};
            float bv[4] = {bb.x, bb.y, bb.z, bb.w};
            #pragma unroll
            for (int i = 0; i < 4; i++)
                #pragma unroll
                for (int j = 0; j < 4; j++)
                    acc[i][j] += av[i] * bv[j];
        }
        __syncthreads();
    }
    float* C = g_rs + (size_t)(b*P + p0) * D + n0;
    #pragma unroll
    for (int i = 0; i < 4; i++)
        #pragma unroll
        for (int j = 0; j < 4; j++)
            C[(size_t)(ty*4 + i)*D + tx*4 + j] = acc[i][j];
}

// ---- kernel 5: extractor z = tanh([gathered_emb, rs] @ W + bias) ----------
__global__ void k_extract(const float* __restrict__ W, const float* __restrict__ bias,
                          const int* __restrict__ hts, int which) {
    const int r0 = blockIdx.y * 64;
    const int n0 = blockIdx.x * 64;
    float* outb = which ? g_zo : g_zs;
    __shared__ float As[16][64];
    __shared__ float Bs[16][64];
    __shared__ const float* arow[64];
    const int tid = threadIdx.x;
    if (tid < 64) {
        const int row = r0 + tid;
        const int b = row / P;
        const int e = hts[row*2 + which];
        arow[tid] = g_eemb + (size_t)(b*NE + e) * D;
    }
    __syncthreads();
    const int tx = tid & 15, ty = tid >> 4;
    float acc[4][4] = {};
    for (int k0 = 0; k0 < KD; k0 += 16) {
        {
            const int m  = tid >> 2;
            const int kk = (tid & 3) * 4;
            const int k  = k0 + kk;
            float4 v;
            if (k < D) v = *(const float4*)&arow[m][k];
            else       v = *(const float4*)&g_rs[(size_t)(r0 + m)*D + (k - D)];
            As[kk+0][m] = v.x; As[kk+1][m] = v.y; As[kk+2][m] = v.z; As[kk+3][m] = v.w;
        }
        {
            const int kr = tid >> 4;
            const int nn = (tid & 15) * 4;
            *(float4*)&Bs[kr][nn] = *(const float4*)&W[(size_t)(k0 + kr)*D + n0 + nn];
        }
        __syncthreads();
        #pragma unroll
        for (int k = 0; k < 16; k++) {
            const float4 a  = *(const float4*)&As[k][ty*4];
            const float4 bb = *(const float4*)&Bs[k][tx*4];
            float av[4] = {a.x, a.y, a.z, a.w};
            float bv[4] = {bb.x, bb.y, bb.z, bb.w};
            #pragma unroll
            for (int i = 0; i < 4; i++)
                #pragma unroll
                for (int j = 0; j < 4; j++)
                    acc[i][j] += av[i] * bv[j];
        }
        __syncthreads();
    }
    float* C = outb + (size_t)(r0) * D + n0;
    #pragma unroll
    for (int i = 0; i < 4; i++)
        #pragma unroll
        for (int j = 0; j < 4; j++)
            C[(size_t)(ty*4 + i)*D + tx*4 + j] =
                tanhf(acc[i][j] + bias[n0 + tx*4 + j]);
}

// ---- kernel 6a: convert W_bi into fragment-ready fp16 hi/lo layouts -------
// out[(g*256+s)*13 + t][lane] : .x = half2(W[k0,n],W[k0+1,n]), .y = k0+8,+9
// where k0 = (lane&3)*2 (within 16-k step), n = t*8 + (lane>>2)
__global__ void k_cvt(const float* __restrict__ Wbi) {
    const int s = blockIdx.x, g = blockIdx.y;
    __shared__ float sm[16][104];
    const int tid = threadIdx.x;  // 128
    for (int idx = tid; idx < 16*104; idx += 128) ((float*)sm)[idx] = 0.f;
    __syncthreads();
    for (int idx = tid; idx < 16*97; idx += 128) {
        const int kr = idx / 97, n = idx % 97;
        sm[kr][n] = Wbi[(size_t)(g*4096 + s*16 + kr)*NL + n];
    }
    __syncthreads();
    for (int o = tid; o < 13*32; o += 128) {
        const int t = o >> 5, lane = o & 31;
        const int n = t*8 + (lane >> 2), kk = (lane & 3)*2;
        float w00 = sm[kk][n],   w01 = sm[kk+1][n];
        float w08 = sm[kk+8][n], w09 = sm[kk+9][n];
        unsigned h0 = h2pack(w00, w01);
        unsigned h1 = h2pack(w08, w09);
        float2 f0 = h2unpack(h0), f1 = h2unpack(h1);
        unsigned l0 = h2pack(w00 - f0.x, w01 - f0.y);
        unsigned l1 = h2pack(w08 - f1.x, w09 - f1.y);
        const size_t oi = ((size_t)(g*256 + s)*13 + t)*32 + lane;
        g_Whi[oi] = make_uint2(h0, h1);
        g_Wlo[oi] = make_uint2(l0, l1);
    }
}

// ---- kernel 6b: bilinear logits via HMMA, 3-pass fp16 compensated ---------
// grid (16 row-blocks, 12 g); 8 warps = 4 M-groups(32 rows) x 2 N-halves
#define ZS_STR 66
#define ZO_STR 72
__global__ __launch_bounds__(256, 2) void k_blmma() {
    const int g  = blockIdx.y;
    const int r0 = blockIdx.x * 128;
    extern __shared__ float sh[];
    float* zs_s = sh;                      // [128][ZS_STR]
    float* zo_s = sh + 128*ZS_STR;         // [128][ZO_STR]
    const int tid = threadIdx.x, lane = tid & 31, wid = tid >> 5;
    const int wm = wid & 3, nh = wid >> 2;
    const int t0 = nh ? 7 : 0;

    for (int idx = tid; idx < 128*16; idx += 256) {
        const int row = idx >> 4, c4 = (idx & 15) * 4;
        float4 a = *(const float4*)&g_zs[(size_t)(r0+row)*D + g*BLKSZ + c4];
        zs_s[row*ZS_STR + c4+0] = a.x; zs_s[row*ZS_STR + c4+1] = a.y;
        zs_s[row*ZS_STR + c4+2] = a.z; zs_s[row*ZS_STR + c4+3] = a.w;
        float4 b = *(const float4*)&g_zo[(size_t)(r0+row)*D + g*BLKSZ + c4];
        zo_s[row*ZO_STR + c4+0] = b.x; zo_s[row*ZO_STR + c4+1] = b.y;
        zo_s[row*ZO_STR + c4+2] = b.z; zo_s[row*ZO_STR + c4+3] = b.w;
    }
    __syncthreads();

    float acc[2][7][4] = {};
    const int rl = wm*32 + (lane >> 2);
    const int k0 = (lane & 3)*2;
    const uint2* __restrict__ Wh = g_Whi + (size_t)g*256*13*32;
    const uint2* __restrict__ Wl = g_Wlo + (size_t)g*256*13*32;

    for (int s = 0; s < 256; s++) {
        const int i  = s >> 2;
        const int jb = ((s & 3) << 4) + k0;
        unsigned ah[2][4], al[2][4];
        #pragma unroll
        for (int m = 0; m < 2; m++) {
            const int r = rl + m*16;
            const float zs0 = zs_s[r*ZS_STR + i];
            const float zs1 = zs_s[(r+8)*ZS_STR + i];
            const float2 x0 = *(const float2*)&zo_s[r*ZO_STR + jb];
            const float2 x1 = *(const float2*)&zo_s[r*ZO_STR + jb + 8];
            const float2 y0 = *(const float2*)&zo_s[(r+8)*ZO_STR + jb];
            const float2 y1 = *(const float2*)&zo_s[(r+8)*ZO_STR + jb + 8];
            const float v00 = zs0*x0.x, v01 = zs0*x0.y, v02 = zs0*x1.x, v03 = zs0*x1.y;
            const float v10 = zs1*y0.x, v11 = zs1*y0.y, v12 = zs1*y1.x, v13 = zs1*y1.y;
            // A-fragment mapping: a0=(r,k0..k0+1) a1=(r+8,..) a2=(r,k0+8..) a3=(r+8,k0+8..)
            ah[m][0] = h2pack(v00, v01); ah[m][1] = h2pack(v10, v11);
            ah[m][2] = h2pack(v02, v03); ah[m][3] = h2pack(v12, v13);
            float2 f;
            f = h2unpack(ah[m][0]); al[m][0] = h2pack(v00 - f.x, v01 - f.y);
            f = h2unpack(ah[m][1]); al[m][1] = h2pack(v10 - f.x, v11 - f.y);
            f = h2unpack(ah[m][2]); al[m][2] = h2pack(v02 - f.x, v03 - f.y);
            f = h2unpack(ah[m][3]); al[m][3] = h2pack(v12 - f.x, v13 - f.y);
        }
        #pragma unroll
        for (int t = 0; t < 7; t++) {
            if (t0 + t < 13) {
                const size_t bi = ((size_t)s*13 + t0 + t)*32 + lane;
                const uint2 bh = __ldg(&Wh[bi]);
                const uint2 bl = __ldg(&Wl[bi]);
                #pragma unroll
                for (int m = 0; m < 2; m++) {
                    mma16816(acc[m][t], ah[m], bh.x, bh.y);
                    mma16816(acc[m][t], al[m], bh.x, bh.y);
                    mma16816(acc[m][t], ah[m], bl.x, bl.y);
                }
            }
        }
    }

    // write partials: c0,c1 -> (r, n0..n0+1); c2,c3 -> (r+8, ..)
    #pragma unroll
    for (int m = 0; m < 2; m++) {
        const int r = r0 + rl + m*16;
        #pragma unroll
        for (int t = 0; t < 7; t++) {
            if (t0 + t < 13) {
                const int n = (t0 + t)*8 + (lane & 3)*2;
                float* o0 = g_part + ((size_t)g*ROWS + r)*NL;
                float* o1 = g_part + ((size_t)g*ROWS + r + 8)*NL;
                if (n < NL)     { o0[n]   = acc[m][t][0]; o1[n]   = acc[m][t][2]; }
                if (n + 1 < NL) { o0[n+1] = acc[m][t][1]; o1[n+1] = acc[m][t][3]; }
            }
        }
    }
}

// ---- kernel 7: reduce partials over g, add bias ---------------------------
__global__ void k_reduce(const float* __restrict__ b_bi, float* __restrict__ out) {
    const int idx = blockIdx.x * 256 + threadIdx.x;
    if (idx >= ROWS * NL) return;
    const int n = idx % NL;
    float s = b_bi[n];
    #pragma unroll
    for (int g = 0; g < GB; g++)
        s += g_part[(size_t)g * (ROWS*NL) + idx];
    out[idx] = s;
}

// ---------------------------------------------------------------------------
extern "C" void kernel_launch(void* const* d_in, const int* in_sizes, int n_in,
                              void* d_out, int out_size) {
    const float* seq    = (const float*)d_in[0];
    const float* att    = (const float*)d_in[1];
    const int*   mpos   = (const int*)d_in[2];
    const int*   hts    = (const int*)d_in[3];
    const float* W_head = (const float*)d_in[4];
    const float* b_head = (const float*)d_in[5];
    const float* W_tail = (const float*)d_in[6];
    const float* b_tail = (const float*)d_in[7];
    const float* W_bi   = (const float*)d_in[8];
    const float* b_bi   = (const float*)d_in[9];
    float* out = (float*)d_out;

    const int blm_smem = (128*ZS_STR + 128*ZO_STR) * 4;  // 70656 B
    cudaFuncSetAttribute(k_blmma, cudaFuncAttributeMaxDynamicSharedMemorySize, blm_smem);

    dim3 gcv(256, GB);
    k_cvt<<<gcv, 128>>>(W_bi);

    k_eemb<<<B*NE, 256>>>(seq, mpos);
    k_eatt<<<B*NE*H, 256>>>(att, mpos);
    k_htw<<<B*P, 256>>>(hts);

    dim3 grs(D/64, P/64, B);
    k_rs<<<grs, 256>>>(seq);

    dim3 gex(D/64, ROWS/64);
    k_extract<<<gex, 256>>>(W_head, b_head, hts, 0);
    k_extract<<<gex, 256>>>(W_tail, b_tail, hts, 1);

    dim3 glg(ROWS/128, GB);
    k_blmma<<<glg, 256, blm_smem>>>();

    k_reduce<<<(ROWS*NL + 255)/256, 256>>>(b_bi, out);
}

// round 4
// speedup vs baseline: 2.3427x; 1.2648x over previous
#include <cuda_runtime.h>
#include <cuda_fp16.h>
#include <math.h>
#include <stdint.h>

#define B 4
#define L 1024
#define D 768
#define H 12
#define NE 42
#define MM 4
#define P 512
#define BLKSZ 64
#define NL 97
#define GB 12          // D / BLKSZ
#define KD 1536        // 2*D
#define ROWS (B*P)     // 2048

// ---------------- scratch (device globals; no allocation allowed) ----------
__device__ __align__(16) float g_eemb[B*NE*D];
__device__ __align__(16) __half g_ehi[B*NE*D];
__device__ __align__(16) __half g_elo[B*NE*D];
__device__ __align__(16) float g_eatt[B*NE*H*L];
__device__ __align__(16) __half g_hthi[(size_t)ROWS*L];
__device__ __align__(16) __half g_htlo[(size_t)ROWS*L];
__device__ __align__(16) __half g_rshi[(size_t)ROWS*D];
__device__ __align__(16) __half g_rslo[(size_t)ROWS*D];
__device__ __align__(16) float g_zs[(size_t)ROWS*D];
__device__ __align__(16) float g_zo[(size_t)ROWS*D];
__device__ __align__(16) float g_part[(size_t)GB*ROWS*NL];
// fragment-ready W_bi (hi/lo fp16 split): [g][kstep s:256][ntile t:13][lane:32]
__device__ __align__(16) uint2 g_Whi[(size_t)GB*256*13*32];
__device__ __align__(16) uint2 g_Wlo[(size_t)GB*256*13*32];
// fragment-ready extractor weights: [which:2][kstep:96][ntile:96][lane:32]
__device__ __align__(16) uint2 g_WxFhi[(size_t)2*96*96*32];
__device__ __align__(16) uint2 g_WxFlo[(size_t)2*96*96*32];
// fragment-ready seq: [b:4][kstep:64][ntile:96][lane:32]
__device__ __align__(16) uint2 g_seqFhi[(size_t)4*64*96*32];
__device__ __align__(16) uint2 g_seqFlo[(size_t)4*64*96*32];

// ---- half helpers ---------------------------------------------------------
__device__ __forceinline__ unsigned h2pack(float a, float b) {
    __half2 h = __float22half2_rn(make_float2(a, b));
    return reinterpret_cast<unsigned&>(h);
}
__device__ __forceinline__ float2 h2unpack(unsigned u) {
    __half2 h = reinterpret_cast<__half2&>(u);
    return __half22float2(h);
}

// ---- mma.sync m16n8k16 fp16 -> fp32 ---------------------------------------
__device__ __forceinline__ void mma16816(float* d, const unsigned* a, unsigned b0, unsigned b1) {
    asm volatile(
        "mma.sync.aligned.m16n8k16.row.col.f32.f16.f16.f32 "
        "{%0,%1,%2,%3}, {%4,%5,%6,%7}, {%8,%9}, {%0,%1,%2,%3};"
        : "+f"(d[0]), "+f"(d[1]), "+f"(d[2]), "+f"(d[3])
        : "r"(a[0]), "r"(a[1]), "r"(a[2]), "r"(a[3]), "r"(b0), "r"(b1));
}

// ---------------- kernel 1: entity embeddings + hi/lo split ----------------
__global__ void k_eemb(const float* __restrict__ seq, const int* __restrict__ mpos) {
    const int be = blockIdx.x;
    const int b = be / NE;
    __shared__ int pos[MM];
    if (threadIdx.x < MM) pos[threadIdx.x] = mpos[be*MM + threadIdx.x] + 1;
    __syncthreads();
    const float* sb = seq + (size_t)b * L * D;
    for (int d = threadIdx.x; d < D; d += blockDim.x) {
        float v0 = sb[(size_t)pos[0]*D + d];
        float v1 = sb[(size_t)pos[1]*D + d];
        float v2 = sb[(size_t)pos[2]*D + d];
        float v3 = sb[(size_t)pos[3]*D + d];
        float mx = fmaxf(fmaxf(v0, v1), fmaxf(v2, v3));
        float s = expf(v0-mx) + expf(v1-mx) + expf(v2-mx) + expf(v3-mx);
        float v = mx + logf(s);
        g_eemb[(size_t)be*D + d] = v;
        __half hv = __float2half_rn(v);
        g_ehi[(size_t)be*D + d] = hv;
        g_elo[(size_t)be*D + d] = __float2half_rn(v - __half2float(hv));
    }
}

// ---------------- kernel 2: entity attentions ------------------------------
__global__ void k_eatt(const float* __restrict__ att, const int* __restrict__ mpos) {
    const int idx = blockIdx.x;
    const int h  = idx % H;
    const int be = idx / H;
    const int b  = be / NE;
    __shared__ int pos[MM];
    if (threadIdx.x < MM) pos[threadIdx.x] = mpos[be*MM + threadIdx.x] + 1;
    __syncthreads();
    const float* ab = att + (size_t)(b*H + h) * L * L;
    float* outp = g_eatt + ((size_t)be*H + h) * L;
    for (int l = threadIdx.x; l < L; l += blockDim.x) {
        float s = ab[(size_t)pos[0]*L + l] + ab[(size_t)pos[1]*L + l]
                + ab[(size_t)pos[2]*L + l] + ab[(size_t)pos[3]*L + l];
        outp[l] = 0.25f * s;
    }
}

// ---------------- kernel 3: per-pair channel weights -> hi/lo halves -------
__global__ void k_htw(const int* __restrict__ hts) {
    const int bp = blockIdx.x;
    const int b  = bp / P;
    const int hi = hts[bp*2 + 0];
    const int ti = hts[bp*2 + 1];
    const float* eh = g_eatt + (size_t)(b*NE + hi) * H * L;
    const float* et = g_eatt + (size_t)(b*NE + ti) * H * L;
    const int tid = threadIdx.x;
    float w[4];
    float lsum = 0.f;
    #pragma unroll
    for (int r = 0; r < 4; r++) {
        const int l = tid + r*256;
        float acc = 0.f;
        #pragma unroll
        for (int hh = 0; hh < H; hh++)
            acc += eh[hh*L + l] * et[hh*L + l];
        w[r] = acc;
        lsum += acc;
    }
    __shared__ float red[256];
    red[tid] = lsum;
    __syncthreads();
    for (int s = 128; s > 0; s >>= 1) {
        if (tid < s) red[tid] += red[tid + s];
        __syncthreads();
    }
    const float total = red[0];
    const float scale = 1.f / ((float)H * (total / (float)H + 1e-5f));
    #pragma unroll
    for (int r = 0; r < 4; r++) {
        const int l = tid + r*256;
        float v = w[r] * scale;
        __half hv = __float2half_rn(v);
        g_hthi[(size_t)bp*L + l] = hv;
        g_htlo[(size_t)bp*L + l] = __float2half_rn(v - __half2float(hv));
    }
}

// ---- conversion: a [16 x 768] fp32 slab -> fragment-ready hi/lo -----------
__device__ __forceinline__ void cvt_slab(const float* __restrict__ src,
                                         uint2* __restrict__ dhi, uint2* __restrict__ dlo) {
    extern __shared__ float smf[];             // [16][772]
    const int tid = threadIdx.x;               // 256
    for (int idx = tid; idx < 16*768; idx += 256) {
        const int kr = idx / 768, n = idx - kr*768;
        smf[kr*772 + n] = src[(size_t)kr*768 + n];
    }
    __syncthreads();
    for (int o = tid; o < 96*32; o += 256) {
        const int nt = o >> 5, lane = o & 31;
        const int n = nt*8 + (lane >> 2), k0 = (lane & 3)*2;
        float w00 = smf[(k0  )*772 + n], w01 = smf[(k0+1)*772 + n];
        float w08 = smf[(k0+8)*772 + n], w09 = smf[(k0+9)*772 + n];
        unsigned h0 = h2pack(w00, w01), h1 = h2pack(w08, w09);
        float2 f0 = h2unpack(h0), f1 = h2unpack(h1);
        unsigned l0 = h2pack(w00 - f0.x, w01 - f0.y);
        unsigned l1 = h2pack(w08 - f1.x, w09 - f1.y);
        dhi[(size_t)nt*32 + lane] = make_uint2(h0, h1);
        dlo[(size_t)nt*32 + lane] = make_uint2(l0, l1);
    }
}

__global__ void k_cvtW(const float* __restrict__ Wh, const float* __restrict__ Wt) {
    const int ks = blockIdx.x, which = blockIdx.y;
    const float* src = (which ? Wt : Wh) + (size_t)ks*16*768;
    const size_t o = ((size_t)which*96 + ks)*96*32;
    cvt_slab(src, g_WxFhi + o, g_WxFlo + o);
}

__global__ void k_cvtseq(const float* __restrict__ seq) {
    const int ks = blockIdx.x, b = blockIdx.y;
    const float* src = seq + (size_t)b*L*D + (size_t)ks*16*768;
    const size_t o = ((size_t)b*64 + ks)*96*32;
    cvt_slab(src, g_seqFhi + o, g_seqFlo + o);
}

// ---- kernel 4: rs = htw @ seq via HMMA (3-pass compensated) ---------------
// grid (12 ntile-blocks, 4 row-blocks, 4 batches), 256 threads
__global__ __launch_bounds__(256, 2) void k_rs_mma() {
    const int b  = blockIdx.z;
    const int p0 = blockIdx.y * 128;
    __shared__ __half Ah[128*72], Al[128*72];
    const int tid = threadIdx.x, lane = tid & 31, wid = tid >> 5;
    const int wm = wid & 3, wn = wid >> 2;
    const size_t rowbase = (size_t)(b*P + p0);
    float acc[2][4][4] = {};
    const int rb = wm*32 + (lane >> 2);
    for (int c0 = 0; c0 < L; c0 += 64) {
        __syncthreads();
        for (int idx = tid; idx < 4096; idx += 256) {
            const int row = idx >> 5, c2 = (idx & 31)*2;
            const size_t o = (rowbase + row)*L + c0 + c2;
            *(unsigned*)&Ah[row*72 + c2] = *(const unsigned*)&g_hthi[o];
            *(unsigned*)&Al[row*72 + c2] = *(const unsigned*)&g_htlo[o];
        }
        __syncthreads();
        #pragma unroll
        for (int kk = 0; kk < 4; kk++) {
            const int ksg = (c0 >> 4) + kk;
            const int kloc = kk*16 + (lane & 3)*2;
            unsigned ah[2][4], al[2][4];
            #pragma unroll
            for (int m = 0; m < 2; m++) {
                const int r = rb + m*16;
                ah[m][0] = *(const unsigned*)&Ah[ r   *72 + kloc];
                ah[m][1] = *(const unsigned*)&Ah[(r+8)*72 + kloc];
                ah[m][2] = *(const unsigned*)&Ah[ r   *72 + kloc + 8];
                ah[m][3] = *(const unsigned*)&Ah[(r+8)*72 + kloc + 8];
                al[m][0] = *(const unsigned*)&Al[ r   *72 + kloc];
                al[m][1] = *(const unsigned*)&Al[(r+8)*72 + kloc];
                al[m][2] = *(const unsigned*)&Al[ r   *72 + kloc + 8];
                al[m][3] = *(const unsigned*)&Al[(r+8)*72 + kloc + 8];
            }
            #pragma unroll
            for (int t = 0; t < 4; t++) {
                const int nt = blockIdx.x*8 + wn*4 + t;
                const size_t bi = (((size_t)b*64 + ksg)*96 + nt)*32 + lane;
                const uint2 bh = g_seqFhi[bi];
                const uint2 bl = g_seqFlo[bi];
                #pragma unroll
                for (int m = 0; m < 2; m++) {
                    mma16816(acc[m][t], ah[m], bh.x, bh.y);
                    mma16816(acc[m][t], al[m], bh.x, bh.y);
                    mma16816(acc[m][t], ah[m], bl.x, bl.y);
                }
            }
        }
    }
    #pragma unroll
    for (int m = 0; m < 2; m++) {
        const size_t r = rowbase + wm*32 + m*16 + (lane >> 2);
        #pragma unroll
        for (int t = 0; t < 4; t++) {
            const int n = blockIdx.x*64 + wn*32 + t*8 + (lane & 3)*2;
            #pragma unroll
            for (int h = 0; h < 2; h++) {          // h=0 -> row r, h=1 -> row r+8
                const size_t rr = r + h*8;
                const float v0 = acc[m][t][h*2+0], v1 = acc[m][t][h*2+1];
                __half h0 = __float2half_rn(v0), h1 = __float2half_rn(v1);
                *(unsigned*)&g_rshi[rr*D + n] = h2pack(0.f,0.f)*0u |
                    (unsigned)(__half_as_ushort(h0)) | ((unsigned)__half_as_ushort(h1) << 16);
                __half l0 = __float2half_rn(v0 - __half2float(h0));
                __half l1 = __float2half_rn(v1 - __half2float(h1));
                *(unsigned*)&g_rslo[rr*D + n] =
                    (unsigned)(__half_as_ushort(l0)) | ((unsigned)__half_as_ushort(l1) << 16);
            }
        }
    }
}

// ---- kernel 5: extractors via HMMA (3-pass), merged head/tail -------------
// grid (12 ntile-blocks, 16 row-blocks, 2 which), 256 threads
__global__ __launch_bounds__(256, 2) void k_extract_mma(
        const float* __restrict__ bh_, const float* __restrict__ bt_,
        const int* __restrict__ hts) {
    const int which = blockIdx.z;
    const int r0 = blockIdx.y * 128;
    __shared__ __half Ah[128*72], Al[128*72];
    __shared__ int ebase[128];
    const int tid = threadIdx.x, lane = tid & 31, wid = tid >> 5;
    const int wm = wid & 3, wn = wid >> 2;
    if (tid < 128) {
        const int row = r0 + tid;
        ebase[tid] = ((row / P)*NE + hts[row*2 + which]) * D;
    }
    const uint2* __restrict__ WFh = g_WxFhi + (size_t)which*96*96*32;
    const uint2* __restrict__ WFl = g_WxFlo + (size_t)which*96*96*32;
    float acc[2][4][4] = {};
    const int rb = wm*32 + (lane >> 2);
    for (int c0 = 0; c0 < KD; c0 += 64) {
        __syncthreads();
        const bool fromE = (c0 < D);
        for (int idx = tid; idx < 4096; idx += 256) {
            const int row = idx >> 5, c2 = (idx & 31)*2;
            size_t o;
            if (fromE) o = (size_t)ebase[row] + c0 + c2;
            else       o = (size_t)(r0 + row)*D + (c0 - D) + c2;
            const __half* sh = fromE ? g_ehi : g_rshi;
            const __half* sl = fromE ? g_elo : g_rslo;
            *(unsigned*)&Ah[row*72 + c2] = *(const unsigned*)&sh[o];
            *(unsigned*)&Al[row*72 + c2] = *(const unsigned*)&sl[o];
        }
        __syncthreads();
        #pragma unroll
        for (int kk = 0; kk < 4; kk++) {
            const int ksg = (c0 >> 4) + kk;
            const int kloc = kk*16 + (lane & 3)*2;
            unsigned ah[2][4], al[2][4];
            #pragma unroll
            for (int m = 0; m < 2; m++) {
                const int r = rb + m*16;
                ah[m][0] = *(const unsigned*)&Ah[ r   *72 + kloc];
                ah[m][1] = *(const unsigned*)&Ah[(r+8)*72 + kloc];
                ah[m][2] = *(const unsigned*)&Ah[ r   *72 + kloc + 8];
                ah[m][3] = *(const unsigned*)&Ah[(r+8)*72 + kloc + 8];
                al[m][0] = *(const unsigned*)&Al[ r   *72 + kloc];
                al[m][1] = *(const unsigned*)&Al[(r+8)*72 + kloc];
                al[m][2] = *(const unsigned*)&Al[ r   *72 + kloc + 8];
                al[m][3] = *(const unsigned*)&Al[(r+8)*72 + kloc + 8];
            }
            #pragma unroll
            for (int t = 0; t < 4; t++) {
                const int nt = blockIdx.x*8 + wn*4 + t;
                const size_t bi = ((size_t)ksg*96 + nt)*32 + lane;
                const uint2 bh = WFh[bi];
                const uint2 bl = WFl[bi];
                #pragma unroll
                for (int m = 0; m < 2; m++) {
                    mma16816(acc[m][t], ah[m], bh.x, bh.y);
                    mma16816(acc[m][t], al[m], bh.x, bh.y);
                    mma16816(acc[m][t], ah[m], bl.x, bl.y);
                }
            }
        }
    }
    const float* bias = which ? bt_ : bh_;
    float* outb = which ? g_zo : g_zs;
    #pragma unroll
    for (int m = 0; m < 2; m++) {
        const int r = r0 + wm*32 + m*16 + (lane >> 2);
        #pragma unroll
        for (int t = 0; t < 4; t++) {
            const int n = blockIdx.x*64 + wn*32 + t*8 + (lane & 3)*2;
            outb[(size_t) r   *D + n  ] = tanhf(acc[m][t][0] + bias[n]);
            outb[(size_t) r   *D + n+1] = tanhf(acc[m][t][1] + bias[n+1]);
            outb[(size_t)(r+8)*D + n  ] = tanhf(acc[m][t][2] + bias[n]);
            outb[(size_t)(r+8)*D + n+1] = tanhf(acc[m][t][3] + bias[n+1]);
        }
    }
}

// ---- kernel 6a: convert W_bi into fragment-ready fp16 hi/lo layouts -------
__global__ void k_cvt(const float* __restrict__ Wbi) {
    const int s = blockIdx.x, g = blockIdx.y;
    __shared__ float sm[16][104];
    const int tid = threadIdx.x;  // 128
    for (int idx = tid; idx < 16*104; idx += 128) ((float*)sm)[idx] = 0.f;
    __syncthreads();
    for (int idx = tid; idx < 16*97; idx += 128) {
        const int kr = idx / 97, n = idx % 97;
        sm[kr][n] = Wbi[(size_t)(g*4096 + s*16 + kr)*NL + n];
    }
    __syncthreads();
    for (int o = tid; o < 13*32; o += 128) {
        const int t = o >> 5, lane = o & 31;
        const int n = t*8 + (lane >> 2), kk = (lane & 3)*2;
        float w00 = sm[kk][n],   w01 = sm[kk+1][n];
        float w08 = sm[kk+8][n], w09 = sm[kk+9][n];
        unsigned h0 = h2pack(w00, w01);
        unsigned h1 = h2pack(w08, w09);
        float2 f0 = h2unpack(h0), f1 = h2unpack(h1);
        unsigned l0 = h2pack(w00 - f0.x, w01 - f0.y);
        unsigned l1 = h2pack(w08 - f1.x, w09 - f1.y);
        const size_t oi = ((size_t)(g*256 + s)*13 + t)*32 + lane;
        g_Whi[oi] = make_uint2(h0, h1);
        g_Wlo[oi] = make_uint2(l0, l1);
    }
}

// ---- kernel 6b: bilinear logits via HMMA, 3-pass fp16 compensated ---------
#define ZS_STR 66
#define ZO_STR 72
__global__ __launch_bounds__(256, 2) void k_blmma() {
    const int g  = blockIdx.y;
    const int r0 = blockIdx.x * 128;
    extern __shared__ float sh[];
    float* zs_s = sh;
    float* zo_s = sh + 128*ZS_STR;
    const int tid = threadIdx.x, lane = tid & 31, wid = tid >> 5;
    const int wm = wid & 3, nh = wid >> 2;
    const int t0 = nh ? 7 : 0;

    for (int idx = tid; idx < 128*16; idx += 256) {
        const int row = idx >> 4, c4 = (idx & 15) * 4;
        float4 a = *(const float4*)&g_zs[(size_t)(r0+row)*D + g*BLKSZ + c4];
        zs_s[row*ZS_STR + c4+0] = a.x; zs_s[row*ZS_STR + c4+1] = a.y;
        zs_s[row*ZS_STR + c4+2] = a.z; zs_s[row*ZS_STR + c4+3] = a.w;
        float4 b = *(const float4*)&g_zo[(size_t)(r0+row)*D + g*BLKSZ + c4];
        zo_s[row*ZO_STR + c4+0] = b.x; zo_s[row*ZO_STR + c4+1] = b.y;
        zo_s[row*ZO_STR + c4+2] = b.z; zo_s[row*ZO_STR + c4+3] = b.w;
    }
    __syncthreads();

    float acc[2][7][4] = {};
    const int rl = wm*32 + (lane >> 2);
    const int k0 = (lane & 3)*2;
    const uint2* __restrict__ Wh = g_Whi + (size_t)g*256*13*32;
    const uint2* __restrict__ Wl = g_Wlo + (size_t)g*256*13*32;

    for (int s = 0; s < 256; s++) {
        const int i  = s >> 2;
        const int jb = ((s & 3) << 4) + k0;
        unsigned ah[2][4], al[2][4];
        #pragma unroll
        for (int m = 0; m < 2; m++) {
            const int r = rl + m*16;
            const float zs0 = zs_s[r*ZS_STR + i];
            const float zs1 = zs_s[(r+8)*ZS_STR + i];
            const float2 x0 = *(const float2*)&zo_s[r*ZO_STR + jb];
            const float2 x1 = *(const float2*)&zo_s[r*ZO_STR + jb + 8];
            const float2 y0 = *(const float2*)&zo_s[(r+8)*ZO_STR + jb];
            const float2 y1 = *(const float2*)&zo_s[(r+8)*ZO_STR + jb + 8];
            const float v00 = zs0*x0.x, v01 = zs0*x0.y, v02 = zs0*x1.x, v03 = zs0*x1.y;
            const float v10 = zs1*y0.x, v11 = zs1*y0.y, v12 = zs1*y1.x, v13 = zs1*y1.y;
            ah[m][0] = h2pack(v00, v01); ah[m][1] = h2pack(v10, v11);
            ah[m][2] = h2pack(v02, v03); ah[m][3] = h2pack(v12, v13);
            float2 f;
            f = h2unpack(ah[m][0]); al[m][0] = h2pack(v00 - f.x, v01 - f.y);
            f = h2unpack(ah[m][1]); al[m][1] = h2pack(v10 - f.x, v11 - f.y);
            f = h2unpack(ah[m][2]); al[m][2] = h2pack(v02 - f.x, v03 - f.y);
            f = h2unpack(ah[m][3]); al[m][3] = h2pack(v12 - f.x, v13 - f.y);
        }
        #pragma unroll
        for (int t = 0; t < 7; t++) {
            if (t0 + t < 13) {
                const size_t bi = ((size_t)s*13 + t0 + t)*32 + lane;
                const uint2 bh = __ldg(&Wh[bi]);
                const uint2 bl = __ldg(&Wl[bi]);
                #pragma unroll
                for (int m = 0; m < 2; m++) {
                    mma16816(acc[m][t], ah[m], bh.x, bh.y);
                    mma16816(acc[m][t], al[m], bh.x, bh.y);
                    mma16816(acc[m][t], ah[m], bl.x, bl.y);
                }
            }
        }
    }

    #pragma unroll
    for (int m = 0; m < 2; m++) {
        const int r = r0 + rl + m*16;
        #pragma unroll
        for (int t = 0; t < 7; t++) {
            if (t0 + t < 13) {
                const int n = (t0 + t)*8 + (lane & 3)*2;
                float* o0 = g_part + ((size_t)g*ROWS + r)*NL;
                float* o1 = g_part + ((size_t)g*ROWS + r + 8)*NL;
                if (n < NL)     { o0[n]   = acc[m][t][0]; o1[n]   = acc[m][t][2]; }
                if (n + 1 < NL) { o0[n+1] = acc[m][t][1]; o1[n+1] = acc[m][t][3]; }
            }
        }
    }
}

// ---- kernel 7: reduce partials over g, add bias ---------------------------
__global__ void k_reduce(const float* __restrict__ b_bi, float* __restrict__ out) {
    const int idx = blockIdx.x * 256 + threadIdx.x;
    if (idx >= ROWS * NL) return;
    const int n = idx % NL;
    float s = b_bi[n];
    #pragma unroll
    for (int g = 0; g < GB; g++)
        s += g_part[(size_t)g * (ROWS*NL) + idx];
    out[idx] = s;
}

// ---------------------------------------------------------------------------
extern "C" void kernel_launch(void* const* d_in, const int* in_sizes, int n_in,
                              void* d_out, int out_size) {
    const float* seq    = (const float*)d_in[0];
    const float* att    = (const float*)d_in[1];
    const int*   mpos   = (const int*)d_in[2];
    const int*   hts    = (const int*)d_in[3];
    const float* W_head = (const float*)d_in[4];
    const float* b_head = (const float*)d_in[5];
    const float* W_tail = (const float*)d_in[6];
    const float* b_tail = (const float*)d_in[7];
    const float* W_bi   = (const float*)d_in[8];
    const float* b_bi   = (const float*)d_in[9];
    float* out = (float*)d_out;

    const int blm_smem = (128*ZS_STR + 128*ZO_STR) * 4;  // 70656 B
    const int cvt_smem = 16*772*4;                       // 49408 B
    cudaFuncSetAttribute(k_blmma, cudaFuncAttributeMaxDynamicSharedMemorySize, blm_smem);
    cudaFuncSetAttribute(k_cvtW, cudaFuncAttributeMaxDynamicSharedMemorySize, cvt_smem);
    cudaFuncSetAttribute(k_cvtseq, cudaFuncAttributeMaxDynamicSharedMemorySize, cvt_smem);

    dim3 gcv(256, GB);
    k_cvt<<<gcv, 128>>>(W_bi);
    dim3 gcw(96, 2);
    k_cvtW<<<gcw, 256, cvt_smem>>>(W_head, W_tail);
    dim3 gcs(64, 4);
    k_cvtseq<<<gcs, 256, cvt_smem>>>(seq);

    k_eemb<<<B*NE, 256>>>(seq, mpos);
    k_eatt<<<B*NE*H, 256>>>(att, mpos);
    k_htw<<<B*P, 256>>>(hts);

    dim3 grs(D/64, P/128, B);
    k_rs_mma<<<grs, 256>>>();

    dim3 gex(D/64, ROWS/128, 2);
    k_extract_mma<<<gex, 256>>>(b_head, b_tail, hts);

    dim3 glg(ROWS/128, GB);
    k_blmma<<<glg, 256, blm_smem>>>();

    k_reduce<<<(ROWS*NL + 255)/256, 256>>>(b_bi, out);
}

// round 5
// speedup vs baseline: 2.3670x; 1.0104x over previous
#include <cuda_runtime.h>
#include <cuda_fp16.h>
#include <math.h>
#include <stdint.h>

#define B 4
#define L 1024
#define D 768
#define H 12
#define NE 42
#define MM 4
#define P 512
#define BLKSZ 64
#define NL 97
#define GB 12          // D / BLKSZ
#define KD 1536        // 2*D
#define ROWS (B*P)     // 2048

// ---------------- scratch (device globals; no allocation allowed) ----------
__device__ __align__(16) float g_eemb[B*NE*D];
__device__ __align__(16) __half g_ehi[B*NE*D];
__device__ __align__(16) __half g_elo[B*NE*D];
__device__ __align__(16) float g_eatt[B*NE*H*L];
__device__ __align__(16) __half g_hthi[(size_t)ROWS*L];
__device__ __align__(16) __half g_htlo[(size_t)ROWS*L];
__device__ __align__(16) __half g_rshi[(size_t)ROWS*D];
__device__ __align__(16) __half g_rslo[(size_t)ROWS*D];
__device__ __align__(16) float g_zs[(size_t)ROWS*D];
__device__ __align__(16) float g_zo[(size_t)ROWS*D];
__device__ __align__(16) float g_part[(size_t)GB*ROWS*NL];
// fragment-ready W_bi (hi fp16): [g][kstep s:256][ntile t:13][lane:32]
__device__ __align__(16) uint2 g_Whi[(size_t)GB*256*13*32];
// fragment-ready extractor weights: [which:2][kstep:96][ntile:96][lane:32]
__device__ __align__(16) uint2 g_WxFhi[(size_t)2*96*96*32];
__device__ __align__(16) uint2 g_WxFlo[(size_t)2*96*96*32];
// fragment-ready seq: [b:4][kstep:64][ntile:96][lane:32]
__device__ __align__(16) uint2 g_seqFhi[(size_t)4*64*96*32];
__device__ __align__(16) uint2 g_seqFlo[(size_t)4*64*96*32];

// ---- half helpers ---------------------------------------------------------
__device__ __forceinline__ unsigned h2pack(float a, float b) {
    __half2 h = __float22half2_rn(make_float2(a, b));
    return reinterpret_cast<unsigned&>(h);
}
__device__ __forceinline__ float2 h2unpack(unsigned u) {
    __half2 h = reinterpret_cast<__half2&>(u);
    return __half22float2(h);
}

// ---- mma.sync m16n8k16 fp16 -> fp32 ---------------------------------------
__device__ __forceinline__ void mma16816(float* d, const unsigned* a, unsigned b0, unsigned b1) {
    asm volatile(
        "mma.sync.aligned.m16n8k16.row.col.f32.f16.f16.f32 "
        "{%0,%1,%2,%3}, {%4,%5,%6,%7}, {%8,%9}, {%0,%1,%2,%3};"
        : "+f"(d[0]), "+f"(d[1]), "+f"(d[2]), "+f"(d[3])
        : "r"(a[0]), "r"(a[1]), "r"(a[2]), "r"(a[3]), "r"(b0), "r"(b1));
}

// ---------------- kernel 1: entity embeddings + hi/lo split ----------------
__global__ void k_eemb(const float* __restrict__ seq, const int* __restrict__ mpos) {
    const int be = blockIdx.x;
    const int b = be / NE;
    __shared__ int pos[MM];
    if (threadIdx.x < MM) pos[threadIdx.x] = mpos[be*MM + threadIdx.x] + 1;
    __syncthreads();
    const float* sb = seq + (size_t)b * L * D;
    for (int d = threadIdx.x; d < D; d += blockDim.x) {
        float v0 = sb[(size_t)pos[0]*D + d];
        float v1 = sb[(size_t)pos[1]*D + d];
        float v2 = sb[(size_t)pos[2]*D + d];
        float v3 = sb[(size_t)pos[3]*D + d];
        float mx = fmaxf(fmaxf(v0, v1), fmaxf(v2, v3));
        float s = expf(v0-mx) + expf(v1-mx) + expf(v2-mx) + expf(v3-mx);
        float v = mx + logf(s);
        g_eemb[(size_t)be*D + d] = v;
        __half hv = __float2half_rn(v);
        g_ehi[(size_t)be*D + d] = hv;
        g_elo[(size_t)be*D + d] = __float2half_rn(v - __half2float(hv));
    }
}

// ---------------- kernel 2: entity attentions ------------------------------
__global__ void k_eatt(const float* __restrict__ att, const int* __restrict__ mpos) {
    const int idx = blockIdx.x;
    const int h  = idx % H;
    const int be = idx / H;
    const int b  = be / NE;
    __shared__ int pos[MM];
    if (threadIdx.x < MM) pos[threadIdx.x] = mpos[be*MM + threadIdx.x] + 1;
    __syncthreads();
    const float* ab = att + (size_t)(b*H + h) * L * L;
    float* outp = g_eatt + ((size_t)be*H + h) * L;
    for (int l = threadIdx.x; l < L; l += blockDim.x) {
        float s = ab[(size_t)pos[0]*L + l] + ab[(size_t)pos[1]*L + l]
                + ab[(size_t)pos[2]*L + l] + ab[(size_t)pos[3]*L + l];
        outp[l] = 0.25f * s;
    }
}

// ---------------- kernel 3: per-pair channel weights -> hi/lo halves -------
__global__ void k_htw(const int* __restrict__ hts) {
    const int bp = blockIdx.x;
    const int b  = bp / P;
    const int hi = hts[bp*2 + 0];
    const int ti = hts[bp*2 + 1];
    const float* eh = g_eatt + (size_t)(b*NE + hi) * H * L;
    const float* et = g_eatt + (size_t)(b*NE + ti) * H * L;
    const int tid = threadIdx.x;
    float w[4];
    float lsum = 0.f;
    #pragma unroll
    for (int r = 0; r < 4; r++) {
        const int l = tid + r*256;
        float acc = 0.f;
        #pragma unroll
        for (int hh = 0; hh < H; hh++)
            acc += eh[hh*L + l] * et[hh*L + l];
        w[r] = acc;
        lsum += acc;
    }
    __shared__ float red[256];
    red[tid] = lsum;
    __syncthreads();
    for (int s = 128; s > 0; s >>= 1) {
        if (tid < s) red[tid] += red[tid + s];
        __syncthreads();
    }
    const float total = red[0];
    const float scale = 1.f / ((float)H * (total / (float)H + 1e-5f));
    #pragma unroll
    for (int r = 0; r < 4; r++) {
        const int l = tid + r*256;
        float v = w[r] * scale;
        __half hv = __float2half_rn(v);
        g_hthi[(size_t)bp*L + l] = hv;
        g_htlo[(size_t)bp*L + l] = __float2half_rn(v - __half2float(hv));
    }
}

// ---- conversion: a [16 x 768] fp32 slab -> fragment-ready hi/lo -----------
__device__ __forceinline__ void cvt_slab(const float* __restrict__ src,
                                         uint2* __restrict__ dhi, uint2* __restrict__ dlo) {
    extern __shared__ float smf[];             // [16][772]
    const int tid = threadIdx.x;               // 256
    for (int idx = tid; idx < 16*768; idx += 256) {
        const int kr = idx / 768, n = idx - kr*768;
        smf[kr*772 + n] = src[(size_t)kr*768 + n];
    }
    __syncthreads();
    for (int o = tid; o < 96*32; o += 256) {
        const int nt = o >> 5, lane = o & 31;
        const int n = nt*8 + (lane >> 2), k0 = (lane & 3)*2;
        float w00 = smf[(k0  )*772 + n], w01 = smf[(k0+1)*772 + n];
        float w08 = smf[(k0+8)*772 + n], w09 = smf[(k0+9)*772 + n];
        unsigned h0 = h2pack(w00, w01), h1 = h2pack(w08, w09);
        float2 f0 = h2unpack(h0), f1 = h2unpack(h1);
        unsigned l0 = h2pack(w00 - f0.x, w01 - f0.y);
        unsigned l1 = h2pack(w08 - f1.x, w09 - f1.y);
        dhi[(size_t)nt*32 + lane] = make_uint2(h0, h1);
        dlo[(size_t)nt*32 + lane] = make_uint2(l0, l1);
    }
}

__global__ void k_cvtW(const float* __restrict__ Wh, const float* __restrict__ Wt) {
    const int ks = blockIdx.x, which = blockIdx.y;
    const float* src = (which ? Wt : Wh) + (size_t)ks*16*768;
    const size_t o = ((size_t)which*96 + ks)*96*32;
    cvt_slab(src, g_WxFhi + o, g_WxFlo + o);
}

__global__ void k_cvtseq(const float* __restrict__ seq) {
    const int ks = blockIdx.x, b = blockIdx.y;
    const float* src = seq + (size_t)b*L*D + (size_t)ks*16*768;
    const size_t o = ((size_t)b*64 + ks)*96*32;
    cvt_slab(src, g_seqFhi + o, g_seqFlo + o);
}

// ---- kernel 4: rs = htw @ seq via HMMA (3-pass, smem-staged B) ------------
// grid (12 ntile-blocks, 4 row-blocks, 4 batches), 256 threads
// dyn smem: Ah[128*72]h Al[128*72]h Bh[1024]uint2 Bl[1024]uint2 = 53248 B
__global__ __launch_bounds__(256, 2) void k_rs_mma() {
    const int b  = blockIdx.z;
    const int p0 = blockIdx.y * 128;
    extern __shared__ char dsm[];
    __half* Ah = (__half*)dsm;
    __half* Al = (__half*)(dsm + 128*72*2);
    uint2*  Bhs = (uint2*)(dsm + 128*72*4);
    uint2*  Bls = Bhs + 1024;
    const int tid = threadIdx.x, lane = tid & 31, wid = tid >> 5;
    const int wm = wid & 3, wn = wid >> 2;
    const size_t rowbase = (size_t)(b*P + p0);
    float acc[2][4][4] = {};
    const int rb = wm*32 + (lane >> 2);
    for (int c0 = 0; c0 < L; c0 += 64) {
        __syncthreads();
        for (int idx = tid; idx < 4096; idx += 256) {
            const int row = idx >> 5, c2 = (idx & 31)*2;
            const size_t o = (rowbase + row)*L + c0 + c2;
            *(unsigned*)&Ah[row*72 + c2] = *(const unsigned*)&g_hthi[o];
            *(unsigned*)&Al[row*72 + c2] = *(const unsigned*)&g_htlo[o];
        }
        for (int idx = tid; idx < 1024; idx += 256) {
            const int kl = idx >> 8, rest = idx & 255;
            const int nt = blockIdx.x*8 + (rest >> 5), l2 = rest & 31;
            const size_t bi = (((size_t)b*64 + (c0 >> 4) + kl)*96 + nt)*32 + l2;
            Bhs[idx] = g_seqFhi[bi];
            Bls[idx] = g_seqFlo[bi];
        }
        __syncthreads();
        #pragma unroll
        for (int kk = 0; kk < 4; kk++) {
            const int kloc = kk*16 + (lane & 3)*2;
            unsigned ah[2][4], al[2][4];
            #pragma unroll
            for (int m = 0; m < 2; m++) {
                const int r = rb + m*16;
                ah[m][0] = *(const unsigned*)&Ah[ r   *72 + kloc];
                ah[m][1] = *(const unsigned*)&Ah[(r+8)*72 + kloc];
                ah[m][2] = *(const unsigned*)&Ah[ r   *72 + kloc + 8];
                ah[m][3] = *(const unsigned*)&Ah[(r+8)*72 + kloc + 8];
                al[m][0] = *(const unsigned*)&Al[ r   *72 + kloc];
                al[m][1] = *(const unsigned*)&Al[(r+8)*72 + kloc];
                al[m][2] = *(const unsigned*)&Al[ r   *72 + kloc + 8];
                al[m][3] = *(const unsigned*)&Al[(r+8)*72 + kloc + 8];
            }
            #pragma unroll
            for (int t = 0; t < 4; t++) {
                const int bi = (kk*8 + wn*4 + t)*32 + lane;
                const uint2 bh = Bhs[bi];
                const uint2 bl = Bls[bi];
                #pragma unroll
                for (int m = 0; m < 2; m++) {
                    mma16816(acc[m][t], ah[m], bh.x, bh.y);
                    mma16816(acc[m][t], al[m], bh.x, bh.y);
                    mma16816(acc[m][t], ah[m], bl.x, bl.y);
                }
            }
        }
    }
    #pragma unroll
    for (int m = 0; m < 2; m++) {
        const size_t r = rowbase + wm*32 + m*16 + (lane >> 2);
        #pragma unroll
        for (int t = 0; t < 4; t++) {
            const int n = blockIdx.x*64 + wn*32 + t*8 + (lane & 3)*2;
            #pragma unroll
            for (int h = 0; h < 2; h++) {
                const size_t rr = r + h*8;
                const float v0 = acc[m][t][h*2+0], v1 = acc[m][t][h*2+1];
                __half h0 = __float2half_rn(v0), h1 = __float2half_rn(v1);
                *(unsigned*)&g_rshi[rr*D + n] =
                    (unsigned)__half_as_ushort(h0) | ((unsigned)__half_as_ushort(h1) << 16);
                __half l0 = __float2half_rn(v0 - __half2float(h0));
                __half l1 = __float2half_rn(v1 - __half2float(h1));
                *(unsigned*)&g_rslo[rr*D + n] =
                    (unsigned)__half_as_ushort(l0) | ((unsigned)__half_as_ushort(l1) << 16);
            }
        }
    }
}

// ---- kernel 5: extractors via HMMA (3-pass, smem-staged B) ----------------
// grid (12 ntile-blocks, 16 row-blocks, 2 which), 256 threads
// dyn smem: Ah/Al + Bh/Bl (53248) + ebase 512 = 53760 B
__global__ __launch_bounds__(256, 2) void k_extract_mma(
        const float* __restrict__ bh_, const float* __restrict__ bt_,
        const int* __restrict__ hts) {
    const int which = blockIdx.z;
    const int r0 = blockIdx.y * 128;
    extern __shared__ char dsm[];
    __half* Ah = (__half*)dsm;
    __half* Al = (__half*)(dsm + 128*72*2);
    uint2*  Bhs = (uint2*)(dsm + 128*72*4);
    uint2*  Bls = Bhs + 1024;
    int*    ebase = (int*)(Bls + 1024);
    const int tid = threadIdx.x, lane = tid & 31, wid = tid >> 5;
    const int wm = wid & 3, wn = wid >> 2;
    if (tid < 128) {
        const int row = r0 + tid;
        ebase[tid] = ((row / P)*NE + hts[row*2 + which]) * D;
    }
    const uint2* __restrict__ WFh = g_WxFhi + (size_t)which*96*96*32;
    const uint2* __restrict__ WFl = g_WxFlo + (size_t)which*96*96*32;
    float acc[2][4][4] = {};
    const int rb = wm*32 + (lane >> 2);
    for (int c0 = 0; c0 < KD; c0 += 64) {
        __syncthreads();
        const bool fromE = (c0 < D);
        for (int idx = tid; idx < 4096; idx += 256) {
            const int row = idx >> 5, c2 = (idx & 31)*2;
            size_t o;
            if (fromE) o = (size_t)ebase[row] + c0 + c2;
            else       o = (size_t)(r0 + row)*D + (c0 - D) + c2;
            const __half* sh = fromE ? g_ehi : g_rshi;
            const __half* sl = fromE ? g_elo : g_rslo;
            *(unsigned*)&Ah[row*72 + c2] = *(const unsigned*)&sh[o];
            *(unsigned*)&Al[row*72 + c2] = *(const unsigned*)&sl[o];
        }
        for (int idx = tid; idx < 1024; idx += 256) {
            const int kl = idx >> 8, rest = idx & 255;
            const int nt = blockIdx.x*8 + (rest >> 5), l2 = rest & 31;
            const size_t bi = ((size_t)((c0 >> 4) + kl)*96 + nt)*32 + l2;
            Bhs[idx] = WFh[bi];
            Bls[idx] = WFl[bi];
        }
        __syncthreads();
        #pragma unroll
        for (int kk = 0; kk < 4; kk++) {
            const int kloc = kk*16 + (lane & 3)*2;
            unsigned ah[2][4], al[2][4];
            #pragma unroll
            for (int m = 0; m < 2; m++) {
                const int r = rb + m*16;
                ah[m][0] = *(const unsigned*)&Ah[ r   *72 + kloc];
                ah[m][1] = *(const unsigned*)&Ah[(r+8)*72 + kloc];
                ah[m][2] = *(const unsigned*)&Ah[ r   *72 + kloc + 8];
                ah[m][3] = *(const unsigned*)&Ah[(r+8)*72 + kloc + 8];
                al[m][0] = *(const unsigned*)&Al[ r   *72 + kloc];
                al[m][1] = *(const unsigned*)&Al[(r+8)*72 + kloc];
                al[m][2] = *(const unsigned*)&Al[ r   *72 + kloc + 8];
                al[m][3] = *(const unsigned*)&Al[(r+8)*72 + kloc + 8];
            }
            #pragma unroll
            for (int t = 0; t < 4; t++) {
                const int bi = (kk*8 + wn*4 + t)*32 + lane;
                const uint2 bh = Bhs[bi];
                const uint2 bl = Bls[bi];
                #pragma unroll
                for (int m = 0; m < 2; m++) {
                    mma16816(acc[m][t], ah[m], bh.x, bh.y);
                    mma16816(acc[m][t], al[m], bh.x, bh.y);
                    mma16816(acc[m][t], ah[m], bl.x, bl.y);
                }
            }
        }
    }
    const float* bias = which ? bt_ : bh_;
    float* outb = which ? g_zo : g_zs;
    #pragma unroll
    for (int m = 0; m < 2; m++) {
        const int r = r0 + wm*32 + m*16 + (lane >> 2);
        #pragma unroll
        for (int t = 0; t < 4; t++) {
            const int n = blockIdx.x*64 + wn*32 + t*8 + (lane & 3)*2;
            outb[(size_t) r   *D + n  ] = tanhf(acc[m][t][0] + bias[n]);
            outb[(size_t) r   *D + n+1] = tanhf(acc[m][t][1] + bias[n+1]);
            outb[(size_t)(r+8)*D + n  ] = tanhf(acc[m][t][2] + bias[n]);
            outb[(size_t)(r+8)*D + n+1] = tanhf(acc[m][t][3] + bias[n+1]);
        }
    }
}

// ---- kernel 6a: convert W_bi into fragment-ready fp16 hi layout -----------
__global__ void k_cvt(const float* __restrict__ Wbi) {
    const int s = blockIdx.x, g = blockIdx.y;
    __shared__ float sm[16][104];
    const int tid = threadIdx.x;  // 128
    for (int idx = tid; idx < 16*104; idx += 128) ((float*)sm)[idx] = 0.f;
    __syncthreads();
    for (int idx = tid; idx < 16*97; idx += 128) {
        const int kr = idx / 97, n = idx % 97;
        sm[kr][n] = Wbi[(size_t)(g*4096 + s*16 + kr)*NL + n];
    }
    __syncthreads();
    for (int o = tid; o < 13*32; o += 128) {
        const int t = o >> 5, lane = o & 31;
        const int n = t*8 + (lane >> 2), kk = (lane & 3)*2;
        unsigned h0 = h2pack(sm[kk][n],   sm[kk+1][n]);
        unsigned h1 = h2pack(sm[kk+8][n], sm[kk+9][n]);
        g_Whi[((size_t)(g*256 + s)*13 + t)*32 + lane] = make_uint2(h0, h1);
    }
}

// ---- kernel 6b: bilinear logits via HMMA, 2-pass (A compensated, W fp16) --
#define ZS_STR 66
#define ZO_STR 72
// dyn smem: zs_s f32 128*66 (33792) + zo_s f32 128*72 (36864) + Wst 1664*8 (13312) = 83968
__global__ __launch_bounds__(256, 2) void k_blmma() {
    const int g  = blockIdx.y;
    const int r0 = blockIdx.x * 128;
    extern __shared__ float sh[];
    float* zs_s = sh;
    float* zo_s = sh + 128*ZS_STR;
    uint2* Wst  = (uint2*)(sh + 128*ZS_STR + 128*ZO_STR);
    const int tid = threadIdx.x, lane = tid & 31, wid = tid >> 5;
    const int wm = wid & 3, nh = wid >> 2;
    const int t0 = nh ? 7 : 0;

    for (int idx = tid; idx < 128*16; idx += 256) {
        const int row = idx >> 4, c4 = (idx & 15) * 4;
        float4 a = *(const float4*)&g_zs[(size_t)(r0+row)*D + g*BLKSZ + c4];
        zs_s[row*ZS_STR + c4+0] = a.x; zs_s[row*ZS_STR + c4+1] = a.y;
        zs_s[row*ZS_STR + c4+2] = a.z; zs_s[row*ZS_STR + c4+3] = a.w;
        float4 b = *(const float4*)&g_zo[(size_t)(r0+row)*D + g*BLKSZ + c4];
        zo_s[row*ZO_STR + c4+0] = b.x; zo_s[row*ZO_STR + c4+1] = b.y;
        zo_s[row*ZO_STR + c4+2] = b.z; zo_s[row*ZO_STR + c4+3] = b.w;
    }

    float acc[2][7][4] = {};
    const int rl = wm*32 + (lane >> 2);
    const int k0 = (lane & 3)*2;
    const uint2* __restrict__ Wh = g_Whi + (size_t)g*256*13*32;

    for (int sc = 0; sc < 256; sc += 4) {
        __syncthreads();                 // protects Wst reuse; first iter covers zs/zo
        for (int idx = tid; idx < 4*13*32; idx += 256)
            Wst[idx] = Wh[(size_t)sc*13*32 + idx];
        __syncthreads();
        #pragma unroll
        for (int sl = 0; sl < 4; sl++) {
            const int s = sc + sl;
            const int i  = s >> 2;
            const int jb = ((s & 3) << 4) + k0;
            unsigned ah[2][4], al[2][4];
            #pragma unroll
            for (int m = 0; m < 2; m++) {
                const int r = rl + m*16;
                const float zs0 = zs_s[r*ZS_STR + i];
                const float zs1 = zs_s[(r+8)*ZS_STR + i];
                const float2 x0 = *(const float2*)&zo_s[r*ZO_STR + jb];
                const float2 x1 = *(const float2*)&zo_s[r*ZO_STR + jb + 8];
                const float2 y0 = *(const float2*)&zo_s[(r+8)*ZO_STR + jb];
                const float2 y1 = *(const float2*)&zo_s[(r+8)*ZO_STR + jb + 8];
                const float v00 = zs0*x0.x, v01 = zs0*x0.y, v02 = zs0*x1.x, v03 = zs0*x1.y;
                const float v10 = zs1*y0.x, v11 = zs1*y0.y, v12 = zs1*y1.x, v13 = zs1*y1.y;
                ah[m][0] = h2pack(v00, v01); ah[m][1] = h2pack(v10, v11);
                ah[m][2] = h2pack(v02, v03); ah[m][3] = h2pack(v12, v13);
                float2 f;
                f = h2unpack(ah[m][0]); al[m][0] = h2pack(v00 - f.x, v01 - f.y);
                f = h2unpack(ah[m][1]); al[m][1] = h2pack(v10 - f.x, v11 - f.y);
                f = h2unpack(ah[m][2]); al[m][2] = h2pack(v02 - f.x, v03 - f.y);
                f = h2unpack(ah[m][3]); al[m][3] = h2pack(v12 - f.x, v13 - f.y);
            }
            #pragma unroll
            for (int t = 0; t < 7; t++) {
                if (t0 + t < 13) {
                    const uint2 bh = Wst[(sl*13 + t0 + t)*32 + lane];
                    #pragma unroll
                    for (int m = 0; m < 2; m++) {
                        mma16816(acc[m][t], ah[m], bh.x, bh.y);
                        mma16816(acc[m][t], al[m], bh.x, bh.y);
                    }
                }
            }
        }
    }

    #pragma unroll
    for (int m = 0; m < 2; m++) {
        const int r = r0 + rl + m*16;
        #pragma unroll
        for (int t = 0; t < 7; t++) {
            if (t0 + t < 13) {
                const int n = (t0 + t)*8 + (lane & 3)*2;
                float* o0 = g_part + ((size_t)g*ROWS + r)*NL;
                float* o1 = g_part + ((size_t)g*ROWS + r + 8)*NL;
                if (n < NL)     { o0[n]   = acc[m][t][0]; o1[n]   = acc[m][t][2]; }
                if (n + 1 < NL) { o0[n+1] = acc[m][t][1]; o1[n+1] = acc[m][t][3]; }
            }
        }
    }
}

// ---- kernel 7: reduce partials over g, add bias ---------------------------
__global__ void k_reduce(const float* __restrict__ b_bi, float* __restrict__ out) {
    const int idx = blockIdx.x * 256 + threadIdx.x;
    if (idx >= ROWS * NL) return;
    const int n = idx % NL;
    float s = b_bi[n];
    #pragma unroll
    for (int g = 0; g < GB; g++)
        s += g_part[(size_t)g * (ROWS*NL) + idx];
    out[idx] = s;
}

// ---------------------------------------------------------------------------
extern "C" void kernel_launch(void* const* d_in, const int* in_sizes, int n_in,
                              void* d_out, int out_size) {
    const float* seq    = (const float*)d_in[0];
    const float* att    = (const float*)d_in[1];
    const int*   mpos   = (const int*)d_in[2];
    const int*   hts    = (const int*)d_in[3];
    const float* W_head = (const float*)d_in[4];
    const float* b_head = (const float*)d_in[5];
    const float* W_tail = (const float*)d_in[6];
    const float* b_tail = (const float*)d_in[7];
    const float* W_bi   = (const float*)d_in[8];
    const float* b_bi   = (const float*)d_in[9];
    float* out = (float*)d_out;

    const int blm_smem = (128*ZS_STR + 128*ZO_STR)*4 + 4*13*32*8;  // 83968
    const int cvt_smem = 16*772*4;                                  // 49408
    const int rs_smem  = 128*72*4 + 2048*8;                         // 53248
    const int ex_smem  = rs_smem + 512;                             // 53760
    cudaFuncSetAttribute(k_blmma, cudaFuncAttributeMaxDynamicSharedMemorySize, blm_smem);
    cudaFuncSetAttribute(k_cvtW, cudaFuncAttributeMaxDynamicSharedMemorySize, cvt_smem);
    cudaFuncSetAttribute(k_cvtseq, cudaFuncAttributeMaxDynamicSharedMemorySize, cvt_smem);
    cudaFuncSetAttribute(k_rs_mma, cudaFuncAttributeMaxDynamicSharedMemorySize, rs_smem);
    cudaFuncSetAttribute(k_extract_mma, cudaFuncAttributeMaxDynamicSharedMemorySize, ex_smem);

    dim3 gcv(256, GB);
    k_cvt<<<gcv, 128>>>(W_bi);
    dim3 gcw(96, 2);
    k_cvtW<<<gcw, 256, cvt_smem>>>(W_head, W_tail);
    dim3 gcs(64, 4);
    k_cvtseq<<<gcs, 256, cvt_smem>>>(seq);

    k_eemb<<<B*NE, 256>>>(seq, mpos);
    k_eatt<<<B*NE*H, 256>>>(att, mpos);
    k_htw<<<B*P, 256>>>(hts);

    dim3 grs(D/64, P/128, B);
    k_rs_mma<<<grs, 256, rs_smem>>>();

    dim3 gex(D/64, ROWS/128, 2);
    k_extract_mma<<<gex, 256, ex_smem>>>(b_head, b_tail, hts);

    dim3 glg(ROWS/128, GB);
    k_blmma<<<glg, 256, blm_smem>>>();

    k_reduce<<<(ROWS*NL + 255)/256, 256>>>(b_bi, out);
}

// round 6
// speedup vs baseline: 3.2966x; 1.3927x over previous
#include <cuda_runtime.h>
#include <cuda_fp16.h>
#include <math.h>
#include <stdint.h>

#define B 4
#define L 1024
#define D 768
#define H 12
#define NE 42
#define MM 4
#define P 512
#define BLKSZ 64
#define NL 97
#define GB 12          // D / BLKSZ
#define KSPL 2         // K-split of bilinear
#define NSL (GB*KSPL)  // 24 partial slices
#define KD 1536        // 2*D
#define ROWS (B*P)     // 2048

// ---------------- scratch (device globals; no allocation allowed) ----------
__device__ __align__(16) float g_eemb[B*NE*D];
__device__ __align__(16) __half g_ehi[B*NE*D];
__device__ __align__(16) __half g_elo[B*NE*D];
__device__ __align__(16) float g_eatt[B*NE*H*L];
__device__ __align__(16) __half g_hthi[(size_t)ROWS*L];
__device__ __align__(16) __half g_htlo[(size_t)ROWS*L];
__device__ __align__(16) __half g_rshi[(size_t)ROWS*D];
__device__ __align__(16) __half g_rslo[(size_t)ROWS*D];
__device__ __align__(16) float g_zs[(size_t)ROWS*D];
__device__ __align__(16) float g_zo[(size_t)ROWS*D];
__device__ __align__(16) float g_part[(size_t)NSL*ROWS*NL];
// fragment-ready W_bi (hi fp16): [g][kstep s:256][ntile t:13][lane:32]
__device__ __align__(16) uint2 g_Whi[(size_t)GB*256*13*32];
// fragment-ready extractor weights: [which:2][kstep:96][ntile:96][lane:32]
__device__ __align__(16) uint2 g_WxFhi[(size_t)2*96*96*32];
__device__ __align__(16) uint2 g_WxFlo[(size_t)2*96*96*32];
// fragment-ready seq: [b:4][kstep:64][ntile:96][lane:32]
__device__ __align__(16) uint2 g_seqFhi[(size_t)4*64*96*32];
__device__ __align__(16) uint2 g_seqFlo[(size_t)4*64*96*32];

// ---- half helpers ---------------------------------------------------------
__device__ __forceinline__ unsigned h2pack(float a, float b) {
    __half2 h = __float22half2_rn(make_float2(a, b));
    return reinterpret_cast<unsigned&>(h);
}
__device__ __forceinline__ float2 h2unpack(unsigned u) {
    __half2 h = reinterpret_cast<__half2&>(u);
    return __half22float2(h);
}

// ---- mma.sync m16n8k16 fp16 -> fp32 ---------------------------------------
__device__ __forceinline__ void mma16816(float* d, const unsigned* a, unsigned b0, unsigned b1) {
    asm volatile(
        "mma.sync.aligned.m16n8k16.row.col.f32.f16.f16.f32 "
        "{%0,%1,%2,%3}, {%4,%5,%6,%7}, {%8,%9}, {%0,%1,%2,%3};"
        : "+f"(d[0]), "+f"(d[1]), "+f"(d[2]), "+f"(d[3])
        : "r"(a[0]), "r"(a[1]), "r"(a[2]), "r"(a[3]), "r"(b0), "r"(b1));
}

// ---------------- kernel: entity embeddings + hi/lo split ------------------
__global__ void k_eemb(const float* __restrict__ seq, const int* __restrict__ mpos) {
    const int be = blockIdx.x;
    const int b = be / NE;
    __shared__ int pos[MM];
    if (threadIdx.x < MM) pos[threadIdx.x] = mpos[be*MM + threadIdx.x] + 1;
    __syncthreads();
    const float* sb = seq + (size_t)b * L * D;
    for (int d = threadIdx.x; d < D; d += blockDim.x) {
        float v0 = sb[(size_t)pos[0]*D + d];
        float v1 = sb[(size_t)pos[1]*D + d];
        float v2 = sb[(size_t)pos[2]*D + d];
        float v3 = sb[(size_t)pos[3]*D + d];
        float mx = fmaxf(fmaxf(v0, v1), fmaxf(v2, v3));
        float s = expf(v0-mx) + expf(v1-mx) + expf(v2-mx) + expf(v3-mx);
        float v = mx + logf(s);
        g_eemb[(size_t)be*D + d] = v;
        __half hv = __float2half_rn(v);
        g_ehi[(size_t)be*D + d] = hv;
        g_elo[(size_t)be*D + d] = __float2half_rn(v - __half2float(hv));
    }
}

// ---------------- kernel: entity attentions --------------------------------
__global__ void k_eatt(const float* __restrict__ att, const int* __restrict__ mpos) {
    const int idx = blockIdx.x;
    const int h  = idx % H;
    const int be = idx / H;
    const int b  = be / NE;
    __shared__ int pos[MM];
    if (threadIdx.x < MM) pos[threadIdx.x] = mpos[be*MM + threadIdx.x] + 1;
    __syncthreads();
    const float* ab = att + (size_t)(b*H + h) * L * L;
    float* outp = g_eatt + ((size_t)be*H + h) * L;
    for (int l = threadIdx.x; l < L; l += blockDim.x) {
        float s = ab[(size_t)pos[0]*L + l] + ab[(size_t)pos[1]*L + l]
                + ab[(size_t)pos[2]*L + l] + ab[(size_t)pos[3]*L + l];
        outp[l] = 0.25f * s;
    }
}

// ---------------- kernel: per-pair channel weights -> hi/lo halves ---------
__global__ void k_htw(const int* __restrict__ hts) {
    const int bp = blockIdx.x;
    const int b  = bp / P;
    const int hi = hts[bp*2 + 0];
    const int ti = hts[bp*2 + 1];
    const float* eh = g_eatt + (size_t)(b*NE + hi) * H * L;
    const float* et = g_eatt + (size_t)(b*NE + ti) * H * L;
    const int tid = threadIdx.x;
    float w[4];
    float lsum = 0.f;
    #pragma unroll
    for (int r = 0; r < 4; r++) {
        const int l = tid + r*256;
        float acc = 0.f;
        #pragma unroll
        for (int hh = 0; hh < H; hh++)
            acc += eh[hh*L + l] * et[hh*L + l];
        w[r] = acc;
        lsum += acc;
    }
    __shared__ float red[256];
    red[tid] = lsum;
    __syncthreads();
    for (int s = 128; s > 0; s >>= 1) {
        if (tid < s) red[tid] += red[tid + s];
        __syncthreads();
    }
    const float total = red[0];
    const float scale = 1.f / ((float)H * (total / (float)H + 1e-5f));
    #pragma unroll
    for (int r = 0; r < 4; r++) {
        const int l = tid + r*256;
        float v = w[r] * scale;
        __half hv = __float2half_rn(v);
        g_hthi[(size_t)bp*L + l] = hv;
        g_htlo[(size_t)bp*L + l] = __float2half_rn(v - __half2float(hv));
    }
}

// ---- conversion: a [16 x 768] fp32 slab -> fragment-ready hi/lo -----------
__device__ __forceinline__ void cvt_slab(const float* __restrict__ src,
                                         uint2* __restrict__ dhi, uint2* __restrict__ dlo) {
    extern __shared__ float smf[];             // [16][772]
    const int tid = threadIdx.x;               // 256
    for (int idx = tid; idx < 16*768; idx += 256) {
        const int kr = idx / 768, n = idx - kr*768;
        smf[kr*772 + n] = src[(size_t)kr*768 + n];
    }
    __syncthreads();
    for (int o = tid; o < 96*32; o += 256) {
        const int nt = o >> 5, lane = o & 31;
        const int n = nt*8 + (lane >> 2), k0 = (lane & 3)*2;
        float w00 = smf[(k0  )*772 + n], w01 = smf[(k0+1)*772 + n];
        float w08 = smf[(k0+8)*772 + n], w09 = smf[(k0+9)*772 + n];
        unsigned h0 = h2pack(w00, w01), h1 = h2pack(w08, w09);
        float2 f0 = h2unpack(h0), f1 = h2unpack(h1);
        unsigned l0 = h2pack(w00 - f0.x, w01 - f0.y);
        unsigned l1 = h2pack(w08 - f1.x, w09 - f1.y);
        dhi[(size_t)nt*32 + lane] = make_uint2(h0, h1);
        dlo[(size_t)nt*32 + lane] = make_uint2(l0, l1);
    }
}

__global__ void k_cvtW(const float* __restrict__ Wh, const float* __restrict__ Wt) {
    const int ks = blockIdx.x, which = blockIdx.y;
    const float* src = (which ? Wt : Wh) + (size_t)ks*16*768;
    const size_t o = ((size_t)which*96 + ks)*96*32;
    cvt_slab(src, g_WxFhi + o, g_WxFlo + o);
}

__global__ void k_cvtseq(const float* __restrict__ seq) {
    const int ks = blockIdx.x, b = blockIdx.y;
    const float* src = seq + (size_t)b*L*D + (size_t)ks*16*768;
    const size_t o = ((size_t)b*64 + ks)*96*32;
    cvt_slab(src, g_seqFhi + o, g_seqFlo + o);
}

// ---- kernel: rs = htw @ seq via HMMA (2-pass: Ah*Bh + Al*Bh) --------------
// grid (12 ntile-blocks, 4 row-blocks, 4 batches), 256 threads
// dyn smem: Ah[128*72]h Al[128*72]h Bh[1024]uint2 = 45056 B
__global__ __launch_bounds__(256) void k_rs_mma() {
    const int b  = blockIdx.z;
    const int p0 = blockIdx.y * 128;
    extern __shared__ char dsm[];
    __half* Ah = (__half*)dsm;
    __half* Al = (__half*)(dsm + 128*72*2);
    uint2*  Bhs = (uint2*)(dsm + 128*72*4);
    const int tid = threadIdx.x, lane = tid & 31, wid = tid >> 5;
    const int wm = wid & 3, wn = wid >> 2;
    const size_t rowbase = (size_t)(b*P + p0);
    float acc[2][4][4] = {};
    const int rb = wm*32 + (lane >> 2);
    for (int c0 = 0; c0 < L; c0 += 64) {
        __syncthreads();
        for (int idx = tid; idx < 4096; idx += 256) {
            const int row = idx >> 5, c2 = (idx & 31)*2;
            const size_t o = (rowbase + row)*L + c0 + c2;
            *(unsigned*)&Ah[row*72 + c2] = *(const unsigned*)&g_hthi[o];
            *(unsigned*)&Al[row*72 + c2] = *(const unsigned*)&g_htlo[o];
        }
        for (int idx = tid; idx < 1024; idx += 256) {
            const int kl = idx >> 8, rest = idx & 255;
            const int nt = blockIdx.x*8 + (rest >> 5), l2 = rest & 31;
            const size_t bi = (((size_t)b*64 + (c0 >> 4) + kl)*96 + nt)*32 + l2;
            Bhs[idx] = g_seqFhi[bi];
        }
        __syncthreads();
        #pragma unroll
        for (int kk = 0; kk < 4; kk++) {
            const int kloc = kk*16 + (lane & 3)*2;
            unsigned ah[2][4], al[2][4];
            #pragma unroll
            for (int m = 0; m < 2; m++) {
                const int r = rb + m*16;
                ah[m][0] = *(const unsigned*)&Ah[ r   *72 + kloc];
                ah[m][1] = *(const unsigned*)&Ah[(r+8)*72 + kloc];
                ah[m][2] = *(const unsigned*)&Ah[ r   *72 + kloc + 8];
                ah[m][3] = *(const unsigned*)&Ah[(r+8)*72 + kloc + 8];
                al[m][0] = *(const unsigned*)&Al[ r   *72 + kloc];
                al[m][1] = *(const unsigned*)&Al[(r+8)*72 + kloc];
                al[m][2] = *(const unsigned*)&Al[ r   *72 + kloc + 8];
                al[m][3] = *(const unsigned*)&Al[(r+8)*72 + kloc + 8];
            }
            #pragma unroll
            for (int t = 0; t < 4; t++) {
                const int bi = (kk*8 + wn*4 + t)*32 + lane;
                const uint2 bh = Bhs[bi];
                #pragma unroll
                for (int m = 0; m < 2; m++) {
                    mma16816(acc[m][t], ah[m], bh.x, bh.y);
                    mma16816(acc[m][t], al[m], bh.x, bh.y);
                }
            }
        }
    }
    #pragma unroll
    for (int m = 0; m < 2; m++) {
        const size_t r = rowbase + wm*32 + m*16 + (lane >> 2);
        #pragma unroll
        for (int t = 0; t < 4; t++) {
            const int n = blockIdx.x*64 + wn*32 + t*8 + (lane & 3)*2;
            #pragma unroll
            for (int h = 0; h < 2; h++) {
                const size_t rr = r + h*8;
                const float v0 = acc[m][t][h*2+0], v1 = acc[m][t][h*2+1];
                __half h0 = __float2half_rn(v0), h1 = __float2half_rn(v1);
                *(unsigned*)&g_rshi[rr*D + n] =
                    (unsigned)__half_as_ushort(h0) | ((unsigned)__half_as_ushort(h1) << 16);
                __half l0 = __float2half_rn(v0 - __half2float(h0));
                __half l1 = __float2half_rn(v1 - __half2float(h1));
                *(unsigned*)&g_rslo[rr*D + n] =
                    (unsigned)__half_as_ushort(l0) | ((unsigned)__half_as_ushort(l1) << 16);
            }
        }
    }
}

// ---- kernel: extractors via HMMA (3-pass, smem-staged B) ------------------
// grid (12 ntile-blocks, 16 row-blocks, 2 which), 256 threads
__global__ __launch_bounds__(256) void k_extract_mma(
        const float* __restrict__ bh_, const float* __restrict__ bt_,
        const int* __restrict__ hts) {
    const int which = blockIdx.z;
    const int r0 = blockIdx.y * 128;
    extern __shared__ char dsm[];
    __half* Ah = (__half*)dsm;
    __half* Al = (__half*)(dsm + 128*72*2);
    uint2*  Bhs = (uint2*)(dsm + 128*72*4);
    uint2*  Bls = Bhs + 1024;
    int*    ebase = (int*)(Bls + 1024);
    const int tid = threadIdx.x, lane = tid & 31, wid = tid >> 5;
    const int wm = wid & 3, wn = wid >> 2;
    if (tid < 128) {
        const int row = r0 + tid;
        ebase[tid] = ((row / P)*NE + hts[row*2 + which]) * D;
    }
    const uint2* __restrict__ WFh = g_WxFhi + (size_t)which*96*96*32;
    const uint2* __restrict__ WFl = g_WxFlo + (size_t)which*96*96*32;
    float acc[2][4][4] = {};
    const int rb = wm*32 + (lane >> 2);
    for (int c0 = 0; c0 < KD; c0 += 64) {
        __syncthreads();
        const bool fromE = (c0 < D);
        for (int idx = tid; idx < 4096; idx += 256) {
            const int row = idx >> 5, c2 = (idx & 31)*2;
            size_t o;
            if (fromE) o = (size_t)ebase[row] + c0 + c2;
            else       o = (size_t)(r0 + row)*D + (c0 - D) + c2;
            const __half* sh = fromE ? g_ehi : g_rshi;
            const __half* sl = fromE ? g_elo : g_rslo;
            *(unsigned*)&Ah[row*72 + c2] = *(const unsigned*)&sh[o];
            *(unsigned*)&Al[row*72 + c2] = *(const unsigned*)&sl[o];
        }
        for (int idx = tid; idx < 1024; idx += 256) {
            const int kl = idx >> 8, rest = idx & 255;
            const int nt = blockIdx.x*8 + (rest >> 5), l2 = rest & 31;
            const size_t bi = ((size_t)((c0 >> 4) + kl)*96 + nt)*32 + l2;
            Bhs[idx] = WFh[bi];
            Bls[idx] = WFl[bi];
        }
        __syncthreads();
        #pragma unroll
        for (int kk = 0; kk < 4; kk++) {
            const int kloc = kk*16 + (lane & 3)*2;
            unsigned ah[2][4], al[2][4];
            #pragma unroll
            for (int m = 0; m < 2; m++) {
                const int r = rb + m*16;
                ah[m][0] = *(const unsigned*)&Ah[ r   *72 + kloc];
                ah[m][1] = *(const unsigned*)&Ah[(r+8)*72 + kloc];
                ah[m][2] = *(const unsigned*)&Ah[ r   *72 + kloc + 8];
                ah[m][3] = *(const unsigned*)&Ah[(r+8)*72 + kloc + 8];
                al[m][0] = *(const unsigned*)&Al[ r   *72 + kloc];
                al[m][1] = *(const unsigned*)&Al[(r+8)*72 + kloc];
                al[m][2] = *(const unsigned*)&Al[ r   *72 + kloc + 8];
                al[m][3] = *(const unsigned*)&Al[(r+8)*72 + kloc + 8];
            }
            #pragma unroll
            for (int t = 0; t < 4; t++) {
                const int bi = (kk*8 + wn*4 + t)*32 + lane;
                const uint2 bh = Bhs[bi];
                const uint2 bl = Bls[bi];
                #pragma unroll
                for (int m = 0; m < 2; m++) {
                    mma16816(acc[m][t], ah[m], bh.x, bh.y);
                    mma16816(acc[m][t], al[m], bh.x, bh.y);
                    mma16816(acc[m][t], ah[m], bl.x, bl.y);
                }
            }
        }
    }
    const float* bias = which ? bt_ : bh_;
    float* outb = which ? g_zo : g_zs;
    #pragma unroll
    for (int m = 0; m < 2; m++) {
        const int r = r0 + wm*32 + m*16 + (lane >> 2);
        #pragma unroll
        for (int t = 0; t < 4; t++) {
            const int n = blockIdx.x*64 + wn*32 + t*8 + (lane & 3)*2;
            outb[(size_t) r   *D + n  ] = tanhf(acc[m][t][0] + bias[n]);
            outb[(size_t) r   *D + n+1] = tanhf(acc[m][t][1] + bias[n+1]);
            outb[(size_t)(r+8)*D + n  ] = tanhf(acc[m][t][2] + bias[n]);
            outb[(size_t)(r+8)*D + n+1] = tanhf(acc[m][t][3] + bias[n+1]);
        }
    }
}

// ---- kernel: convert W_bi into fragment-ready fp16 hi layout --------------
__global__ void k_cvt(const float* __restrict__ Wbi) {
    const int s = blockIdx.x, g = blockIdx.y;
    __shared__ float sm[16][104];
    const int tid = threadIdx.x;  // 128
    for (int idx = tid; idx < 16*104; idx += 128) ((float*)sm)[idx] = 0.f;
    __syncthreads();
    for (int idx = tid; idx < 16*97; idx += 128) {
        const int kr = idx / 97, n = idx % 97;
        sm[kr][n] = Wbi[(size_t)(g*4096 + s*16 + kr)*NL + n];
    }
    __syncthreads();
    for (int o = tid; o < 13*32; o += 128) {
        const int t = o >> 5, lane = o & 31;
        const int n = t*8 + (lane >> 2), kk = (lane & 3)*2;
        unsigned h0 = h2pack(sm[kk][n],   sm[kk+1][n]);
        unsigned h1 = h2pack(sm[kk+8][n], sm[kk+9][n]);
        g_Whi[((size_t)(g*256 + s)*13 + t)*32 + lane] = make_uint2(h0, h1);
    }
}

// ---- kernel: bilinear logits via HMMA, 2-pass, warp=m-tile, K-split -------
// grid (16 rowblocks, 12 g, KSPL halves); 256 threads = 8 warps = 8 m-tiles
#define ZS_STR 33
#define ZO_STR 72
// dyn smem: zs 128*33*4=16896 + zo 128*72*4=36864 + Wst 4*13*32*8=13312 = 67072
__global__ __launch_bounds__(256) void k_blmma() {
    const int g    = blockIdx.y;
    const int r0   = blockIdx.x * 128;
    const int half = blockIdx.z;
    extern __shared__ float sh[];
    float* zs_s = sh;
    float* zo_s = sh + 128*ZS_STR;
    uint2* Wst  = (uint2*)(sh + 128*ZS_STR + 128*ZO_STR);
    const int tid = threadIdx.x, lane = tid & 31, wid = tid >> 5;

    // stage zs slice (32 i-cols of this half) and zo (all 64 j-cols)
    for (int idx = tid; idx < 128*8; idx += 256) {
        const int row = idx >> 3, c4 = (idx & 7) * 4;
        float4 a = *(const float4*)&g_zs[(size_t)(r0+row)*D + g*BLKSZ + half*32 + c4];
        zs_s[row*ZS_STR + c4+0] = a.x; zs_s[row*ZS_STR + c4+1] = a.y;
        zs_s[row*ZS_STR + c4+2] = a.z; zs_s[row*ZS_STR + c4+3] = a.w;
    }
    for (int idx = tid; idx < 128*16; idx += 256) {
        const int row = idx >> 4, c4 = (idx & 15) * 4;
        float4 b = *(const float4*)&g_zo[(size_t)(r0+row)*D + g*BLKSZ + c4];
        zo_s[row*ZO_STR + c4+0] = b.x; zo_s[row*ZO_STR + c4+1] = b.y;
        zo_s[row*ZO_STR + c4+2] = b.z; zo_s[row*ZO_STR + c4+3] = b.w;
    }

    float acc[13][4] = {};
    const int rl = wid*16 + (lane >> 2);       // this warp's m-tile rows: rl, rl+8
    const int k0 = (lane & 3)*2;
    const uint2* __restrict__ Wh = g_Whi + ((size_t)g*256 + half*128)*13*32;

    for (int sc = 0; sc < 128; sc += 4) {
        __syncthreads();                 // protects Wst reuse; first iter covers zs/zo
        for (int idx = tid; idx < 4*13*32; idx += 256)
            Wst[idx] = Wh[(size_t)sc*13*32 + idx];
        __syncthreads();
        #pragma unroll
        for (int sl = 0; sl < 4; sl++) {
            const int s = sc + sl;
            const int i  = s >> 2;
            const int jb = ((s & 3) << 4) + k0;
            const float zs0 = zs_s[rl*ZS_STR + i];
            const float zs1 = zs_s[(rl+8)*ZS_STR + i];
            const float2 x0 = *(const float2*)&zo_s[rl*ZO_STR + jb];
            const float2 x1 = *(const float2*)&zo_s[rl*ZO_STR + jb + 8];
            const float2 y0 = *(const float2*)&zo_s[(rl+8)*ZO_STR + jb];
            const float2 y1 = *(const float2*)&zo_s[(rl+8)*ZO_STR + jb + 8];
            const float v00 = zs0*x0.x, v01 = zs0*x0.y, v02 = zs0*x1.x, v03 = zs0*x1.y;
            const float v10 = zs1*y0.x, v11 = zs1*y0.y, v12 = zs1*y1.x, v13 = zs1*y1.y;
            unsigned ah[4], al[4];
            ah[0] = h2pack(v00, v01); ah[1] = h2pack(v10, v11);
            ah[2] = h2pack(v02, v03); ah[3] = h2pack(v12, v13);
            float2 f;
            f = h2unpack(ah[0]); al[0] = h2pack(v00 - f.x, v01 - f.y);
            f = h2unpack(ah[1]); al[1] = h2pack(v10 - f.x, v11 - f.y);
            f = h2unpack(ah[2]); al[2] = h2pack(v02 - f.x, v03 - f.y);
            f = h2unpack(ah[3]); al[3] = h2pack(v12 - f.x, v13 - f.y);
            #pragma unroll
            for (int t = 0; t < 13; t++) {
                const uint2 bh = Wst[(sl*13 + t)*32 + lane];
                mma16816(acc[t], ah, bh.x, bh.y);
                mma16816(acc[t], al, bh.x, bh.y);
            }
        }
    }

    float* outp = g_part + ((size_t)(g*KSPL + half) * ROWS + r0) * NL;
    const int r = rl;
    #pragma unroll
    for (int t = 0; t < 13; t++) {
        const int n = t*8 + (lane & 3)*2;
        if (n < NL) {
            outp[(size_t) r   *NL + n] = acc[t][0];
            outp[(size_t)(r+8)*NL + n] = acc[t][2];
        }
        if (n + 1 < NL) {
            outp[(size_t) r   *NL + n+1] = acc[t][1];
            outp[(size_t)(r+8)*NL + n+1] = acc[t][3];
        }
    }
}

// ---- kernel: reduce partials over slices, add bias ------------------------
__global__ void k_reduce(const float* __restrict__ b_bi, float* __restrict__ out) {
    const int idx = blockIdx.x * 256 + threadIdx.x;
    if (idx >= ROWS * NL) return;
    const int n = idx % NL;
    float s = b_bi[n];
    #pragma unroll
    for (int g = 0; g < NSL; g++)
        s += g_part[(size_t)g * (ROWS*NL) + idx];
    out[idx] = s;
}

// ---------------------------------------------------------------------------
extern "C" void kernel_launch(void* const* d_in, const int* in_sizes, int n_in,
                              void* d_out, int out_size) {
    const float* seq    = (const float*)d_in[0];
    const float* att    = (const float*)d_in[1];
    const int*   mpos   = (const int*)d_in[2];
    const int*   hts    = (const int*)d_in[3];
    const float* W_head = (const float*)d_in[4];
    const float* b_head = (const float*)d_in[5];
    const float* W_tail = (const float*)d_in[6];
    const float* b_tail = (const float*)d_in[7];
    const float* W_bi   = (const float*)d_in[8];
    const float* b_bi   = (const float*)d_in[9];
    float* out = (float*)d_out;

    const int blm_smem = 128*ZS_STR*4 + 128*ZO_STR*4 + 4*13*32*8;  // 67072
    const int cvt_smem = 16*772*4;                                  // 49408
    const int rs_smem  = 128*72*4 + 1024*8;                         // 45056
    const int ex_smem  = 128*72*4 + 2048*8 + 512;                   // 53760
    cudaFuncSetAttribute(k_blmma, cudaFuncAttributeMaxDynamicSharedMemorySize, blm_smem);
    cudaFuncSetAttribute(k_cvtW, cudaFuncAttributeMaxDynamicSharedMemorySize, cvt_smem);
    cudaFuncSetAttribute(k_cvtseq, cudaFuncAttributeMaxDynamicSharedMemorySize, cvt_smem);
    cudaFuncSetAttribute(k_rs_mma, cudaFuncAttributeMaxDynamicSharedMemorySize, rs_smem);
    cudaFuncSetAttribute(k_extract_mma, cudaFuncAttributeMaxDynamicSharedMemorySize, ex_smem);

    // launch order arranged so ncu (-s 5 -c 1) captures k_rs_mma (launch #6)
    k_eatt<<<B*NE*H, 256>>>(att, mpos);                       // 1
    dim3 gcs(64, 4);
    k_cvtseq<<<gcs, 256, cvt_smem>>>(seq);                    // 2
    k_htw<<<B*P, 256>>>(hts);                                 // 3
    k_eemb<<<B*NE, 256>>>(seq, mpos);                         // 4
    dim3 gcw(96, 2);
    k_cvtW<<<gcw, 256, cvt_smem>>>(W_head, W_tail);           // 5
    dim3 grs(D/64, P/128, B);
    k_rs_mma<<<grs, 256, rs_smem>>>();                        // 6  <- profiled
    dim3 gex(D/64, ROWS/128, 2);
    k_extract_mma<<<gex, 256, ex_smem>>>(b_head, b_tail, hts);// 7
    dim3 gcv(256, GB);
    k_cvt<<<gcv, 128>>>(W_bi);                                // 8
    dim3 glg(ROWS/128, GB, KSPL);
    k_blmma<<<glg, 256, blm_smem>>>();                        // 9
    k_reduce<<<(ROWS*NL + 255)/256, 256>>>(b_bi, out);        // 10
}

// round 7
// speedup vs baseline: 3.9395x; 1.1950x over previous
#include <cuda_runtime.h>
#include <cuda_fp16.h>
#include <math.h>
#include <stdint.h>

#define B 4
#define L 1024
#define D 768
#define H 12
#define NE 42
#define MM 4
#define P 512
#define BLKSZ 64
#define NL 97
#define GB 12          // D / BLKSZ
#define KSPL 2         // K-split of bilinear
#define NSL (GB*KSPL)  // 24 partial slices
#define KD 1536        // 2*D
#define ROWS (B*P)     // 2048
#define NENT (B*NE)    // 168

// ---------------- scratch (device globals; no allocation allowed) ----------
__device__ __align__(16) __half g_ehi[NENT*D];
__device__ __align__(16) __half g_elo[NENT*D];
__device__ __align__(16) float g_eatt[B*NE*H*L];
__device__ __align__(16) __half g_hthi[(size_t)ROWS*L];
__device__ __align__(16) __half g_htlo[(size_t)ROWS*L];
__device__ __align__(16) __half g_rshi[(size_t)ROWS*D];
__device__ __align__(16) __half g_rslo[(size_t)ROWS*D];
__device__ __align__(16) float g_cent[2*NENT*D];      // precomputed emb@W1 + bias
__device__ __align__(16) float g_zs[(size_t)ROWS*D];
__device__ __align__(16) float g_zo[(size_t)ROWS*D];
__device__ __align__(16) float g_part[(size_t)NSL*ROWS*NL];
// fragment-ready W_bi (hi fp16): [g][kstep s:256][ntile t:13][lane:32]
__device__ __align__(16) uint2 g_Whi[(size_t)GB*256*13*32];
// fragment-ready extractor weights: [which:2][kstep:96][ntile:96][lane:32]
__device__ __align__(16) uint2 g_WxFhi[(size_t)2*96*96*32];
__device__ __align__(16) uint2 g_WxFlo[(size_t)2*96*96*32];
// fragment-ready seq (hi only): [b:4][kstep:64][ntile:96][lane:32]
__device__ __align__(16) uint2 g_seqFhi[(size_t)4*64*96*32];

// ---- half helpers ---------------------------------------------------------
__device__ __forceinline__ unsigned h2pack(float a, float b) {
    __half2 h = __float22half2_rn(make_float2(a, b));
    return reinterpret_cast<unsigned&>(h);
}
__device__ __forceinline__ float2 h2unpack(unsigned u) {
    __half2 h = reinterpret_cast<__half2&>(u);
    return __half22float2(h);
}

// ---- mma.sync m16n8k16 fp16 -> fp32 ---------------------------------------
__device__ __forceinline__ void mma16816(float* d, const unsigned* a, unsigned b0, unsigned b1) {
    asm volatile(
        "mma.sync.aligned.m16n8k16.row.col.f32.f16.f16.f32 "
        "{%0,%1,%2,%3}, {%4,%5,%6,%7}, {%8,%9}, {%0,%1,%2,%3};"
        : "+f"(d[0]), "+f"(d[1]), "+f"(d[2]), "+f"(d[3])
        : "r"(a[0]), "r"(a[1]), "r"(a[2]), "r"(a[3]), "r"(b0), "r"(b1));
}

// ---------------- kernel: entity embeddings (hi/lo split only) -------------
__global__ void k_eemb(const float* __restrict__ seq, const int* __restrict__ mpos) {
    const int be = blockIdx.x;
    const int b = be / NE;
    __shared__ int pos[MM];
    if (threadIdx.x < MM) pos[threadIdx.x] = mpos[be*MM + threadIdx.x] + 1;
    __syncthreads();
    const float* sb = seq + (size_t)b * L * D;
    for (int d = threadIdx.x; d < D; d += blockDim.x) {
        float v0 = sb[(size_t)pos[0]*D + d];
        float v1 = sb[(size_t)pos[1]*D + d];
        float v2 = sb[(size_t)pos[2]*D + d];
        float v3 = sb[(size_t)pos[3]*D + d];
        float mx = fmaxf(fmaxf(v0, v1), fmaxf(v2, v3));
        float s = expf(v0-mx) + expf(v1-mx) + expf(v2-mx) + expf(v3-mx);
        float v = mx + logf(s);
        __half hv = __float2half_rn(v);
        g_ehi[(size_t)be*D + d] = hv;
        g_elo[(size_t)be*D + d] = __float2half_rn(v - __half2float(hv));
    }
}

// ---------------- kernel: entity attentions --------------------------------
__global__ void k_eatt(const float* __restrict__ att, const int* __restrict__ mpos) {
    const int idx = blockIdx.x;
    const int h  = idx % H;
    const int be = idx / H;
    const int b  = be / NE;
    __shared__ int pos[MM];
    if (threadIdx.x < MM) pos[threadIdx.x] = mpos[be*MM + threadIdx.x] + 1;
    __syncthreads();
    const float* ab = att + (size_t)(b*H + h) * L * L;
    float* outp = g_eatt + ((size_t)be*H + h) * L;
    for (int l = threadIdx.x; l < L; l += blockDim.x) {
        float s = ab[(size_t)pos[0]*L + l] + ab[(size_t)pos[1]*L + l]
                + ab[(size_t)pos[2]*L + l] + ab[(size_t)pos[3]*L + l];
        outp[l] = 0.25f * s;
    }
}

// ---------------- kernel: per-pair channel weights -> hi/lo halves ---------
__global__ void k_htw(const int* __restrict__ hts) {
    const int bp = blockIdx.x;
    const int b  = bp / P;
    const int hi = hts[bp*2 + 0];
    const int ti = hts[bp*2 + 1];
    const float* eh = g_eatt + (size_t)(b*NE + hi) * H * L;
    const float* et = g_eatt + (size_t)(b*NE + ti) * H * L;
    const int tid = threadIdx.x;
    float w[4];
    float lsum = 0.f;
    #pragma unroll
    for (int r = 0; r < 4; r++) {
        const int l = tid + r*256;
        float acc = 0.f;
        #pragma unroll
        for (int hh = 0; hh < H; hh++)
            acc += eh[hh*L + l] * et[hh*L + l];
        w[r] = acc;
        lsum += acc;
    }
    __shared__ float red[256];
    red[tid] = lsum;
    __syncthreads();
    for (int s = 128; s > 0; s >>= 1) {
        if (tid < s) red[tid] += red[tid + s];
        __syncthreads();
    }
    const float total = red[0];
    const float scale = 1.f / ((float)H * (total / (float)H + 1e-5f));
    #pragma unroll
    for (int r = 0; r < 4; r++) {
        const int l = tid + r*256;
        float v = w[r] * scale;
        __half hv = __float2half_rn(v);
        g_hthi[(size_t)bp*L + l] = hv;
        g_htlo[(size_t)bp*L + l] = __float2half_rn(v - __half2float(hv));
    }
}

// ---- conversion: a [16 x 768] fp32 slab -> fragment-ready hi/lo -----------
__device__ __forceinline__ void cvt_slab(const float* __restrict__ src,
                                         uint2* __restrict__ dhi, uint2* __restrict__ dlo) {
    extern __shared__ float smf[];             // [16][772]
    const int tid = threadIdx.x;               // 256
    for (int idx = tid; idx < 16*768; idx += 256) {
        const int kr = idx / 768, n = idx - kr*768;
        smf[kr*772 + n] = src[(size_t)kr*768 + n];
    }
    __syncthreads();
    for (int o = tid; o < 96*32; o += 256) {
        const int nt = o >> 5, lane = o & 31;
        const int n = nt*8 + (lane >> 2), k0 = (lane & 3)*2;
        float w00 = smf[(k0  )*772 + n], w01 = smf[(k0+1)*772 + n];
        float w08 = smf[(k0+8)*772 + n], w09 = smf[(k0+9)*772 + n];
        unsigned h0 = h2pack(w00, w01), h1 = h2pack(w08, w09);
        if (dlo) {
            float2 f0 = h2unpack(h0), f1 = h2unpack(h1);
            unsigned l0 = h2pack(w00 - f0.x, w01 - f0.y);
            unsigned l1 = h2pack(w08 - f1.x, w09 - f1.y);
            dlo[(size_t)nt*32 + lane] = make_uint2(l0, l1);
        }
        dhi[(size_t)nt*32 + lane] = make_uint2(h0, h1);
    }
}

__global__ void k_cvtW(const float* __restrict__ Wh, const float* __restrict__ Wt) {
    const int ks = blockIdx.x, which = blockIdx.y;
    const float* src = (which ? Wt : Wh) + (size_t)ks*16*768;
    const size_t o = ((size_t)which*96 + ks)*96*32;
    cvt_slab(src, g_WxFhi + o, g_WxFlo + o);
}

__global__ void k_cvtseq(const float* __restrict__ seq) {
    const int ks = blockIdx.x, b = blockIdx.y;
    const float* src = seq + (size_t)b*L*D + (size_t)ks*16*768;
    const size_t o = ((size_t)b*64 + ks)*96*32;
    cvt_slab(src, g_seqFhi + o, (uint2*)0);
}

// ---- kernel: rs = htw @ seq via HMMA (2-pass: Ah*Bh + Al*Bh) --------------
// grid (12 ntile-blocks, 4 row-blocks, 4 batches), 256 threads
// dyn smem: Ah[128*72]h Al[128*72]h Bh[1024]uint2 = 45056 B
__global__ __launch_bounds__(256) void k_rs_mma() {
    const int b  = blockIdx.z;
    const int p0 = blockIdx.y * 128;
    extern __shared__ char dsm[];
    __half* Ah = (__half*)dsm;
    __half* Al = (__half*)(dsm + 128*72*2);
    uint2*  Bhs = (uint2*)(dsm + 128*72*4);
    const int tid = threadIdx.x, lane = tid & 31, wid = tid >> 5;
    const int wm = wid & 3, wn = wid >> 2;
    const size_t rowbase = (size_t)(b*P + p0);
    float acc[2][4][4] = {};
    const int rb = wm*32 + (lane >> 2);
    for (int c0 = 0; c0 < L; c0 += 64) {
        __syncthreads();
        for (int idx = tid; idx < 4096; idx += 256) {
            const int row = idx >> 5, c2 = (idx & 31)*2;
            const size_t o = (rowbase + row)*L + c0 + c2;
            *(unsigned*)&Ah[row*72 + c2] = *(const unsigned*)&g_hthi[o];
            *(unsigned*)&Al[row*72 + c2] = *(const unsigned*)&g_htlo[o];
        }
        for (int idx = tid; idx < 1024; idx += 256) {
            const int kl = idx >> 8, rest = idx & 255;
            const int nt = blockIdx.x*8 + (rest >> 5), l2 = rest & 31;
            const size_t bi = (((size_t)b*64 + (c0 >> 4) + kl)*96 + nt)*32 + l2;
            Bhs[idx] = g_seqFhi[bi];
        }
        __syncthreads();
        #pragma unroll
        for (int kk = 0; kk < 4; kk++) {
            const int kloc = kk*16 + (lane & 3)*2;
            unsigned ah[2][4], al[2][4];
            #pragma unroll
            for (int m = 0; m < 2; m++) {
                const int r = rb + m*16;
                ah[m][0] = *(const unsigned*)&Ah[ r   *72 + kloc];
                ah[m][1] = *(const unsigned*)&Ah[(r+8)*72 + kloc];
                ah[m][2] = *(const unsigned*)&Ah[ r   *72 + kloc + 8];
                ah[m][3] = *(const unsigned*)&Ah[(r+8)*72 + kloc + 8];
                al[m][0] = *(const unsigned*)&Al[ r   *72 + kloc];
                al[m][1] = *(const unsigned*)&Al[(r+8)*72 + kloc];
                al[m][2] = *(const unsigned*)&Al[ r   *72 + kloc + 8];
                al[m][3] = *(const unsigned*)&Al[(r+8)*72 + kloc + 8];
            }
            #pragma unroll
            for (int t = 0; t < 4; t++) {
                const int bi = (kk*8 + wn*4 + t)*32 + lane;
                const uint2 bh = Bhs[bi];
                #pragma unroll
                for (int m = 0; m < 2; m++) {
                    mma16816(acc[m][t], ah[m], bh.x, bh.y);
                    mma16816(acc[m][t], al[m], bh.x, bh.y);
                }
            }
        }
    }
    #pragma unroll
    for (int m = 0; m < 2; m++) {
        const size_t r = rowbase + wm*32 + m*16 + (lane >> 2);
        #pragma unroll
        for (int t = 0; t < 4; t++) {
            const int n = blockIdx.x*64 + wn*32 + t*8 + (lane & 3)*2;
            #pragma unroll
            for (int h = 0; h < 2; h++) {
                const size_t rr = r + h*8;
                const float v0 = acc[m][t][h*2+0], v1 = acc[m][t][h*2+1];
                __half h0 = __float2half_rn(v0), h1 = __float2half_rn(v1);
                *(unsigned*)&g_rshi[rr*D + n] =
                    (unsigned)__half_as_ushort(h0) | ((unsigned)__half_as_ushort(h1) << 16);
                __half l0 = __float2half_rn(v0 - __half2float(h0));
                __half l1 = __float2half_rn(v1 - __half2float(h1));
                *(unsigned*)&g_rslo[rr*D + n] =
                    (unsigned)__half_as_ushort(l0) | ((unsigned)__half_as_ushort(l1) << 16);
            }
        }
    }
}

// ---- kernel: entity-side extractor GEMM: cent = emb @ W1 + bias -----------
// grid (12 ntile-blocks, 2 row-blocks, 2 which), 256 threads; rows padded to 256
__global__ __launch_bounds__(256) void k_entgemm(
        const float* __restrict__ bh_, const float* __restrict__ bt_) {
    const int which = blockIdx.z;
    const int r0 = blockIdx.y * 128;
    extern __shared__ char dsm[];
    __half* Ah = (__half*)dsm;
    __half* Al = (__half*)(dsm + 128*72*2);
    uint2*  Bhs = (uint2*)(dsm + 128*72*4);
    uint2*  Bls = Bhs + 1024;
    const int tid = threadIdx.x, lane = tid & 31, wid = tid >> 5;
    const int wm = wid & 3, wn = wid >> 2;
    const uint2* __restrict__ WFh = g_WxFhi + (size_t)which*96*96*32;
    const uint2* __restrict__ WFl = g_WxFlo + (size_t)which*96*96*32;
    float acc[2][4][4] = {};
    const int rb = wm*32 + (lane >> 2);
    for (int c0 = 0; c0 < D; c0 += 64) {
        __syncthreads();
        for (int idx = tid; idx < 4096; idx += 256) {
            const int row = idx >> 5, c2 = (idx & 31)*2;
            int be = r0 + row; if (be >= NENT) be = 0;
            const size_t o = (size_t)be*D + c0 + c2;
            *(unsigned*)&Ah[row*72 + c2] = *(const unsigned*)&g_ehi[o];
            *(unsigned*)&Al[row*72 + c2] = *(const unsigned*)&g_elo[o];
        }
        for (int idx = tid; idx < 1024; idx += 256) {
            const int kl = idx >> 8, rest = idx & 255;
            const int nt = blockIdx.x*8 + (rest >> 5), l2 = rest & 31;
            const size_t bi = ((size_t)((c0 >> 4) + kl)*96 + nt)*32 + l2;
            Bhs[idx] = WFh[bi];
            Bls[idx] = WFl[bi];
        }
        __syncthreads();
        #pragma unroll
        for (int kk = 0; kk < 4; kk++) {
            const int kloc = kk*16 + (lane & 3)*2;
            unsigned ah[2][4], al[2][4];
            #pragma unroll
            for (int m = 0; m < 2; m++) {
                const int r = rb + m*16;
                ah[m][0] = *(const unsigned*)&Ah[ r   *72 + kloc];
                ah[m][1] = *(const unsigned*)&Ah[(r+8)*72 + kloc];
                ah[m][2] = *(const unsigned*)&Ah[ r   *72 + kloc + 8];
                ah[m][3] = *(const unsigned*)&Ah[(r+8)*72 + kloc + 8];
                al[m][0] = *(const unsigned*)&Al[ r   *72 + kloc];
                al[m][1] = *(const unsigned*)&Al[(r+8)*72 + kloc];
                al[m][2] = *(const unsigned*)&Al[ r   *72 + kloc + 8];
                al[m][3] = *(const unsigned*)&Al[(r+8)*72 + kloc + 8];
            }
            #pragma unroll
            for (int t = 0; t < 4; t++) {
                const int bi = (kk*8 + wn*4 + t)*32 + lane;
                const uint2 bh = Bhs[bi];
                const uint2 bl = Bls[bi];
                #pragma unroll
                for (int m = 0; m < 2; m++) {
                    mma16816(acc[m][t], ah[m], bh.x, bh.y);
                    mma16816(acc[m][t], al[m], bh.x, bh.y);
                    mma16816(acc[m][t], ah[m], bl.x, bl.y);
                }
            }
        }
    }
    const float* bias = which ? bt_ : bh_;
    float* cent = g_cent + (size_t)which*NENT*D;
    #pragma unroll
    for (int m = 0; m < 2; m++) {
        const int r = r0 + wm*32 + m*16 + (lane >> 2);
        #pragma unroll
        for (int t = 0; t < 4; t++) {
            const int n = blockIdx.x*64 + wn*32 + t*8 + (lane & 3)*2;
            if (r < NENT) {
                cent[(size_t)r*D + n  ] = acc[m][t][0] + bias[n];
                cent[(size_t)r*D + n+1] = acc[m][t][1] + bias[n+1];
            }
            if (r + 8 < NENT) {
                cent[(size_t)(r+8)*D + n  ] = acc[m][t][2] + bias[n];
                cent[(size_t)(r+8)*D + n+1] = acc[m][t][3] + bias[n+1];
            }
        }
    }
}

// ---- kernel: pair extractor: z = tanh(rs @ W2 + cent[ent(p)]) -------------
// grid.x = 24 (which*12 + nb), grid.y = 16 rowblocks; 256 threads
__global__ __launch_bounds__(256) void k_extract2(const int* __restrict__ hts) {
    const int which = blockIdx.x / 12;
    const int nb    = blockIdx.x % 12;
    const int r0 = blockIdx.y * 128;
    extern __shared__ char dsm[];
    __half* Ah = (__half*)dsm;
    __half* Al = (__half*)(dsm + 128*72*2);
    uint2*  Bhs = (uint2*)(dsm + 128*72*4);
    uint2*  Bls = Bhs + 1024;
    int*    eoff = (int*)(Bls + 1024);
    const int tid = threadIdx.x, lane = tid & 31, wid = tid >> 5;
    const int wm = wid & 3, wn = wid >> 2;
    if (tid < 128) {
        const int row = r0 + tid;
        eoff[tid] = ((row / P)*NE + hts[row*2 + which]) * D;
    }
    const uint2* __restrict__ WFh = g_WxFhi + (size_t)which*96*96*32;
    const uint2* __restrict__ WFl = g_WxFlo + (size_t)which*96*96*32;
    float acc[2][4][4] = {};
    const int rb = wm*32 + (lane >> 2);
    for (int c0 = 0; c0 < D; c0 += 64) {
        __syncthreads();
        for (int idx = tid; idx < 4096; idx += 256) {
            const int row = idx >> 5, c2 = (idx & 31)*2;
            const size_t o = (size_t)(r0 + row)*D + c0 + c2;
            *(unsigned*)&Ah[row*72 + c2] = *(const unsigned*)&g_rshi[o];
            *(unsigned*)&Al[row*72 + c2] = *(const unsigned*)&g_rslo[o];
        }
        for (int idx = tid; idx < 1024; idx += 256) {
            const int kl = idx >> 8, rest = idx & 255;
            const int nt = nb*8 + (rest >> 5), l2 = rest & 31;
            const size_t bi = ((size_t)(48 + (c0 >> 4) + kl)*96 + nt)*32 + l2;
            Bhs[idx] = WFh[bi];
            Bls[idx] = WFl[bi];
        }
        __syncthreads();
        #pragma unroll
        for (int kk = 0; kk < 4; kk++) {
            const int kloc = kk*16 + (lane & 3)*2;
            unsigned ah[2][4], al[2][4];
            #pragma unroll
            for (int m = 0; m < 2; m++) {
                const int r = rb + m*16;
                ah[m][0] = *(const unsigned*)&Ah[ r   *72 + kloc];
                ah[m][1] = *(const unsigned*)&Ah[(r+8)*72 + kloc];
                ah[m][2] = *(const unsigned*)&Ah[ r   *72 + kloc + 8];
                ah[m][3] = *(const unsigned*)&Ah[(r+8)*72 + kloc + 8];
                al[m][0] = *(const unsigned*)&Al[ r   *72 + kloc];
                al[m][1] = *(const unsigned*)&Al[(r+8)*72 + kloc];
                al[m][2] = *(const unsigned*)&Al[ r   *72 + kloc + 8];
                al[m][3] = *(const unsigned*)&Al[(r+8)*72 + kloc + 8];
            }
            #pragma unroll
            for (int t = 0; t < 4; t++) {
                const int bi = (kk*8 + wn*4 + t)*32 + lane;
                const uint2 bh = Bhs[bi];
                const uint2 bl = Bls[bi];
                #pragma unroll
                for (int m = 0; m < 2; m++) {
                    mma16816(acc[m][t], ah[m], bh.x, bh.y);
                    mma16816(acc[m][t], al[m], bh.x, bh.y);
                    mma16816(acc[m][t], ah[m], bl.x, bl.y);
                }
            }
        }
    }
    float* outb = which ? g_zo : g_zs;
    const float* cent = g_cent + (size_t)which*NENT*D;
    #pragma unroll
    for (int m = 0; m < 2; m++) {
        const int lr = wm*32 + m*16 + (lane >> 2);
        const int r = r0 + lr;
        #pragma unroll
        for (int t = 0; t < 4; t++) {
            const int n = nb*64 + wn*32 + t*8 + (lane & 3)*2;
            const float* c0p = cent + eoff[lr];
            const float* c1p = cent + eoff[lr + 8];
            outb[(size_t) r   *D + n  ] = tanhf(acc[m][t][0] + c0p[n]);
            outb[(size_t) r   *D + n+1] = tanhf(acc[m][t][1] + c0p[n+1]);
            outb[(size_t)(r+8)*D + n  ] = tanhf(acc[m][t][2] + c1p[n]);
            outb[(size_t)(r+8)*D + n+1] = tanhf(acc[m][t][3] + c1p[n+1]);
        }
    }
}

// ---- kernel: convert W_bi into fragment-ready fp16 hi layout --------------
__global__ void k_cvt(const float* __restrict__ Wbi) {
    const int s = blockIdx.x, g = blockIdx.y;
    __shared__ float sm[16][104];
    const int tid = threadIdx.x;  // 128
    for (int idx = tid; idx < 16*104; idx += 128) ((float*)sm)[idx] = 0.f;
    __syncthreads();
    for (int idx = tid; idx < 16*97; idx += 128) {
        const int kr = idx / 97, n = idx % 97;
        sm[kr][n] = Wbi[(size_t)(g*4096 + s*16 + kr)*NL + n];
    }
    __syncthreads();
    for (int o = tid; o < 13*32; o += 128) {
        const int t = o >> 5, lane = o & 31;
        const int n = t*8 + (lane >> 2), kk = (lane & 3)*2;
        unsigned h0 = h2pack(sm[kk][n],   sm[kk+1][n]);
        unsigned h1 = h2pack(sm[kk+8][n], sm[kk+9][n]);
        g_Whi[((size_t)(g*256 + s)*13 + t)*32 + lane] = make_uint2(h0, h1);
    }
}

// ---- kernel: bilinear logits via HMMA, 2-pass, warp=m-tile, K-split -------
// grid (16 rowblocks, 12 g, KSPL halves); 256 threads = 8 warps = 8 m-tiles
#define ZS_STR 33
#define ZO_STR 72
// dyn smem: zs 128*33*4=16896 + zo 128*72*4=36864 + Wst 4*13*32*8=13312 = 67072
__global__ __launch_bounds__(256) void k_blmma() {
    const int g    = blockIdx.y;
    const int r0   = blockIdx.x * 128;
    const int half = blockIdx.z;
    extern __shared__ float sh[];
    float* zs_s = sh;
    float* zo_s = sh + 128*ZS_STR;
    uint2* Wst  = (uint2*)(sh + 128*ZS_STR + 128*ZO_STR);
    const int tid = threadIdx.x, lane = tid & 31, wid = tid >> 5;

    for (int idx = tid; idx < 128*8; idx += 256) {
        const int row = idx >> 3, c4 = (idx & 7) * 4;
        float4 a = *(const float4*)&g_zs[(size_t)(r0+row)*D + g*BLKSZ + half*32 + c4];
        zs_s[row*ZS_STR + c4+0] = a.x; zs_s[row*ZS_STR + c4+1] = a.y;
        zs_s[row*ZS_STR + c4+2] = a.z; zs_s[row*ZS_STR + c4+3] = a.w;
    }
    for (int idx = tid; idx < 128*16; idx += 256) {
        const int row = idx >> 4, c4 = (idx & 15) * 4;
        float4 b = *(const float4*)&g_zo[(size_t)(r0+row)*D + g*BLKSZ + c4];
        zo_s[row*ZO_STR + c4+0] = b.x; zo_s[row*ZO_STR + c4+1] = b.y;
        zo_s[row*ZO_STR + c4+2] = b.z; zo_s[row*ZO_STR + c4+3] = b.w;
    }

    float acc[13][4] = {};
    const int rl = wid*16 + (lane >> 2);
    const int k0 = (lane & 3)*2;
    const uint2* __restrict__ Wh = g_Whi + ((size_t)g*256 + half*128)*13*32;

    for (int sc = 0; sc < 128; sc += 4) {
        __syncthreads();
        for (int idx = tid; idx < 4*13*32; idx += 256)
            Wst[idx] = Wh[(size_t)sc*13*32 + idx];
        __syncthreads();
        #pragma unroll
        for (int sl = 0; sl < 4; sl++) {
            const int s = sc + sl;
            const int i  = s >> 2;
            const int jb = ((s & 3) << 4) + k0;
            const float zs0 = zs_s[rl*ZS_STR + i];
            const float zs1 = zs_s[(rl+8)*ZS_STR + i];
            const float2 x0 = *(const float2*)&zo_s[rl*ZO_STR + jb];
            const float2 x1 = *(const float2*)&zo_s[rl*ZO_STR + jb + 8];
            const float2 y0 = *(const float2*)&zo_s[(rl+8)*ZO_STR + jb];
            const float2 y1 = *(const float2*)&zo_s[(rl+8)*ZO_STR + jb + 8];
            const float v00 = zs0*x0.x, v01 = zs0*x0.y, v02 = zs0*x1.x, v03 = zs0*x1.y;
            const float v10 = zs1*y0.x, v11 = zs1*y0.y, v12 = zs1*y1.x, v13 = zs1*y1.y;
            unsigned ah[4], al[4];
            ah[0] = h2pack(v00, v01); ah[1] = h2pack(v10, v11);
            ah[2] = h2pack(v02, v03); ah[3] = h2pack(v12, v13);
            float2 f;
            f = h2unpack(ah[0]); al[0] = h2pack(v00 - f.x, v01 - f.y);
            f = h2unpack(ah[1]); al[1] = h2pack(v10 - f.x, v11 - f.y);
            f = h2unpack(ah[2]); al[2] = h2pack(v02 - f.x, v03 - f.y);
            f = h2unpack(ah[3]); al[3] = h2pack(v12 - f.x, v13 - f.y);
            #pragma unroll
            for (int t = 0; t < 13; t++) {
                const uint2 bh = Wst[(sl*13 + t)*32 + lane];
                mma16816(acc[t], ah, bh.x, bh.y);
                mma16816(acc[t], al, bh.x, bh.y);
            }
        }
    }

    float* outp = g_part + ((size_t)(g*KSPL + half) * ROWS + r0) * NL;
    const int r = rl;
    #pragma unroll
    for (int t = 0; t < 13; t++) {
        const int n = t*8 + (lane & 3)*2;
        if (n < NL) {
            outp[(size_t) r   *NL + n] = acc[t][0];
            outp[(size_t)(r+8)*NL + n] = acc[t][2];
        }
        if (n + 1 < NL) {
            outp[(size_t) r   *NL + n+1] = acc[t][1];
            outp[(size_t)(r+8)*NL + n+1] = acc[t][3];
        }
    }
}

// ---- kernel: reduce partials over slices, add bias ------------------------
__global__ void k_reduce(const float* __restrict__ b_bi, float* __restrict__ out) {
    const int idx = blockIdx.x * 256 + threadIdx.x;
    if (idx >= ROWS * NL) return;
    const int n = idx % NL;
    float s = b_bi[n];
    #pragma unroll
    for (int g = 0; g < NSL; g++)
        s += g_part[(size_t)g * (ROWS*NL) + idx];
    out[idx] = s;
}

// ---------------------------------------------------------------------------
extern "C" void kernel_launch(void* const* d_in, const int* in_sizes, int n_in,
                              void* d_out, int out_size) {
    const float* seq    = (const float*)d_in[0];
    const float* att    = (const float*)d_in[1];
    const int*   mpos   = (const int*)d_in[2];
    const int*   hts    = (const int*)d_in[3];
    const float* W_head = (const float*)d_in[4];
    const float* b_head = (const float*)d_in[5];
    const float* W_tail = (const float*)d_in[6];
    const float* b_tail = (const float*)d_in[7];
    const float* W_bi   = (const float*)d_in[8];
    const float* b_bi   = (const float*)d_in[9];
    float* out = (float*)d_out;

    const int blm_smem = 128*ZS_STR*4 + 128*ZO_STR*4 + 4*13*32*8;  // 67072
    const int cvt_smem = 16*772*4;                                  // 49408
    const int rs_smem  = 128*72*4 + 1024*8;                         // 45056
    const int ex_smem  = 128*72*4 + 2048*8 + 512;                   // 53760
    cudaFuncSetAttribute(k_blmma, cudaFuncAttributeMaxDynamicSharedMemorySize, blm_smem);
    cudaFuncSetAttribute(k_cvtW, cudaFuncAttributeMaxDynamicSharedMemorySize, cvt_smem);
    cudaFuncSetAttribute(k_cvtseq, cudaFuncAttributeMaxDynamicSharedMemorySize, cvt_smem);
    cudaFuncSetAttribute(k_rs_mma, cudaFuncAttributeMaxDynamicSharedMemorySize, rs_smem);
    cudaFuncSetAttribute(k_entgemm, cudaFuncAttributeMaxDynamicSharedMemorySize, ex_smem);
    cudaFuncSetAttribute(k_extract2, cudaFuncAttributeMaxDynamicSharedMemorySize, ex_smem);

    k_eatt<<<B*NE*H, 256>>>(att, mpos);
    dim3 gcs(64, 4);
    k_cvtseq<<<gcs, 256, cvt_smem>>>(seq);
    k_htw<<<B*P, 256>>>(hts);
    k_eemb<<<B*NE, 256>>>(seq, mpos);
    dim3 gcw(96, 2);
    k_cvtW<<<gcw, 256, cvt_smem>>>(W_head, W_tail);
    dim3 geg(12, 2, 2);
    k_entgemm<<<geg, 256, ex_smem>>>(b_head, b_tail);
    dim3 grs(D/64, P/128, B);
    k_rs_mma<<<grs, 256, rs_smem>>>();
    dim3 gex(24, ROWS/128);
    k_extract2<<<gex, 256, ex_smem>>>(hts);
    dim3 gcv(256, GB);
    k_cvt<<<gcv, 128>>>(W_bi);
    dim3 glg(ROWS/128, GB, KSPL);
    k_blmma<<<glg, 256, blm_smem>>>();
    k_reduce<<<(ROWS*NL + 255)/256, 256>>>(b_bi, out);
}

// round 8
// speedup vs baseline: 4.3447x; 1.1028x over previous
#include <cuda_runtime.h>
#include <cuda_fp16.h>
#include <math.h>
#include <stdint.h>

#define B 4
#define L 1024
#define D 768
#define H 12
#define NE 42
#define MM 4
#define P 512
#define BLKSZ 64
#define NL 97
#define GB 12          // D / BLKSZ
#define KSPL 2         // K-split of bilinear
#define NSL (GB*KSPL)  // 24 partial slices
#define KD 1536        // 2*D
#define ROWS (B*P)     // 2048
#define NENT (B*NE)    // 168

// ---------------- scratch (device globals; no allocation allowed) ----------
__device__ __align__(16) __half g_ehi[NENT*D];
__device__ __align__(16) __half g_elo[NENT*D];
__device__ __align__(16) float g_eatt[B*NE*H*L];
__device__ __align__(16) __half g_hthi[(size_t)ROWS*L];
__device__ __align__(16) __half g_htlo[(size_t)ROWS*L];
__device__ __align__(16) __half g_rshi[(size_t)ROWS*D];
__device__ __align__(16) __half g_rslo[(size_t)ROWS*D];
__device__ __align__(16) float g_cent[2*NENT*D];      // precomputed emb@W1 + bias
__device__ __align__(16) float g_zs[(size_t)ROWS*D];
__device__ __align__(16) float g_zo[(size_t)ROWS*D];
__device__ __align__(16) float g_part[(size_t)NSL*ROWS*NL];
// fragment-ready W_bi (hi fp16): [g][kstep s:256][ntile t:13][lane:32]
__device__ __align__(16) uint2 g_Whi[(size_t)GB*256*13*32];
// fragment-ready extractor weights: [which:2][kstep:96][ntile:96][lane:32]
__device__ __align__(16) uint2 g_WxFhi[(size_t)2*96*96*32];
__device__ __align__(16) uint2 g_WxFlo[(size_t)2*96*96*32];
// fragment-ready seq (hi only): [b:4][kstep:64][ntile:96][lane:32]
__device__ __align__(16) uint2 g_seqFhi[(size_t)4*64*96*32];

// ---- half helpers ---------------------------------------------------------
__device__ __forceinline__ unsigned h2pack(float a, float b) {
    __half2 h = __float22half2_rn(make_float2(a, b));
    return reinterpret_cast<unsigned&>(h);
}
__device__ __forceinline__ float2 h2unpack(unsigned u) {
    __half2 h = reinterpret_cast<__half2&>(u);
    return __half22float2(h);
}

// ---- mma.sync m16n8k16 fp16 -> fp32 ---------------------------------------
__device__ __forceinline__ void mma16816(float* d, const unsigned* a, unsigned b0, unsigned b1) {
    asm volatile(
        "mma.sync.aligned.m16n8k16.row.col.f32.f16.f16.f32 "
        "{%0,%1,%2,%3}, {%4,%5,%6,%7}, {%8,%9}, {%0,%1,%2,%3};"
        : "+f"(d[0]), "+f"(d[1]), "+f"(d[2]), "+f"(d[3])
        : "r"(a[0]), "r"(a[1]), "r"(a[2]), "r"(a[3]), "r"(b0), "r"(b1));
}

// ---------------- kernel: entity embeddings (hi/lo split only) -------------
__global__ void k_eemb(const float* __restrict__ seq, const int* __restrict__ mpos) {
    const int be = blockIdx.x;
    const int b = be / NE;
    __shared__ int pos[MM];
    if (threadIdx.x < MM) pos[threadIdx.x] = mpos[be*MM + threadIdx.x] + 1;
    __syncthreads();
    const float* sb = seq + (size_t)b * L * D;
    for (int d = threadIdx.x; d < D; d += blockDim.x) {
        float v0 = sb[(size_t)pos[0]*D + d];
        float v1 = sb[(size_t)pos[1]*D + d];
        float v2 = sb[(size_t)pos[2]*D + d];
        float v3 = sb[(size_t)pos[3]*D + d];
        float mx = fmaxf(fmaxf(v0, v1), fmaxf(v2, v3));
        float s = expf(v0-mx) + expf(v1-mx) + expf(v2-mx) + expf(v3-mx);
        float v = mx + logf(s);
        __half hv = __float2half_rn(v);
        g_ehi[(size_t)be*D + d] = hv;
        g_elo[(size_t)be*D + d] = __float2half_rn(v - __half2float(hv));
    }
}

// ---------------- kernel: entity attentions --------------------------------
__global__ void k_eatt(const float* __restrict__ att, const int* __restrict__ mpos) {
    const int idx = blockIdx.x;
    const int h  = idx % H;
    const int be = idx / H;
    const int b  = be / NE;
    __shared__ int pos[MM];
    if (threadIdx.x < MM) pos[threadIdx.x] = mpos[be*MM + threadIdx.x] + 1;
    __syncthreads();
    const float* ab = att + (size_t)(b*H + h) * L * L;
    float* outp = g_eatt + ((size_t)be*H + h) * L;
    for (int l = threadIdx.x; l < L; l += blockDim.x) {
        float s = ab[(size_t)pos[0]*L + l] + ab[(size_t)pos[1]*L + l]
                + ab[(size_t)pos[2]*L + l] + ab[(size_t)pos[3]*L + l];
        outp[l] = 0.25f * s;
    }
}

// ---------------- kernel: per-pair channel weights -> hi/lo halves ---------
__global__ void k_htw(const int* __restrict__ hts) {
    const int bp = blockIdx.x;
    const int b  = bp / P;
    const int hi = hts[bp*2 + 0];
    const int ti = hts[bp*2 + 1];
    const float* eh = g_eatt + (size_t)(b*NE + hi) * H * L;
    const float* et = g_eatt + (size_t)(b*NE + ti) * H * L;
    const int tid = threadIdx.x;
    float w[4];
    float lsum = 0.f;
    #pragma unroll
    for (int r = 0; r < 4; r++) {
        const int l = tid + r*256;
        float acc = 0.f;
        #pragma unroll
        for (int hh = 0; hh < H; hh++)
            acc += eh[hh*L + l] * et[hh*L + l];
        w[r] = acc;
        lsum += acc;
    }
    __shared__ float red[256];
    red[tid] = lsum;
    __syncthreads();
    for (int s = 128; s > 0; s >>= 1) {
        if (tid < s) red[tid] += red[tid + s];
        __syncthreads();
    }
    const float total = red[0];
    const float scale = 1.f / ((float)H * (total / (float)H + 1e-5f));
    #pragma unroll
    for (int r = 0; r < 4; r++) {
        const int l = tid + r*256;
        float v = w[r] * scale;
        __half hv = __float2half_rn(v);
        g_hthi[(size_t)bp*L + l] = hv;
        g_htlo[(size_t)bp*L + l] = __float2half_rn(v - __half2float(hv));
    }
}

// ---- conversion: a [16 x 768] fp32 slab -> fragment-ready hi/lo -----------
__device__ __forceinline__ void cvt_slab(const float* __restrict__ src,
                                         uint2* __restrict__ dhi, uint2* __restrict__ dlo) {
    extern __shared__ float smf[];             // [16][772]
    const int tid = threadIdx.x;               // 256
    for (int idx = tid; idx < 16*768; idx += 256) {
        const int kr = idx / 768, n = idx - kr*768;
        smf[kr*772 + n] = src[(size_t)kr*768 + n];
    }
    __syncthreads();
    for (int o = tid; o < 96*32; o += 256) {
        const int nt = o >> 5, lane = o & 31;
        const int n = nt*8 + (lane >> 2), k0 = (lane & 3)*2;
        float w00 = smf[(k0  )*772 + n], w01 = smf[(k0+1)*772 + n];
        float w08 = smf[(k0+8)*772 + n], w09 = smf[(k0+9)*772 + n];
        unsigned h0 = h2pack(w00, w01), h1 = h2pack(w08, w09);
        if (dlo) {
            float2 f0 = h2unpack(h0), f1 = h2unpack(h1);
            unsigned l0 = h2pack(w00 - f0.x, w01 - f0.y);
            unsigned l1 = h2pack(w08 - f1.x, w09 - f1.y);
            dlo[(size_t)nt*32 + lane] = make_uint2(l0, l1);
        }
        dhi[(size_t)nt*32 + lane] = make_uint2(h0, h1);
    }
}

__global__ void k_cvtW(const float* __restrict__ Wh, const float* __restrict__ Wt) {
    const int ks = blockIdx.x, which = blockIdx.y;
    const float* src = (which ? Wt : Wh) + (size_t)ks*16*768;
    const size_t o = ((size_t)which*96 + ks)*96*32;
    cvt_slab(src, g_WxFhi + o, g_WxFlo + o);
}

__global__ void k_cvtseq(const float* __restrict__ seq) {
    const int ks = blockIdx.x, b = blockIdx.y;
    const float* src = seq + (size_t)b*L*D + (size_t)ks*16*768;
    const size_t o = ((size_t)b*64 + ks)*96*32;
    cvt_slab(src, g_seqFhi + o, (uint2*)0);
}

// ---- kernel: rs = htw @ seq via HMMA (2-pass: Ah*Bh + Al*Bh) --------------
// grid (12 ntile-blocks, 4 row-blocks, 4 batches), 256 threads
// dyn smem: Ah[128*72]h Al[128*72]h Bh[1024]uint2 = 45056 B
__global__ __launch_bounds__(256) void k_rs_mma() {
    const int b  = blockIdx.z;
    const int p0 = blockIdx.y * 128;
    extern __shared__ char dsm[];
    __half* Ah = (__half*)dsm;
    __half* Al = (__half*)(dsm + 128*72*2);
    uint2*  Bhs = (uint2*)(dsm + 128*72*4);
    const int tid = threadIdx.x, lane = tid & 31, wid = tid >> 5;
    const int wm = wid & 3, wn = wid >> 2;
    const size_t rowbase = (size_t)(b*P + p0);
    float acc[2][4][4] = {};
    const int rb = wm*32 + (lane >> 2);
    for (int c0 = 0; c0 < L; c0 += 64) {
        __syncthreads();
        for (int idx = tid; idx < 4096; idx += 256) {
            const int row = idx >> 5, c2 = (idx & 31)*2;
            const size_t o = (rowbase + row)*L + c0 + c2;
            *(unsigned*)&Ah[row*72 + c2] = *(const unsigned*)&g_hthi[o];
            *(unsigned*)&Al[row*72 + c2] = *(const unsigned*)&g_htlo[o];
        }
        for (int idx = tid; idx < 1024; idx += 256) {
            const int kl = idx >> 8, rest = idx & 255;
            const int nt = blockIdx.x*8 + (rest >> 5), l2 = rest & 31;
            const size_t bi = (((size_t)b*64 + (c0 >> 4) + kl)*96 + nt)*32 + l2;
            Bhs[idx] = g_seqFhi[bi];
        }
        __syncthreads();
        #pragma unroll
        for (int kk = 0; kk < 4; kk++) {
            const int kloc = kk*16 + (lane & 3)*2;
            unsigned ah[2][4], al[2][4];
            #pragma unroll
            for (int m = 0; m < 2; m++) {
                const int r = rb + m*16;
                ah[m][0] = *(const unsigned*)&Ah[ r   *72 + kloc];
                ah[m][1] = *(const unsigned*)&Ah[(r+8)*72 + kloc];
                ah[m][2] = *(const unsigned*)&Ah[ r   *72 + kloc + 8];
                ah[m][3] = *(const unsigned*)&Ah[(r+8)*72 + kloc + 8];
                al[m][0] = *(const unsigned*)&Al[ r   *72 + kloc];
                al[m][1] = *(const unsigned*)&Al[(r+8)*72 + kloc];
                al[m][2] = *(const unsigned*)&Al[ r   *72 + kloc + 8];
                al[m][3] = *(const unsigned*)&Al[(r+8)*72 + kloc + 8];
            }
            #pragma unroll
            for (int t = 0; t < 4; t++) {
                const int bi = (kk*8 + wn*4 + t)*32 + lane;
                const uint2 bh = Bhs[bi];
                #pragma unroll
                for (int m = 0; m < 2; m++) {
                    mma16816(acc[m][t], ah[m], bh.x, bh.y);
                    mma16816(acc[m][t], al[m], bh.x, bh.y);
                }
            }
        }
    }
    #pragma unroll
    for (int m = 0; m < 2; m++) {
        const size_t r = rowbase + wm*32 + m*16 + (lane >> 2);
        #pragma unroll
        for (int t = 0; t < 4; t++) {
            const int n = blockIdx.x*64 + wn*32 + t*8 + (lane & 3)*2;
            #pragma unroll
            for (int h = 0; h < 2; h++) {
                const size_t rr = r + h*8;
                const float v0 = acc[m][t][h*2+0], v1 = acc[m][t][h*2+1];
                __half h0 = __float2half_rn(v0), h1 = __float2half_rn(v1);
                *(unsigned*)&g_rshi[rr*D + n] =
                    (unsigned)__half_as_ushort(h0) | ((unsigned)__half_as_ushort(h1) << 16);
                __half l0 = __float2half_rn(v0 - __half2float(h0));
                __half l1 = __float2half_rn(v1 - __half2float(h1));
                *(unsigned*)&g_rslo[rr*D + n] =
                    (unsigned)__half_as_ushort(l0) | ((unsigned)__half_as_ushort(l1) << 16);
            }
        }
    }
}

// ---- kernel: entity-side extractor GEMM: cent = emb @ W1 + bias -----------
// grid (12 ntile-blocks, 2 row-blocks, 2 which), 256 threads; rows padded to 256
__global__ __launch_bounds__(256) void k_entgemm(
        const float* __restrict__ bh_, const float* __restrict__ bt_) {
    const int which = blockIdx.z;
    const int r0 = blockIdx.y * 128;
    extern __shared__ char dsm[];
    __half* Ah = (__half*)dsm;
    __half* Al = (__half*)(dsm + 128*72*2);
    uint2*  Bhs = (uint2*)(dsm + 128*72*4);
    uint2*  Bls = Bhs + 1024;
    const int tid = threadIdx.x, lane = tid & 31, wid = tid >> 5;
    const int wm = wid & 3, wn = wid >> 2;
    const uint2* __restrict__ WFh = g_WxFhi + (size_t)which*96*96*32;
    const uint2* __restrict__ WFl = g_WxFlo + (size_t)which*96*96*32;
    float acc[2][4][4] = {};
    const int rb = wm*32 + (lane >> 2);
    for (int c0 = 0; c0 < D; c0 += 64) {
        __syncthreads();
        for (int idx = tid; idx < 4096; idx += 256) {
            const int row = idx >> 5, c2 = (idx & 31)*2;
            int be = r0 + row; if (be >= NENT) be = 0;
            const size_t o = (size_t)be*D + c0 + c2;
            *(unsigned*)&Ah[row*72 + c2] = *(const unsigned*)&g_ehi[o];
            *(unsigned*)&Al[row*72 + c2] = *(const unsigned*)&g_elo[o];
        }
        for (int idx = tid; idx < 1024; idx += 256) {
            const int kl = idx >> 8, rest = idx & 255;
            const int nt = blockIdx.x*8 + (rest >> 5), l2 = rest & 31;
            const size_t bi = ((size_t)((c0 >> 4) + kl)*96 + nt)*32 + l2;
            Bhs[idx] = WFh[bi];
            Bls[idx] = WFl[bi];
        }
        __syncthreads();
        #pragma unroll
        for (int kk = 0; kk < 4; kk++) {
            const int kloc = kk*16 + (lane & 3)*2;
            unsigned ah[2][4], al[2][4];
            #pragma unroll
            for (int m = 0; m < 2; m++) {
                const int r = rb + m*16;
                ah[m][0] = *(const unsigned*)&Ah[ r   *72 + kloc];
                ah[m][1] = *(const unsigned*)&Ah[(r+8)*72 + kloc];
                ah[m][2] = *(const unsigned*)&Ah[ r   *72 + kloc + 8];
                ah[m][3] = *(const unsigned*)&Ah[(r+8)*72 + kloc + 8];
                al[m][0] = *(const unsigned*)&Al[ r   *72 + kloc];
                al[m][1] = *(const unsigned*)&Al[(r+8)*72 + kloc];
                al[m][2] = *(const unsigned*)&Al[ r   *72 + kloc + 8];
                al[m][3] = *(const unsigned*)&Al[(r+8)*72 + kloc + 8];
            }
            #pragma unroll
            for (int t = 0; t < 4; t++) {
                const int bi = (kk*8 + wn*4 + t)*32 + lane;
                const uint2 bh = Bhs[bi];
                const uint2 bl = Bls[bi];
                #pragma unroll
                for (int m = 0; m < 2; m++) {
                    mma16816(acc[m][t], ah[m], bh.x, bh.y);
                    mma16816(acc[m][t], al[m], bh.x, bh.y);
                    mma16816(acc[m][t], ah[m], bl.x, bl.y);
                }
            }
        }
    }
    const float* bias = which ? bt_ : bh_;
    float* cent = g_cent + (size_t)which*NENT*D;
    #pragma unroll
    for (int m = 0; m < 2; m++) {
        const int r = r0 + wm*32 + m*16 + (lane >> 2);
        #pragma unroll
        for (int t = 0; t < 4; t++) {
            const int n = blockIdx.x*64 + wn*32 + t*8 + (lane & 3)*2;
            if (r < NENT) {
                cent[(size_t)r*D + n  ] = acc[m][t][0] + bias[n];
                cent[(size_t)r*D + n+1] = acc[m][t][1] + bias[n+1];
            }
            if (r + 8 < NENT) {
                cent[(size_t)(r+8)*D + n  ] = acc[m][t][2] + bias[n];
                cent[(size_t)(r+8)*D + n+1] = acc[m][t][3] + bias[n+1];
            }
        }
    }
}

// ---- kernel: pair extractor: z = tanh(rs @ W2 + cent[ent(p)]) -------------
// grid.x = 24 (which*12 + nb), grid.y = 16 rowblocks; 256 threads
__global__ __launch_bounds__(256) void k_extract2(const int* __restrict__ hts) {
    const int which = blockIdx.x / 12;
    const int nb    = blockIdx.x % 12;
    const int r0 = blockIdx.y * 128;
    extern __shared__ char dsm[];
    __half* Ah = (__half*)dsm;
    __half* Al = (__half*)(dsm + 128*72*2);
    uint2*  Bhs = (uint2*)(dsm + 128*72*4);
    uint2*  Bls = Bhs + 1024;
    int*    eoff = (int*)(Bls + 1024);
    const int tid = threadIdx.x, lane = tid & 31, wid = tid >> 5;
    const int wm = wid & 3, wn = wid >> 2;
    if (tid < 128) {
        const int row = r0 + tid;
        eoff[tid] = ((row / P)*NE + hts[row*2 + which]) * D;
    }
    const uint2* __restrict__ WFh = g_WxFhi + (size_t)which*96*96*32;
    const uint2* __restrict__ WFl = g_WxFlo + (size_t)which*96*96*32;
    float acc[2][4][4] = {};
    const int rb = wm*32 + (lane >> 2);
    for (int c0 = 0; c0 < D; c0 += 64) {
        __syncthreads();
        for (int idx = tid; idx < 4096; idx += 256) {
            const int row = idx >> 5, c2 = (idx & 31)*2;
            const size_t o = (size_t)(r0 + row)*D + c0 + c2;
            *(unsigned*)&Ah[row*72 + c2] = *(const unsigned*)&g_rshi[o];
            *(unsigned*)&Al[row*72 + c2] = *(const unsigned*)&g_rslo[o];
        }
        for (int idx = tid; idx < 1024; idx += 256) {
            const int kl = idx >> 8, rest = idx & 255;
            const int nt = nb*8 + (rest >> 5), l2 = rest & 31;
            const size_t bi = ((size_t)(48 + (c0 >> 4) + kl)*96 + nt)*32 + l2;
            Bhs[idx] = WFh[bi];
            Bls[idx] = WFl[bi];
        }
        __syncthreads();
        #pragma unroll
        for (int kk = 0; kk < 4; kk++) {
            const int kloc = kk*16 + (lane & 3)*2;
            unsigned ah[2][4], al[2][4];
            #pragma unroll
            for (int m = 0; m < 2; m++) {
                const int r = rb + m*16;
                ah[m][0] = *(const unsigned*)&Ah[ r   *72 + kloc];
                ah[m][1] = *(const unsigned*)&Ah[(r+8)*72 + kloc];
                ah[m][2] = *(const unsigned*)&Ah[ r   *72 + kloc + 8];
                ah[m][3] = *(const unsigned*)&Ah[(r+8)*72 + kloc + 8];
                al[m][0] = *(const unsigned*)&Al[ r   *72 + kloc];
                al[m][1] = *(const unsigned*)&Al[(r+8)*72 + kloc];
                al[m][2] = *(const unsigned*)&Al[ r   *72 + kloc + 8];
                al[m][3] = *(const unsigned*)&Al[(r+8)*72 + kloc + 8];
            }
            #pragma unroll
            for (int t = 0; t < 4; t++) {
                const int bi = (kk*8 + wn*4 + t)*32 + lane;
                const uint2 bh = Bhs[bi];
                const uint2 bl = Bls[bi];
                #pragma unroll
                for (int m = 0; m < 2; m++) {
                    mma16816(acc[m][t], ah[m], bh.x, bh.y);
                    mma16816(acc[m][t], al[m], bh.x, bh.y);
                    mma16816(acc[m][t], ah[m], bl.x, bl.y);
                }
            }
        }
    }
    float* outb = which ? g_zo : g_zs;
    const float* cent = g_cent + (size_t)which*NENT*D;
    #pragma unroll
    for (int m = 0; m < 2; m++) {
        const int lr = wm*32 + m*16 + (lane >> 2);
        const int r = r0 + lr;
        #pragma unroll
        for (int t = 0; t < 4; t++) {
            const int n = nb*64 + wn*32 + t*8 + (lane & 3)*2;
            const float* c0p = cent + eoff[lr];
            const float* c1p = cent + eoff[lr + 8];
            outb[(size_t) r   *D + n  ] = tanhf(acc[m][t][0] + c0p[n]);
            outb[(size_t) r   *D + n+1] = tanhf(acc[m][t][1] + c0p[n+1]);
            outb[(size_t)(r+8)*D + n  ] = tanhf(acc[m][t][2] + c1p[n]);
            outb[(size_t)(r+8)*D + n+1] = tanhf(acc[m][t][3] + c1p[n+1]);
        }
    }
}

// ---- kernel: convert W_bi into fragment-ready fp16 hi layout --------------
__global__ void k_cvt(const float* __restrict__ Wbi) {
    const int s = blockIdx.x, g = blockIdx.y;
    __shared__ float sm[16][104];
    const int tid = threadIdx.x;  // 128
    for (int idx = tid; idx < 16*104; idx += 128) ((float*)sm)[idx] = 0.f;
    __syncthreads();
    for (int idx = tid; idx < 16*97; idx += 128) {
        const int kr = idx / 97, n = idx % 97;
        sm[kr][n] = Wbi[(size_t)(g*4096 + s*16 + kr)*NL + n];
    }
    __syncthreads();
    for (int o = tid; o < 13*32; o += 128) {
        const int t = o >> 5, lane = o & 31;
        const int n = t*8 + (lane >> 2), kk = (lane & 3)*2;
        unsigned h0 = h2pack(sm[kk][n],   sm[kk+1][n]);
        unsigned h1 = h2pack(sm[kk+8][n], sm[kk+9][n]);
        g_Whi[((size_t)(g*256 + s)*13 + t)*32 + lane] = make_uint2(h0, h1);
    }
}

// ---- kernel: bilinear logits via HMMA, 1-pass fp16, warp=m-tile, K-split --
// grid (16 rowblocks, 12 g, KSPL halves); 256 threads = 8 warps = 8 m-tiles
#define ZS_STR 33
#define ZO_STR 72
// dyn smem: zs 128*33*4=16896 + zo 128*72*4=36864 + Wst 4*13*32*8=13312 = 67072
__global__ __launch_bounds__(256) void k_blmma() {
    const int g    = blockIdx.y;
    const int r0   = blockIdx.x * 128;
    const int half = blockIdx.z;
    extern __shared__ float sh[];
    float* zs_s = sh;
    float* zo_s = sh + 128*ZS_STR;
    uint2* Wst  = (uint2*)(sh + 128*ZS_STR + 128*ZO_STR);
    const int tid = threadIdx.x, lane = tid & 31, wid = tid >> 5;

    for (int idx = tid; idx < 128*8; idx += 256) {
        const int row = idx >> 3, c4 = (idx & 7) * 4;
        float4 a = *(const float4*)&g_zs[(size_t)(r0+row)*D + g*BLKSZ + half*32 + c4];
        zs_s[row*ZS_STR + c4+0] = a.x; zs_s[row*ZS_STR + c4+1] = a.y;
        zs_s[row*ZS_STR + c4+2] = a.z; zs_s[row*ZS_STR + c4+3] = a.w;
    }
    for (int idx = tid; idx < 128*16; idx += 256) {
        const int row = idx >> 4, c4 = (idx & 15) * 4;
        float4 b = *(const float4*)&g_zo[(size_t)(r0+row)*D + g*BLKSZ + c4];
        zo_s[row*ZO_STR + c4+0] = b.x; zo_s[row*ZO_STR + c4+1] = b.y;
        zo_s[row*ZO_STR + c4+2] = b.z; zo_s[row*ZO_STR + c4+3] = b.w;
    }

    float acc[13][4] = {};
    const int rl = wid*16 + (lane >> 2);
    const int k0 = (lane & 3)*2;
    const uint2* __restrict__ Wh = g_Whi + ((size_t)g*256 + half*128)*13*32;

    for (int sc = 0; sc < 128; sc += 4) {
        __syncthreads();
        for (int idx = tid; idx < 4*13*32; idx += 256)
            Wst[idx] = Wh[(size_t)sc*13*32 + idx];
        __syncthreads();
        #pragma unroll
        for (int sl = 0; sl < 4; sl++) {
            const int s = sc + sl;
            const int i  = s >> 2;
            const int jb = ((s & 3) << 4) + k0;
            const float zs0 = zs_s[rl*ZS_STR + i];
            const float zs1 = zs_s[(rl+8)*ZS_STR + i];
            const float2 x0 = *(const float2*)&zo_s[rl*ZO_STR + jb];
            const float2 x1 = *(const float2*)&zo_s[rl*ZO_STR + jb + 8];
            const float2 y0 = *(const float2*)&zo_s[(rl+8)*ZO_STR + jb];
            const float2 y1 = *(const float2*)&zo_s[(rl+8)*ZO_STR + jb + 8];
            unsigned ah[4];
            ah[0] = h2pack(zs0*x0.x, zs0*x0.y);
            ah[1] = h2pack(zs1*y0.x, zs1*y0.y);
            ah[2] = h2pack(zs0*x1.x, zs0*x1.y);
            ah[3] = h2pack(zs1*y1.x, zs1*y1.y);
            #pragma unroll
            for (int t = 0; t < 13; t++) {
                const uint2 bh = Wst[(sl*13 + t)*32 + lane];
                mma16816(acc[t], ah, bh.x, bh.y);
            }
        }
    }

    float* outp = g_part + ((size_t)(g*KSPL + half) * ROWS + r0) * NL;
    const int r = rl;
    #pragma unroll
    for (int t = 0; t < 13; t++) {
        const int n = t*8 + (lane & 3)*2;
        if (n < NL) {
            outp[(size_t) r   *NL + n] = acc[t][0];
            outp[(size_t)(r+8)*NL + n] = acc[t][2];
        }
        if (n + 1 < NL) {
            outp[(size_t) r   *NL + n+1] = acc[t][1];
            outp[(size_t)(r+8)*NL + n+1] = acc[t][3];
        }
    }
}

// ---- kernel: reduce partials over slices, add bias ------------------------
__global__ void k_reduce(const float* __restrict__ b_bi, float* __restrict__ out) {
    const int idx = blockIdx.x * 256 + threadIdx.x;
    if (idx >= ROWS * NL) return;
    const int n = idx % NL;
    float s = b_bi[n];
    #pragma unroll
    for (int g = 0; g < NSL; g++)
        s += g_part[(size_t)g * (ROWS*NL) + idx];
    out[idx] = s;
}

// ---------------------------------------------------------------------------
extern "C" void kernel_launch(void* const* d_in, const int* in_sizes, int n_in,
                              void* d_out, int out_size) {
    const float* seq    = (const float*)d_in[0];
    const float* att    = (const float*)d_in[1];
    const int*   mpos   = (const int*)d_in[2];
    const int*   hts    = (const int*)d_in[3];
    const float* W_head = (const float*)d_in[4];
    const float* b_head = (const float*)d_in[5];
    const float* W_tail = (const float*)d_in[6];
    const float* b_tail = (const float*)d_in[7];
    const float* W_bi   = (const float*)d_in[8];
    const float* b_bi   = (const float*)d_in[9];
    float* out = (float*)d_out;

    const int blm_smem = 128*ZS_STR*4 + 128*ZO_STR*4 + 4*13*32*8;  // 67072
    const int cvt_smem = 16*772*4;                                  // 49408
    const int rs_smem  = 128*72*4 + 1024*8;                         // 45056
    const int ex_smem  = 128*72*4 + 2048*8 + 512;                   // 53760
    cudaFuncSetAttribute(k_blmma, cudaFuncAttributeMaxDynamicSharedMemorySize, blm_smem);
    cudaFuncSetAttribute(k_cvtW, cudaFuncAttributeMaxDynamicSharedMemorySize, cvt_smem);
    cudaFuncSetAttribute(k_cvtseq, cudaFuncAttributeMaxDynamicSharedMemorySize, cvt_smem);
    cudaFuncSetAttribute(k_rs_mma, cudaFuncAttributeMaxDynamicSharedMemorySize, rs_smem);
    cudaFuncSetAttribute(k_entgemm, cudaFuncAttributeMaxDynamicSharedMemorySize, ex_smem);
    cudaFuncSetAttribute(k_extract2, cudaFuncAttributeMaxDynamicSharedMemorySize, ex_smem);

    k_eatt<<<B*NE*H, 256>>>(att, mpos);
    dim3 gcs(64, 4);
    k_cvtseq<<<gcs, 256, cvt_smem>>>(seq);
    k_htw<<<B*P, 256>>>(hts);
    k_eemb<<<B*NE, 256>>>(seq, mpos);
    dim3 gcw(96, 2);
    k_cvtW<<<gcw, 256, cvt_smem>>>(W_head, W_tail);
    dim3 geg(12, 2, 2);
    k_entgemm<<<geg, 256, ex_smem>>>(b_head, b_tail);
    dim3 grs(D/64, P/128, B);
    k_rs_mma<<<grs, 256, rs_smem>>>();
    dim3 gex(24, ROWS/128);
    k_extract2<<<gex, 256, ex_smem>>>(hts);
    dim3 gcv(256, GB);
    k_cvt<<<gcv, 128>>>(W_bi);
    dim3 glg(ROWS/128, GB, KSPL);
    k_blmma<<<glg, 256, blm_smem>>>();
    k_reduce<<<(ROWS*NL + 255)/256, 256>>>(b_bi, out);
}

// round 9
// speedup vs baseline: 4.6184x; 1.0630x over previous
#include <cuda_runtime.h>
#include <cuda_fp16.h>
#include <math.h>
#include <stdint.h>

#define B 4
#define L 1024
#define D 768
#define H 12
#define NE 42
#define MM 4
#define P 512
#define BLKSZ 64
#define NL 97
#define GB 12          // D / BLKSZ
#define KSPL 2         // K-split of bilinear
#define NSL (GB*KSPL)  // 24 partial slices
#define KD 1536        // 2*D
#define ROWS (B*P)     // 2048
#define NENT (B*NE)    // 168

// ---------------- scratch (device globals; no allocation allowed) ----------
__device__ __align__(16) __half g_ehi[NENT*D];
__device__ __align__(16) __half g_elo[NENT*D];
__device__ __align__(16) float g_eatt[B*NE*H*L];
__device__ __align__(16) __half g_hthi[(size_t)ROWS*L];
__device__ __align__(16) __half g_rshi[(size_t)ROWS*D];
__device__ __align__(16) __half g_rslo[(size_t)ROWS*D];
__device__ __align__(16) float g_cent[2*NENT*D];      // precomputed emb@W1 + bias
__device__ __align__(16) float g_zs[(size_t)ROWS*D];
__device__ __align__(16) float g_zo[(size_t)ROWS*D];
__device__ __align__(16) float g_part[(size_t)NSL*ROWS*NL];
// fragment-ready W_bi (hi fp16): [g][kstep s:256][ntile t:13][lane:32]
__device__ __align__(16) uint2 g_Whi[(size_t)GB*256*13*32];
// fragment-ready extractor weights (hi only): [which:2][kstep:96][ntile:96][lane:32]
__device__ __align__(16) uint2 g_WxFhi[(size_t)2*96*96*32];
// fragment-ready seq (hi only): [b:4][kstep:64][ntile:96][lane:32]
__device__ __align__(16) uint2 g_seqFhi[(size_t)4*64*96*32];

// ---- half helpers ---------------------------------------------------------
__device__ __forceinline__ unsigned h2pack(float a, float b) {
    __half2 h = __float22half2_rn(make_float2(a, b));
    return reinterpret_cast<unsigned&>(h);
}
__device__ __forceinline__ float2 h2unpack(unsigned u) {
    __half2 h = reinterpret_cast<__half2&>(u);
    return __half22float2(h);
}

// ---- mma.sync m16n8k16 fp16 -> fp32 ---------------------------------------
__device__ __forceinline__ void mma16816(float* d, const unsigned* a, unsigned b0, unsigned b1) {
    asm volatile(
        "mma.sync.aligned.m16n8k16.row.col.f32.f16.f16.f32 "
        "{%0,%1,%2,%3}, {%4,%5,%6,%7}, {%8,%9}, {%0,%1,%2,%3};"
        : "+f"(d[0]), "+f"(d[1]), "+f"(d[2]), "+f"(d[3])
        : "r"(a[0]), "r"(a[1]), "r"(a[2]), "r"(a[3]), "r"(b0), "r"(b1));
}

// ---------------- kernel: entity embeddings (hi/lo split) ------------------
__global__ void k_eemb(const float* __restrict__ seq, const int* __restrict__ mpos) {
    const int be = blockIdx.x;
    const int b = be / NE;
    __shared__ int pos[MM];
    if (threadIdx.x < MM) pos[threadIdx.x] = mpos[be*MM + threadIdx.x] + 1;
    __syncthreads();
    const float* sb = seq + (size_t)b * L * D;
    for (int d = threadIdx.x; d < D; d += blockDim.x) {
        float v0 = sb[(size_t)pos[0]*D + d];
        float v1 = sb[(size_t)pos[1]*D + d];
        float v2 = sb[(size_t)pos[2]*D + d];
        float v3 = sb[(size_t)pos[3]*D + d];
        float mx = fmaxf(fmaxf(v0, v1), fmaxf(v2, v3));
        float s = expf(v0-mx) + expf(v1-mx) + expf(v2-mx) + expf(v3-mx);
        float v = mx + logf(s);
        __half hv = __float2half_rn(v);
        g_ehi[(size_t)be*D + d] = hv;
        g_elo[(size_t)be*D + d] = __float2half_rn(v - __half2float(hv));
    }
}

// ---------------- kernel: entity attentions --------------------------------
__global__ void k_eatt(const float* __restrict__ att, const int* __restrict__ mpos) {
    const int idx = blockIdx.x;
    const int h  = idx % H;
    const int be = idx / H;
    const int b  = be / NE;
    __shared__ int pos[MM];
    if (threadIdx.x < MM) pos[threadIdx.x] = mpos[be*MM + threadIdx.x] + 1;
    __syncthreads();
    const float* ab = att + (size_t)(b*H + h) * L * L;
    float* outp = g_eatt + ((size_t)be*H + h) * L;
    for (int l = threadIdx.x; l < L; l += blockDim.x) {
        float s = ab[(size_t)pos[0]*L + l] + ab[(size_t)pos[1]*L + l]
                + ab[(size_t)pos[2]*L + l] + ab[(size_t)pos[3]*L + l];
        outp[l] = 0.25f * s;
    }
}

// ---------------- kernel: per-pair channel weights -> fp16 -----------------
__global__ void k_htw(const int* __restrict__ hts) {
    const int bp = blockIdx.x;
    const int b  = bp / P;
    const int hi = hts[bp*2 + 0];
    const int ti = hts[bp*2 + 1];
    const float* eh = g_eatt + (size_t)(b*NE + hi) * H * L;
    const float* et = g_eatt + (size_t)(b*NE + ti) * H * L;
    const int tid = threadIdx.x;
    float w[4];
    float lsum = 0.f;
    #pragma unroll
    for (int r = 0; r < 4; r++) {
        const int l = tid + r*256;
        float acc = 0.f;
        #pragma unroll
        for (int hh = 0; hh < H; hh++)
            acc += eh[hh*L + l] * et[hh*L + l];
        w[r] = acc;
        lsum += acc;
    }
    __shared__ float red[256];
    red[tid] = lsum;
    __syncthreads();
    for (int s = 128; s > 0; s >>= 1) {
        if (tid < s) red[tid] += red[tid + s];
        __syncthreads();
    }
    const float total = red[0];
    const float scale = 1.f / ((float)H * (total / (float)H + 1e-5f));
    #pragma unroll
    for (int r = 0; r < 4; r++) {
        const int l = tid + r*256;
        g_hthi[(size_t)bp*L + l] = __float2half_rn(w[r] * scale);
    }
}

// ---- conversion: a [16 x 768] fp32 slab -> fragment-ready hi --------------
__device__ __forceinline__ void cvt_slab(const float* __restrict__ src,
                                         uint2* __restrict__ dhi) {
    extern __shared__ float smf[];             // [16][772]
    const int tid = threadIdx.x;               // 256
    for (int idx = tid; idx < 16*768; idx += 256) {
        const int kr = idx / 768, n = idx - kr*768;
        smf[kr*772 + n] = src[(size_t)kr*768 + n];
    }
    __syncthreads();
    for (int o = tid; o < 96*32; o += 256) {
        const int nt = o >> 5, lane = o & 31;
        const int n = nt*8 + (lane >> 2), k0 = (lane & 3)*2;
        unsigned h0 = h2pack(smf[(k0  )*772 + n], smf[(k0+1)*772 + n]);
        unsigned h1 = h2pack(smf[(k0+8)*772 + n], smf[(k0+9)*772 + n]);
        dhi[(size_t)nt*32 + lane] = make_uint2(h0, h1);
    }
}

__global__ void k_cvtW(const float* __restrict__ Wh, const float* __restrict__ Wt) {
    const int ks = blockIdx.x, which = blockIdx.y;
    const float* src = (which ? Wt : Wh) + (size_t)ks*16*768;
    cvt_slab(src, g_WxFhi + ((size_t)which*96 + ks)*96*32);
}

__global__ void k_cvtseq(const float* __restrict__ seq) {
    const int ks = blockIdx.x, b = blockIdx.y;
    const float* src = seq + (size_t)b*L*D + (size_t)ks*16*768;
    cvt_slab(src, g_seqFhi + ((size_t)b*64 + ks)*96*32);
}

// ---- kernel: rs = htw @ seq via HMMA (1-pass fp16) ------------------------
// grid (12 ntile-blocks, 4 row-blocks, 4 batches), 256 threads
// dyn smem: Ah[128*72]h + Bh[1024]uint2 = 26624 B
__global__ __launch_bounds__(256) void k_rs_mma() {
    const int b  = blockIdx.z;
    const int p0 = blockIdx.y * 128;
    extern __shared__ char dsm[];
    __half* Ah = (__half*)dsm;
    uint2*  Bhs = (uint2*)(dsm + 128*72*2);
    const int tid = threadIdx.x, lane = tid & 31, wid = tid >> 5;
    const int wm = wid & 3, wn = wid >> 2;
    const size_t rowbase = (size_t)(b*P + p0);
    float acc[2][4][4] = {};
    const int rb = wm*32 + (lane >> 2);
    for (int c0 = 0; c0 < L; c0 += 64) {
        __syncthreads();
        for (int idx = tid; idx < 4096; idx += 256) {
            const int row = idx >> 5, c2 = (idx & 31)*2;
            const size_t o = (rowbase + row)*L + c0 + c2;
            *(unsigned*)&Ah[row*72 + c2] = *(const unsigned*)&g_hthi[o];
        }
        for (int idx = tid; idx < 1024; idx += 256) {
            const int kl = idx >> 8, rest = idx & 255;
            const int nt = blockIdx.x*8 + (rest >> 5), l2 = rest & 31;
            const size_t bi = (((size_t)b*64 + (c0 >> 4) + kl)*96 + nt)*32 + l2;
            Bhs[idx] = g_seqFhi[bi];
        }
        __syncthreads();
        #pragma unroll
        for (int kk = 0; kk < 4; kk++) {
            const int kloc = kk*16 + (lane & 3)*2;
            unsigned ah[2][4];
            #pragma unroll
            for (int m = 0; m < 2; m++) {
                const int r = rb + m*16;
                ah[m][0] = *(const unsigned*)&Ah[ r   *72 + kloc];
                ah[m][1] = *(const unsigned*)&Ah[(r+8)*72 + kloc];
                ah[m][2] = *(const unsigned*)&Ah[ r   *72 + kloc + 8];
                ah[m][3] = *(const unsigned*)&Ah[(r+8)*72 + kloc + 8];
            }
            #pragma unroll
            for (int t = 0; t < 4; t++) {
                const int bi = (kk*8 + wn*4 + t)*32 + lane;
                const uint2 bh = Bhs[bi];
                #pragma unroll
                for (int m = 0; m < 2; m++)
                    mma16816(acc[m][t], ah[m], bh.x, bh.y);
            }
        }
    }
    #pragma unroll
    for (int m = 0; m < 2; m++) {
        const size_t r = rowbase + wm*32 + m*16 + (lane >> 2);
        #pragma unroll
        for (int t = 0; t < 4; t++) {
            const int n = blockIdx.x*64 + wn*32 + t*8 + (lane & 3)*2;
            #pragma unroll
            for (int h = 0; h < 2; h++) {
                const size_t rr = r + h*8;
                const float v0 = acc[m][t][h*2+0], v1 = acc[m][t][h*2+1];
                __half h0 = __float2half_rn(v0), h1 = __float2half_rn(v1);
                *(unsigned*)&g_rshi[rr*D + n] =
                    (unsigned)__half_as_ushort(h0) | ((unsigned)__half_as_ushort(h1) << 16);
                __half l0 = __float2half_rn(v0 - __half2float(h0));
                __half l1 = __float2half_rn(v1 - __half2float(h1));
                *(unsigned*)&g_rslo[rr*D + n] =
                    (unsigned)__half_as_ushort(l0) | ((unsigned)__half_as_ushort(l1) << 16);
            }
        }
    }
}

// ---- kernel: entity-side extractor GEMM: cent = emb @ W1 + bias -----------
// 2-pass (Ah*Bh + Al*Bh); grid (12 ntile, 2 rowblocks, 2 which), 256 threads
__global__ __launch_bounds__(256) void k_entgemm(
        const float* __restrict__ bh_, const float* __restrict__ bt_) {
    const int which = blockIdx.z;
    const int r0 = blockIdx.y * 128;
    extern __shared__ char dsm[];
    __half* Ah = (__half*)dsm;
    __half* Al = (__half*)(dsm + 128*72*2);
    uint2*  Bhs = (uint2*)(dsm + 128*72*4);
    const int tid = threadIdx.x, lane = tid & 31, wid = tid >> 5;
    const int wm = wid & 3, wn = wid >> 2;
    const uint2* __restrict__ WFh = g_WxFhi + (size_t)which*96*96*32;
    float acc[2][4][4] = {};
    const int rb = wm*32 + (lane >> 2);
    for (int c0 = 0; c0 < D; c0 += 64) {
        __syncthreads();
        for (int idx = tid; idx < 4096; idx += 256) {
            const int row = idx >> 5, c2 = (idx & 31)*2;
            int be = r0 + row; if (be >= NENT) be = 0;
            const size_t o = (size_t)be*D + c0 + c2;
            *(unsigned*)&Ah[row*72 + c2] = *(const unsigned*)&g_ehi[o];
            *(unsigned*)&Al[row*72 + c2] = *(const unsigned*)&g_elo[o];
        }
        for (int idx = tid; idx < 1024; idx += 256) {
            const int kl = idx >> 8, rest = idx & 255;
            const int nt = blockIdx.x*8 + (rest >> 5), l2 = rest & 31;
            Bhs[idx] = WFh[((size_t)((c0 >> 4) + kl)*96 + nt)*32 + l2];
        }
        __syncthreads();
        #pragma unroll
        for (int kk = 0; kk < 4; kk++) {
            const int kloc = kk*16 + (lane & 3)*2;
            unsigned ah[2][4], al[2][4];
            #pragma unroll
            for (int m = 0; m < 2; m++) {
                const int r = rb + m*16;
                ah[m][0] = *(const unsigned*)&Ah[ r   *72 + kloc];
                ah[m][1] = *(const unsigned*)&Ah[(r+8)*72 + kloc];
                ah[m][2] = *(const unsigned*)&Ah[ r   *72 + kloc + 8];
                ah[m][3] = *(const unsigned*)&Ah[(r+8)*72 + kloc + 8];
                al[m][0] = *(const unsigned*)&Al[ r   *72 + kloc];
                al[m][1] = *(const unsigned*)&Al[(r+8)*72 + kloc];
                al[m][2] = *(const unsigned*)&Al[ r   *72 + kloc + 8];
                al[m][3] = *(const unsigned*)&Al[(r+8)*72 + kloc + 8];
            }
            #pragma unroll
            for (int t = 0; t < 4; t++) {
                const int bi = (kk*8 + wn*4 + t)*32 + lane;
                const uint2 bh = Bhs[bi];
                #pragma unroll
                for (int m = 0; m < 2; m++) {
                    mma16816(acc[m][t], ah[m], bh.x, bh.y);
                    mma16816(acc[m][t], al[m], bh.x, bh.y);
                }
            }
        }
    }
    const float* bias = which ? bt_ : bh_;
    float* cent = g_cent + (size_t)which*NENT*D;
    #pragma unroll
    for (int m = 0; m < 2; m++) {
        const int r = r0 + wm*32 + m*16 + (lane >> 2);
        #pragma unroll
        for (int t = 0; t < 4; t++) {
            const int n = blockIdx.x*64 + wn*32 + t*8 + (lane & 3)*2;
            if (r < NENT) {
                cent[(size_t)r*D + n  ] = acc[m][t][0] + bias[n];
                cent[(size_t)r*D + n+1] = acc[m][t][1] + bias[n+1];
            }
            if (r + 8 < NENT) {
                cent[(size_t)(r+8)*D + n  ] = acc[m][t][2] + bias[n];
                cent[(size_t)(r+8)*D + n+1] = acc[m][t][3] + bias[n+1];
            }
        }
    }
}

// ---- kernel: pair extractor: z = tanh(rs @ W2 + cent[ent(p)]) -------------
// 2-pass (Ah*Bh + Al*Bh); grid.x = 24 (which*12+nb), grid.y = 16; 256 threads
__global__ __launch_bounds__(256) void k_extract2(const int* __restrict__ hts) {
    const int which = blockIdx.x / 12;
    const int nb    = blockIdx.x % 12;
    const int r0 = blockIdx.y * 128;
    extern __shared__ char dsm[];
    __half* Ah = (__half*)dsm;
    __half* Al = (__half*)(dsm + 128*72*2);
    uint2*  Bhs = (uint2*)(dsm + 128*72*4);
    int*    eoff = (int*)(Bhs + 1024);
    const int tid = threadIdx.x, lane = tid & 31, wid = tid >> 5;
    const int wm = wid & 3, wn = wid >> 2;
    if (tid < 128) {
        const int row = r0 + tid;
        eoff[tid] = ((row / P)*NE + hts[row*2 + which]) * D;
    }
    const uint2* __restrict__ WFh = g_WxFhi + (size_t)which*96*96*32;
    float acc[2][4][4] = {};
    const int rb = wm*32 + (lane >> 2);
    for (int c0 = 0; c0 < D; c0 += 64) {
        __syncthreads();
        for (int idx = tid; idx < 4096; idx += 256) {
            const int row = idx >> 5, c2 = (idx & 31)*2;
            const size_t o = (size_t)(r0 + row)*D + c0 + c2;
            *(unsigned*)&Ah[row*72 + c2] = *(const unsigned*)&g_rshi[o];
            *(unsigned*)&Al[row*72 + c2] = *(const unsigned*)&g_rslo[o];
        }
        for (int idx = tid; idx < 1024; idx += 256) {
            const int kl = idx >> 8, rest = idx & 255;
            const int nt = nb*8 + (rest >> 5), l2 = rest & 31;
            Bhs[idx] = WFh[((size_t)(48 + (c0 >> 4) + kl)*96 + nt)*32 + l2];
        }
        __syncthreads();
        #pragma unroll
        for (int kk = 0; kk < 4; kk++) {
            const int kloc = kk*16 + (lane & 3)*2;
            unsigned ah[2][4], al[2][4];
            #pragma unroll
            for (int m = 0; m < 2; m++) {
                const int r = rb + m*16;
                ah[m][0] = *(const unsigned*)&Ah[ r   *72 + kloc];
                ah[m][1] = *(const unsigned*)&Ah[(r+8)*72 + kloc];
                ah[m][2] = *(const unsigned*)&Ah[ r   *72 + kloc + 8];
                ah[m][3] = *(const unsigned*)&Ah[(r+8)*72 + kloc + 8];
                al[m][0] = *(const unsigned*)&Al[ r   *72 + kloc];
                al[m][1] = *(const unsigned*)&Al[(r+8)*72 + kloc];
                al[m][2] = *(const unsigned*)&Al[ r   *72 + kloc + 8];
                al[m][3] = *(const unsigned*)&Al[(r+8)*72 + kloc + 8];
            }
            #pragma unroll
            for (int t = 0; t < 4; t++) {
                const int bi = (kk*8 + wn*4 + t)*32 + lane;
                const uint2 bh = Bhs[bi];
                #pragma unroll
                for (int m = 0; m < 2; m++) {
                    mma16816(acc[m][t], ah[m], bh.x, bh.y);
                    mma16816(acc[m][t], al[m], bh.x, bh.y);
                }
            }
        }
    }
    float* outb = which ? g_zo : g_zs;
    const float* cent = g_cent + (size_t)which*NENT*D;
    #pragma unroll
    for (int m = 0; m < 2; m++) {
        const int lr = wm*32 + m*16 + (lane >> 2);
        const int r = r0 + lr;
        #pragma unroll
        for (int t = 0; t < 4; t++) {
            const int n = nb*64 + wn*32 + t*8 + (lane & 3)*2;
            const float* c0p = cent + eoff[lr];
            const float* c1p = cent + eoff[lr + 8];
            outb[(size_t) r   *D + n  ] = tanhf(acc[m][t][0] + c0p[n]);
            outb[(size_t) r   *D + n+1] = tanhf(acc[m][t][1] + c0p[n+1]);
            outb[(size_t)(r+8)*D + n  ] = tanhf(acc[m][t][2] + c1p[n]);
            outb[(size_t)(r+8)*D + n+1] = tanhf(acc[m][t][3] + c1p[n+1]);
        }
    }
}

// ---- kernel: convert W_bi into fragment-ready fp16 hi layout --------------
__global__ void k_cvt(const float* __restrict__ Wbi) {
    const int s = blockIdx.x, g = blockIdx.y;
    __shared__ float sm[16][104];
    const int tid = threadIdx.x;  // 128
    for (int idx = tid; idx < 16*104; idx += 128) ((float*)sm)[idx] = 0.f;
    __syncthreads();
    for (int idx = tid; idx < 16*97; idx += 128) {
        const int kr = idx / 97, n = idx % 97;
        sm[kr][n] = Wbi[(size_t)(g*4096 + s*16 + kr)*NL + n];
    }
    __syncthreads();
    for (int o = tid; o < 13*32; o += 128) {
        const int t = o >> 5, lane = o & 31;
        const int n = t*8 + (lane >> 2), kk = (lane & 3)*2;
        unsigned h0 = h2pack(sm[kk][n],   sm[kk+1][n]);
        unsigned h1 = h2pack(sm[kk+8][n], sm[kk+9][n]);
        g_Whi[((size_t)(g*256 + s)*13 + t)*32 + lane] = make_uint2(h0, h1);
    }
}

// ---- kernel: bilinear logits via HMMA, 1-pass fp16, warp=m-tile, K-split --
// grid (16 rowblocks, 12 g, KSPL halves); 256 threads = 8 warps = 8 m-tiles
#define ZS_STR 33
#define ZO_STR 72
// dyn smem: zs 128*33*4=16896 + zo 128*72*4=36864 + Wst 4*13*32*8=13312 = 67072
__global__ __launch_bounds__(256) void k_blmma() {
    const int g    = blockIdx.y;
    const int r0   = blockIdx.x * 128;
    const int half = blockIdx.z;
    extern __shared__ float sh[];
    float* zs_s = sh;
    float* zo_s = sh + 128*ZS_STR;
    uint2* Wst  = (uint2*)(sh + 128*ZS_STR + 128*ZO_STR);
    const int tid = threadIdx.x, lane = tid & 31, wid = tid >> 5;

    for (int idx = tid; idx < 128*8; idx += 256) {
        const int row = idx >> 3, c4 = (idx & 7) * 4;
        float4 a = *(const float4*)&g_zs[(size_t)(r0+row)*D + g*BLKSZ + half*32 + c4];
        zs_s[row*ZS_STR + c4+0] = a.x; zs_s[row*ZS_STR + c4+1] = a.y;
        zs_s[row*ZS_STR + c4+2] = a.z; zs_s[row*ZS_STR + c4+3] = a.w;
    }
    for (int idx = tid; idx < 128*16; idx += 256) {
        const int row = idx >> 4, c4 = (idx & 15) * 4;
        float4 b = *(const float4*)&g_zo[(size_t)(r0+row)*D + g*BLKSZ + c4];
        zo_s[row*ZO_STR + c4+0] = b.x; zo_s[row*ZO_STR + c4+1] = b.y;
        zo_s[row*ZO_STR + c4+2] = b.z; zo_s[row*ZO_STR + c4+3] = b.w;
    }

    float acc[13][4] = {};
    const int rl = wid*16 + (lane >> 2);
    const int k0 = (lane & 3)*2;
    const uint2* __restrict__ Wh = g_Whi + ((size_t)g*256 + half*128)*13*32;

    for (int sc = 0; sc < 128; sc += 4) {
        __syncthreads();
        for (int idx = tid; idx < 4*13*32; idx += 256)
            Wst[idx] = Wh[(size_t)sc*13*32 + idx];
        __syncthreads();
        #pragma unroll
        for (int sl = 0; sl < 4; sl++) {
            const int s = sc + sl;
            const int i  = s >> 2;
            const int jb = ((s & 3) << 4) + k0;
            const float zs0 = zs_s[rl*ZS_STR + i];
            const float zs1 = zs_s[(rl+8)*ZS_STR + i];
            const float2 x0 = *(const float2*)&zo_s[rl*ZO_STR + jb];
            const float2 x1 = *(const float2*)&zo_s[rl*ZO_STR + jb + 8];
            const float2 y0 = *(const float2*)&zo_s[(rl+8)*ZO_STR + jb];
            const float2 y1 = *(const float2*)&zo_s[(rl+8)*ZO_STR + jb + 8];
            unsigned ah[4];
            ah[0] = h2pack(zs0*x0.x, zs0*x0.y);
            ah[1] = h2pack(zs1*y0.x, zs1*y0.y);
            ah[2] = h2pack(zs0*x1.x, zs0*x1.y);
            ah[3] = h2pack(zs1*y1.x, zs1*y1.y);
            #pragma unroll
            for (int t = 0; t < 13; t++) {
                const uint2 bh = Wst[(sl*13 + t)*32 + lane];
                mma16816(acc[t], ah, bh.x, bh.y);
            }
        }
    }

    float* outp = g_part + ((size_t)(g*KSPL + half) * ROWS + r0) * NL;
    const int r = rl;
    #pragma unroll
    for (int t = 0; t < 13; t++) {
        const int n = t*8 + (lane & 3)*2;
        if (n < NL) {
            outp[(size_t) r   *NL + n] = acc[t][0];
            outp[(size_t)(r+8)*NL + n] = acc[t][2];
        }
        if (n + 1 < NL) {
            outp[(size_t) r   *NL + n+1] = acc[t][1];
            outp[(size_t)(r+8)*NL + n+1] = acc[t][3];
        }
    }
}

// ---- kernel: reduce partials over slices, add bias ------------------------
__global__ void k_reduce(const float* __restrict__ b_bi, float* __restrict__ out) {
    const int idx = blockIdx.x * 256 + threadIdx.x;
    if (idx >= ROWS * NL) return;
    const int n = idx % NL;
    float s = b_bi[n];
    #pragma unroll
    for (int g = 0; g < NSL; g++)
        s += g_part[(size_t)g * (ROWS*NL) + idx];
    out[idx] = s;
}

// ---------------------------------------------------------------------------
extern "C" void kernel_launch(void* const* d_in, const int* in_sizes, int n_in,
                              void* d_out, int out_size) {
    const float* seq    = (const float*)d_in[0];
    const float* att    = (const float*)d_in[1];
    const int*   mpos   = (const int*)d_in[2];
    const int*   hts    = (const int*)d_in[3];
    const float* W_head = (const float*)d_in[4];
    const float* b_head = (const float*)d_in[5];
    const float* W_tail = (const float*)d_in[6];
    const float* b_tail = (const float*)d_in[7];
    const float* W_bi   = (const float*)d_in[8];
    const float* b_bi   = (const float*)d_in[9];
    float* out = (float*)d_out;

    const int blm_smem = 128*ZS_STR*4 + 128*ZO_STR*4 + 4*13*32*8;  // 67072
    const int cvt_smem = 16*772*4;                                  // 49408
    const int rs_smem  = 128*72*2 + 1024*8;                         // 26624
    const int eg_smem  = 128*72*4 + 1024*8;                         // 45056
    const int ex_smem  = eg_smem + 512;                             // 45568
    cudaFuncSetAttribute(k_blmma, cudaFuncAttributeMaxDynamicSharedMemorySize, blm_smem);
    cudaFuncSetAttribute(k_cvtW, cudaFuncAttributeMaxDynamicSharedMemorySize, cvt_smem);
    cudaFuncSetAttribute(k_cvtseq, cudaFuncAttributeMaxDynamicSharedMemorySize, cvt_smem);
    cudaFuncSetAttribute(k_rs_mma, cudaFuncAttributeMaxDynamicSharedMemorySize, rs_smem);
    cudaFuncSetAttribute(k_entgemm, cudaFuncAttributeMaxDynamicSharedMemorySize, eg_smem);
    cudaFuncSetAttribute(k_extract2, cudaFuncAttributeMaxDynamicSharedMemorySize, ex_smem);

    k_eatt<<<B*NE*H, 256>>>(att, mpos);
    dim3 gcs(64, 4);
    k_cvtseq<<<gcs, 256, cvt_smem>>>(seq);
    k_htw<<<B*P, 256>>>(hts);
    k_eemb<<<B*NE, 256>>>(seq, mpos);
    dim3 gcw(96, 2);
    k_cvtW<<<gcw, 256, cvt_smem>>>(W_head, W_tail);
    dim3 geg(12, 2, 2);
    k_entgemm<<<geg, 256, eg_smem>>>(b_head, b_tail);
    dim3 grs(D/64, P/128, B);
    k_rs_mma<<<grs, 256, rs_smem>>>();
    dim3 gex(24, ROWS/128);
    k_extract2<<<gex, 256, ex_smem>>>(hts);
    dim3 gcv(256, GB);
    k_cvt<<<gcv, 128>>>(W_bi);
    dim3 glg(ROWS/128, GB, KSPL);
    k_blmma<<<glg, 256, blm_smem>>>();
    k_reduce<<<(ROWS*NL + 255)/256, 256>>>(b_bi, out);
}